// round 1
// baseline (speedup 1.0000x reference)
#include <cuda_runtime.h>
#include <math.h>

#define N       2048
#define ITERS   1000
#define TEMP    100.0f

#define SGRID   128
#define SBLOCK  512
#define ROWS_PER_CTA (N / SGRID / (SBLOCK/32))  // informational; 1 row per warp

// ---------------- scratch (static device globals; allocation-free) -------------
__device__ float g_E [N * N];   // exp matrix
__device__ float g_ET[N * N];   // transposed exp matrix
__device__ float g_F [N * N];   // final m
__device__ float g_G [N * N];   // row suffix sums of m
__device__ float g_u[N];
__device__ float g_v[N];
__device__ float g_rowmax[N];

__device__ unsigned g_count = 0;          // barrier arrival counter (returns to 0)
__device__ volatile unsigned g_gen = 0;   // barrier generation (monotone, wraps OK)

// ---------------- grid barrier (sense-reversing, replay-safe) ------------------
__device__ __forceinline__ void grid_sync() {
    __syncthreads();
    if (threadIdx.x == 0) {
        __threadfence();
        unsigned my = g_gen;
        unsigned arrived = atomicAdd(&g_count, 1u);
        if (arrived == SGRID - 1) {
            g_count = 0;
            __threadfence();
            g_gen = my + 1u;
        } else {
            while (g_gen == my) { }
        }
        __threadfence();
    }
    __syncthreads();
}

// ---------------- prep: row max -------------------------------------------------
__global__ void rowmax_kernel(const float* __restrict__ A) {
    int row = blockIdx.x;
    const float* a = A + (size_t)row * N;
    float m = -3.0e38f;
    for (int j = threadIdx.x; j < N; j += blockDim.x) m = fmaxf(m, a[j]);
    __shared__ float s[256];
    s[threadIdx.x] = m;
    __syncthreads();
    for (int o = 128; o > 0; o >>= 1) {
        if (threadIdx.x < o) s[threadIdx.x] = fmaxf(s[threadIdx.x], s[threadIdx.x + o]);
        __syncthreads();
    }
    if (threadIdx.x == 0) g_rowmax[row] = s[0];
}

// ---------------- prep: E = exp(T*(A - rowmax)), ET = E^T, v = 1 ---------------
__global__ void exp_kernel(const float* __restrict__ A) {
    __shared__ float tile[32][33];
    int x = blockIdx.x * 32 + threadIdx.x;   // col of E
    int y = blockIdx.y * 32 + threadIdx.y;   // row of E
    float rm = g_rowmax[y];
    float e = expf(TEMP * (A[(size_t)y * N + x] - rm));
    g_E[(size_t)y * N + x] = e;
    tile[threadIdx.y][threadIdx.x] = e;
    __syncthreads();
    int tx = blockIdx.y * 32 + threadIdx.x;  // inner (row of E) index for ET write
    int ty = blockIdx.x * 32 + threadIdx.y;  // col of E = row of ET
    g_ET[(size_t)ty * N + tx] = tile[threadIdx.x][threadIdx.y];
}

__global__ void init_kernel() {
    int i = blockIdx.x * blockDim.x + threadIdx.x;
    if (i < N) { g_v[i] = 1.0f; g_u[i] = 1.0f; }
}

// ---------------- persistent Sinkhorn: u = 1/(E v); v = 1/(ET u) ---------------
__global__ void __launch_bounds__(SBLOCK, 1) sinkhorn_kernel() {
    const int warp = threadIdx.x >> 5;
    const int lane = threadIdx.x & 31;
    const int row  = blockIdx.x * (SBLOCK / 32) + warp;  // 128*16 = 2048 rows

    __shared__ float svec[N];
    float4* svec4 = (float4*)svec;

    const float4* E4  = (const float4*)g_E;
    const float4* ET4 = (const float4*)g_ET;

    for (int t = 0; t < ITERS; ++t) {
        // ---- phase A: u = 1 / (E v) ----
        {
            const float4* v4 = (const float4*)g_v;
            for (int i = threadIdx.x; i < N / 4; i += SBLOCK) svec4[i] = v4[i];
            __syncthreads();

            const float4* erow = E4 + (size_t)row * (N / 4);
            float s = 0.0f;
#pragma unroll
            for (int jb = 0; jb < N / 4; jb += 32) {
                float4 e  = erow[jb + lane];
                float4 vv = svec4[jb + lane];
                s += e.x * vv.x + e.y * vv.y + e.z * vv.z + e.w * vv.w;
            }
#pragma unroll
            for (int o = 16; o > 0; o >>= 1) s += __shfl_xor_sync(0xffffffff, s, o);
            if (lane == 0) g_u[row] = 1.0f / s;
        }
        grid_sync();

        // ---- phase B: v = 1 / (ET u) ----
        {
            const float4* u4 = (const float4*)g_u;
            for (int i = threadIdx.x; i < N / 4; i += SBLOCK) svec4[i] = u4[i];
            __syncthreads();

            const float4* etrow = ET4 + (size_t)row * (N / 4);
            float s = 0.0f;
#pragma unroll
            for (int jb = 0; jb < N / 4; jb += 32) {
                float4 e  = etrow[jb + lane];
                float4 uu = svec4[jb + lane];
                s += e.x * uu.x + e.y * uu.y + e.z * uu.z + e.w * uu.w;
            }
#pragma unroll
            for (int o = 16; o > 0; o >>= 1) s += __shfl_xor_sync(0xffffffff, s, o);
            if (lane == 0) g_v[row] = 1.0f / s;
        }
        grid_sync();
    }
}

// ---------------- F = m = diag(u) E diag(v);  G = row suffix sums of m ----------
__global__ void fg_kernel() {
    int row = blockIdx.x;
    int t   = threadIdx.x;        // 256 threads, 8 elements each
    float uu = g_u[row];

    const float4* erow = (const float4*)g_E + (size_t)row * (N / 4);
    const float4* v4   = (const float4*)g_v;

    float4 e0 = erow[t * 2], e1 = erow[t * 2 + 1];
    float4 w0 = v4[t * 2],   w1 = v4[t * 2 + 1];

    float m[8];
    m[0] = uu * e0.x * w0.x;  m[1] = uu * e0.y * w0.y;
    m[2] = uu * e0.z * w0.z;  m[3] = uu * e0.w * w0.w;
    m[4] = uu * e1.x * w1.x;  m[5] = uu * e1.y * w1.y;
    m[6] = uu * e1.z * w1.z;  m[7] = uu * e1.w * w1.w;

    float tsum = 0.0f;
#pragma unroll
    for (int e = 0; e < 8; ++e) tsum += m[e];

    __shared__ float ss[256];
    ss[t] = tsum;
    __syncthreads();
    float run = tsum;
#pragma unroll
    for (int o = 1; o < 256; o <<= 1) {
        float y = (t >= o) ? ss[t - o] : 0.0f;
        __syncthreads();
        run += y;
        ss[t] = run;
        __syncthreads();
    }
    float total = ss[255];
    float pf = run - tsum;   // exclusive prefix before this thread's chunk

    float g[8];
#pragma unroll
    for (int e = 0; e < 8; ++e) { g[e] = total - pf; pf += m[e]; }

    float4* F4 = (float4*)g_F + (size_t)row * (N / 4);
    float4* G4 = (float4*)g_G + (size_t)row * (N / 4);
    F4[t * 2]     = make_float4(m[0], m[1], m[2], m[3]);
    F4[t * 2 + 1] = make_float4(m[4], m[5], m[6], m[7]);
    G4[t * 2]     = make_float4(g[0], g[1], g[2], g[3]);
    G4[t * 2 + 1] = make_float4(g[4], g[5], g[6], g[7]);
}

// ---------------- C[a,b] = dot(F[a,:], G[b,:])  (2048^3 fp32 SGEMM, NT) --------
__global__ void __launch_bounds__(256, 2) gemm_kernel(float* __restrict__ C) {
    __shared__ float As[8][128];
    __shared__ float Bs[8][128];

    const float* A = g_F;
    const float* B = g_G;

    const int bi = blockIdx.y * 128;   // rows of out (a)
    const int bj = blockIdx.x * 128;   // cols of out (b)
    const int tid = threadIdx.x;
    const int lr = tid >> 1;           // 0..127 load row
    const int lc = (tid & 1) * 4;      // 0 or 4
    const int ty = tid >> 4;           // 0..15
    const int tx = tid & 15;           // 0..15

    float acc[8][8];
#pragma unroll
    for (int i = 0; i < 8; ++i)
#pragma unroll
        for (int j = 0; j < 8; ++j) acc[i][j] = 0.0f;

    for (int k0 = 0; k0 < N; k0 += 8) {
        float4 a = *(const float4*)(A + (size_t)(bi + lr) * N + k0 + lc);
        float4 b = *(const float4*)(B + (size_t)(bj + lr) * N + k0 + lc);
        __syncthreads();
        As[lc + 0][lr] = a.x; As[lc + 1][lr] = a.y; As[lc + 2][lr] = a.z; As[lc + 3][lr] = a.w;
        Bs[lc + 0][lr] = b.x; Bs[lc + 1][lr] = b.y; Bs[lc + 2][lr] = b.z; Bs[lc + 3][lr] = b.w;
        __syncthreads();
#pragma unroll
        for (int k = 0; k < 8; ++k) {
            float ar[8], br[8];
            *(float4*)(ar)     = *(const float4*)&As[k][ty * 8];
            *(float4*)(ar + 4) = *(const float4*)&As[k][ty * 8 + 4];
            *(float4*)(br)     = *(const float4*)&Bs[k][tx * 8];
            *(float4*)(br + 4) = *(const float4*)&Bs[k][tx * 8 + 4];
#pragma unroll
            for (int i = 0; i < 8; ++i)
#pragma unroll
                for (int j = 0; j < 8; ++j) acc[i][j] += ar[i] * br[j];
        }
    }

#pragma unroll
    for (int i = 0; i < 8; ++i) {
        float* crow = C + (size_t)(bi + ty * 8 + i) * N + bj + tx * 8;
        *(float4*)(crow)     = make_float4(acc[i][0], acc[i][1], acc[i][2], acc[i][3]);
        *(float4*)(crow + 4) = make_float4(acc[i][4], acc[i][5], acc[i][6], acc[i][7]);
    }
}

// ---------------- launch --------------------------------------------------------
extern "C" void kernel_launch(void* const* d_in, const int* in_sizes, int n_in,
                              void* d_out, int out_size) {
    const float* A = (const float*)d_in[0];
    float* out = (float*)d_out;

    rowmax_kernel<<<N, 256>>>(A);
    exp_kernel<<<dim3(N / 32, N / 32), dim3(32, 32)>>>(A);
    init_kernel<<<(N + 255) / 256, 256>>>();
    sinkhorn_kernel<<<SGRID, SBLOCK>>>();
    fg_kernel<<<N, 256>>>();
    gemm_kernel<<<dim3(N / 128, N / 128), 256>>>(out);
}

// round 2
// speedup vs baseline: 15.9603x; 15.9603x over previous
#include <cuda_runtime.h>
#include <math.h>

#define N       2048
#define ITERS   1000
#define TEMP    100.0f
#define EPS_CONV 1e-5f

#define SGRID   128
#define SBLOCK  1024
#define WPC     (SBLOCK/32)     // 32 warps per CTA
#define RPC     (WPC/2)         // 16 rows per CTA (2 warps per row)

// ---------------- scratch (static device globals; allocation-free) -------------
__device__ float g_E [N * N];   // exp matrix
__device__ float g_ET[N * N];   // transposed exp matrix
__device__ float g_F [N * N];   // final m
__device__ float g_G [N * N];   // row suffix sums of m
__device__ float g_u[N];
__device__ float g_v[N];
__device__ float g_rowmax[N];

__device__ unsigned g_count = 0;           // barrier arrival counter (self-resets)
__device__ unsigned g_gen   = 0;           // barrier generation (monotone)
__device__ unsigned g_delta[2] = {0, 0};   // per-iteration max |du/u| (float bits)

// ---------------- acquire/release grid barrier ---------------------------------
__device__ __forceinline__ void grid_sync() {
    __syncthreads();
    if (threadIdx.x == 0) {
        unsigned my;
        asm volatile("ld.acquire.gpu.global.u32 %0, [%1];" : "=r"(my) : "l"(&g_gen));
        unsigned old;
        asm volatile("atom.release.gpu.global.add.u32 %0, [%1], %2;"
                     : "=r"(old) : "l"(&g_count), "r"(1u));
        if (old == SGRID - 1) {
            asm volatile("st.relaxed.gpu.global.u32 [%0], %1;" :: "l"(&g_count), "r"(0u));
            asm volatile("st.release.gpu.global.u32 [%0], %1;" :: "l"(&g_gen), "r"(my + 1u));
        } else {
            unsigned cur;
            do {
                asm volatile("ld.acquire.gpu.global.u32 %0, [%1];" : "=r"(cur) : "l"(&g_gen));
            } while (cur == my);
        }
    }
    __syncthreads();
}

// ---------------- prep: row max -------------------------------------------------
__global__ void rowmax_kernel(const float* __restrict__ A) {
    int row = blockIdx.x;
    const float* a = A + (size_t)row * N;
    float m = -3.0e38f;
    for (int j = threadIdx.x; j < N; j += blockDim.x) m = fmaxf(m, a[j]);
    __shared__ float s[256];
    s[threadIdx.x] = m;
    __syncthreads();
    for (int o = 128; o > 0; o >>= 1) {
        if (threadIdx.x < o) s[threadIdx.x] = fmaxf(s[threadIdx.x], s[threadIdx.x + o]);
        __syncthreads();
    }
    if (threadIdx.x == 0) g_rowmax[row] = s[0];
}

// ---------------- prep: E = exp(T*(A - rowmax)), ET = E^T ----------------------
__global__ void exp_kernel(const float* __restrict__ A) {
    __shared__ float tile[32][33];
    int x = blockIdx.x * 32 + threadIdx.x;
    int y = blockIdx.y * 32 + threadIdx.y;
    float rm = g_rowmax[y];
    float e = expf(TEMP * (A[(size_t)y * N + x] - rm));
    g_E[(size_t)y * N + x] = e;
    tile[threadIdx.y][threadIdx.x] = e;
    __syncthreads();
    int tx = blockIdx.y * 32 + threadIdx.x;
    int ty = blockIdx.x * 32 + threadIdx.y;
    g_ET[(size_t)ty * N + tx] = tile[threadIdx.x][threadIdx.y];
}

__global__ void init_kernel() {
    int i = blockIdx.x * blockDim.x + threadIdx.x;
    if (i < N) { g_v[i] = 1.0f; g_u[i] = 1.0f; }
    if (i < 2) g_delta[i] = 0u;
}

// ---------------- persistent Sinkhorn -------------------------------------------
// 128 CTAs x 1024 threads. 2 warps per row (column halves). Early exit on u-convergence.
__global__ void __launch_bounds__(SBLOCK, 1) sinkhorn_kernel() {
    const int tid  = threadIdx.x;
    const int wid  = tid >> 5;
    const int lane = tid & 31;
    const int rloc = wid >> 1;             // 0..15
    const int half = wid & 1;
    const int row  = blockIdx.x * RPC + rloc;

    __shared__ float svec[N];
    __shared__ float spart[WPC];
    __shared__ float sdel[RPC];
    __shared__ float sflag;
    float4* svec4 = (float4*)svec;

    const float4* erow  = (const float4*)g_E  + (size_t)row * (N / 4) + half * (N / 8);
    const float4* etrow = (const float4*)g_ET + (size_t)row * (N / 4) + half * (N / 8);
    const float4* sv = svec4 + half * (N / 8);

    float u_old = 1.0f;

    for (int t = 0; t < ITERS; ++t) {
        // ================= phase A: u = 1 / (E v) =================
        {
            const float4* v4 = (const float4*)g_v;
            if (tid < N / 4) svec4[tid] = v4[tid];
            __syncthreads();

            float s = 0.0f;
#pragma unroll 4
            for (int jb = 0; jb < N / 8; jb += 32) {
                float4 e  = erow[jb + lane];
                float4 vv = sv[jb + lane];
                s += e.x * vv.x + e.y * vv.y + e.z * vv.z + e.w * vv.w;
            }
#pragma unroll
            for (int o = 16; o > 0; o >>= 1) s += __shfl_xor_sync(0xffffffffu, s, o);
            if (lane == 0) spart[wid] = s;
            __syncthreads();

            if (half == 0 && lane == 0) {
                float tot = spart[wid] + spart[wid + 1];
                float un = 1.0f / tot;
                g_u[row] = un;
                sdel[rloc] = fabsf(un - u_old) / u_old;   // u > 0 always
                u_old = un;
            }
            __syncthreads();
            if (tid == 0) {
                float dm = 0.0f;
#pragma unroll
                for (int i = 0; i < RPC; ++i) dm = fmaxf(dm, sdel[i]);
                atomicMax(&g_delta[t & 1], __float_as_uint(dm));  // positives: bit order == float order
            }
        }
        grid_sync();

        // conv decision + reset slot for iteration t+1
        if (tid == 0) {
            unsigned db;
            asm volatile("ld.acquire.gpu.global.u32 %0, [%1];" : "=r"(db) : "l"(&g_delta[t & 1]));
            sflag = (t > 0 && __uint_as_float(db) < EPS_CONV) ? 1.0f : 0.0f;
            g_delta[(t + 1) & 1] = 0u;
        }

        // ================= phase B: v = 1 / (ET u) =================
        bool conv;
        {
            const float4* u4 = (const float4*)g_u;
            if (tid < N / 4) svec4[tid] = u4[tid];
            __syncthreads();
            conv = (sflag > 0.5f);

            float s = 0.0f;
#pragma unroll 4
            for (int jb = 0; jb < N / 8; jb += 32) {
                float4 e  = etrow[jb + lane];
                float4 uu = sv[jb + lane];
                s += e.x * uu.x + e.y * uu.y + e.z * uu.z + e.w * uu.w;
            }
#pragma unroll
            for (int o = 16; o > 0; o >>= 1) s += __shfl_xor_sync(0xffffffffu, s, o);
            if (lane == 0) spart[wid] = s;
            __syncthreads();
            if (half == 0 && lane == 0) {
                float tot = spart[wid] + spart[wid + 1];
                g_v[row] = 1.0f / tot;
            }
        }
        grid_sync();

        if (conv) break;
    }
}

// ---------------- F = m = diag(u) E diag(v);  G = row suffix sums ---------------
__global__ void fg_kernel() {
    int row = blockIdx.x;
    int t   = threadIdx.x;
    float uu = g_u[row];

    const float4* erow = (const float4*)g_E + (size_t)row * (N / 4);
    const float4* v4   = (const float4*)g_v;

    float4 e0 = erow[t * 2], e1 = erow[t * 2 + 1];
    float4 w0 = v4[t * 2],   w1 = v4[t * 2 + 1];

    float m[8];
    m[0] = uu * e0.x * w0.x;  m[1] = uu * e0.y * w0.y;
    m[2] = uu * e0.z * w0.z;  m[3] = uu * e0.w * w0.w;
    m[4] = uu * e1.x * w1.x;  m[5] = uu * e1.y * w1.y;
    m[6] = uu * e1.z * w1.z;  m[7] = uu * e1.w * w1.w;

    float tsum = 0.0f;
#pragma unroll
    for (int e = 0; e < 8; ++e) tsum += m[e];

    __shared__ float ss[256];
    ss[t] = tsum;
    __syncthreads();
    float run = tsum;
#pragma unroll
    for (int o = 1; o < 256; o <<= 1) {
        float y = (t >= o) ? ss[t - o] : 0.0f;
        __syncthreads();
        run += y;
        ss[t] = run;
        __syncthreads();
    }
    float total = ss[255];
    float pf = run - tsum;

    float g[8];
#pragma unroll
    for (int e = 0; e < 8; ++e) { g[e] = total - pf; pf += m[e]; }

    float4* F4 = (float4*)g_F + (size_t)row * (N / 4);
    float4* G4 = (float4*)g_G + (size_t)row * (N / 4);
    F4[t * 2]     = make_float4(m[0], m[1], m[2], m[3]);
    F4[t * 2 + 1] = make_float4(m[4], m[5], m[6], m[7]);
    G4[t * 2]     = make_float4(g[0], g[1], g[2], g[3]);
    G4[t * 2 + 1] = make_float4(g[4], g[5], g[6], g[7]);
}

// ---------------- C[a,b] = dot(F[a,:], G[b,:])  (fp32 SGEMM, NT) ----------------
__global__ void __launch_bounds__(256, 2) gemm_kernel(float* __restrict__ C) {
    __shared__ float As[8][128];
    __shared__ float Bs[8][128];

    const float* A = g_F;
    const float* B = g_G;

    const int bi = blockIdx.y * 128;
    const int bj = blockIdx.x * 128;
    const int tid = threadIdx.x;
    const int lr = tid >> 1;
    const int lc = (tid & 1) * 4;
    const int ty = tid >> 4;
    const int tx = tid & 15;

    float acc[8][8];
#pragma unroll
    for (int i = 0; i < 8; ++i)
#pragma unroll
        for (int j = 0; j < 8; ++j) acc[i][j] = 0.0f;

    for (int k0 = 0; k0 < N; k0 += 8) {
        float4 a = *(const float4*)(A + (size_t)(bi + lr) * N + k0 + lc);
        float4 b = *(const float4*)(B + (size_t)(bj + lr) * N + k0 + lc);
        __syncthreads();
        As[lc + 0][lr] = a.x; As[lc + 1][lr] = a.y; As[lc + 2][lr] = a.z; As[lc + 3][lr] = a.w;
        Bs[lc + 0][lr] = b.x; Bs[lc + 1][lr] = b.y; Bs[lc + 2][lr] = b.z; Bs[lc + 3][lr] = b.w;
        __syncthreads();
#pragma unroll
        for (int k = 0; k < 8; ++k) {
            float ar[8], br[8];
            *(float4*)(ar)     = *(const float4*)&As[k][ty * 8];
            *(float4*)(ar + 4) = *(const float4*)&As[k][ty * 8 + 4];
            *(float4*)(br)     = *(const float4*)&Bs[k][tx * 8];
            *(float4*)(br + 4) = *(const float4*)&Bs[k][tx * 8 + 4];
#pragma unroll
            for (int i = 0; i < 8; ++i)
#pragma unroll
                for (int j = 0; j < 8; ++j) acc[i][j] += ar[i] * br[j];
        }
    }

#pragma unroll
    for (int i = 0; i < 8; ++i) {
        float* crow = C + (size_t)(bi + ty * 8 + i) * N + bj + tx * 8;
        *(float4*)(crow)     = make_float4(acc[i][0], acc[i][1], acc[i][2], acc[i][3]);
        *(float4*)(crow + 4) = make_float4(acc[i][4], acc[i][5], acc[i][6], acc[i][7]);
    }
}

// ---------------- launch --------------------------------------------------------
extern "C" void kernel_launch(void* const* d_in, const int* in_sizes, int n_in,
                              void* d_out, int out_size) {
    const float* A = (const float*)d_in[0];
    float* out = (float*)d_out;

    rowmax_kernel<<<N, 256>>>(A);
    exp_kernel<<<dim3(N / 32, N / 32), dim3(32, 32)>>>(A);
    init_kernel<<<(N + 255) / 256, 256>>>();
    sinkhorn_kernel<<<SGRID, SBLOCK>>>();
    fg_kernel<<<N, 256>>>();
    gemm_kernel<<<dim3(N / 128, N / 128), 256>>>(out);
}

// round 5
// speedup vs baseline: 25.0774x; 1.5712x over previous
#include <cuda_runtime.h>
#include <cuda_bf16.h>
#include <math.h>
#include <stdint.h>

#define N       2048
#define ITERS   1000
#define TEMP    100.0f
#define EPS_CONV 1e-5f

#define SGRID   128
#define SBLOCK  1024
#define WPC     (SBLOCK/32)
#define RPC     (WPC/2)

// ---------------- scratch (static device globals; allocation-free) -------------
__device__ float g_E [N * N];
__device__ float g_ET[N * N];
__device__ __nv_bfloat16 g_Fh[N * N];
__device__ __nv_bfloat16 g_Fl[N * N];
__device__ __nv_bfloat16 g_Gh[N * N];
__device__ __nv_bfloat16 g_Gl[N * N];
__device__ float g_u[N];
__device__ float g_v[N];
__device__ float g_rowmax[N];

__device__ unsigned g_count = 0;
__device__ unsigned g_gen   = 0;
__device__ unsigned g_delta[2] = {0, 0};

// ---------------- acquire/release grid barrier ---------------------------------
__device__ __forceinline__ void grid_sync() {
    __syncthreads();
    if (threadIdx.x == 0) {
        unsigned my;
        asm volatile("ld.acquire.gpu.global.u32 %0, [%1];" : "=r"(my) : "l"(&g_gen));
        unsigned old;
        asm volatile("atom.release.gpu.global.add.u32 %0, [%1], %2;"
                     : "=r"(old) : "l"(&g_count), "r"(1u));
        if (old == SGRID - 1) {
            asm volatile("st.relaxed.gpu.global.u32 [%0], %1;" :: "l"(&g_count), "r"(0u));
            asm volatile("st.release.gpu.global.u32 [%0], %1;" :: "l"(&g_gen), "r"(my + 1u));
        } else {
            unsigned cur;
            do {
                asm volatile("ld.acquire.gpu.global.u32 %0, [%1];" : "=r"(cur) : "l"(&g_gen));
            } while (cur == my);
        }
    }
    __syncthreads();
}

// ---------------- prep kernels ---------------------------------------------------
__global__ void rowmax_kernel(const float* __restrict__ A) {
    int row = blockIdx.x;
    const float* a = A + (size_t)row * N;
    float m = -3.0e38f;
    for (int j = threadIdx.x; j < N; j += blockDim.x) m = fmaxf(m, a[j]);
    __shared__ float s[256];
    s[threadIdx.x] = m;
    __syncthreads();
    for (int o = 128; o > 0; o >>= 1) {
        if (threadIdx.x < o) s[threadIdx.x] = fmaxf(s[threadIdx.x], s[threadIdx.x + o]);
        __syncthreads();
    }
    if (threadIdx.x == 0) g_rowmax[row] = s[0];
}

__global__ void exp_kernel(const float* __restrict__ A) {
    __shared__ float tile[32][33];
    int x = blockIdx.x * 32 + threadIdx.x;
    int y = blockIdx.y * 32 + threadIdx.y;
    float rm = g_rowmax[y];
    float e = expf(TEMP * (A[(size_t)y * N + x] - rm));
    g_E[(size_t)y * N + x] = e;
    tile[threadIdx.y][threadIdx.x] = e;
    __syncthreads();
    int tx = blockIdx.y * 32 + threadIdx.x;
    int ty = blockIdx.x * 32 + threadIdx.y;
    g_ET[(size_t)ty * N + tx] = tile[threadIdx.x][threadIdx.y];
}

__global__ void init_kernel() {
    int i = blockIdx.x * blockDim.x + threadIdx.x;
    if (i < N) { g_v[i] = 1.0f; g_u[i] = 1.0f; }
    if (i < 2) g_delta[i] = 0u;
}

// ---------------- persistent Sinkhorn (early-exit) ------------------------------
__global__ void __launch_bounds__(SBLOCK, 1) sinkhorn_kernel() {
    const int tid  = threadIdx.x;
    const int wid  = tid >> 5;
    const int lane = tid & 31;
    const int rloc = wid >> 1;
    const int half = wid & 1;
    const int row  = blockIdx.x * RPC + rloc;

    __shared__ float svec[N];
    __shared__ float spart[WPC];
    __shared__ float sdel[RPC];
    __shared__ float sflag;
    float4* svec4 = (float4*)svec;

    const float4* erow  = (const float4*)g_E  + (size_t)row * (N / 4) + half * (N / 8);
    const float4* etrow = (const float4*)g_ET + (size_t)row * (N / 4) + half * (N / 8);
    const float4* sv = svec4 + half * (N / 8);

    float u_old = 1.0f;

    for (int t = 0; t < ITERS; ++t) {
        {
            const float4* v4 = (const float4*)g_v;
            if (tid < N / 4) svec4[tid] = v4[tid];
            __syncthreads();

            float s = 0.0f;
#pragma unroll 4
            for (int jb = 0; jb < N / 8; jb += 32) {
                float4 e  = erow[jb + lane];
                float4 vv = sv[jb + lane];
                s += e.x * vv.x + e.y * vv.y + e.z * vv.z + e.w * vv.w;
            }
#pragma unroll
            for (int o = 16; o > 0; o >>= 1) s += __shfl_xor_sync(0xffffffffu, s, o);
            if (lane == 0) spart[wid] = s;
            __syncthreads();

            if (half == 0 && lane == 0) {
                float tot = spart[wid] + spart[wid + 1];
                float un = 1.0f / tot;
                g_u[row] = un;
                sdel[rloc] = fabsf(un - u_old) / u_old;
                u_old = un;
            }
            __syncthreads();
            if (tid == 0) {
                float dm = 0.0f;
#pragma unroll
                for (int i = 0; i < RPC; ++i) dm = fmaxf(dm, sdel[i]);
                atomicMax(&g_delta[t & 1], __float_as_uint(dm));
            }
        }
        grid_sync();

        if (tid == 0) {
            unsigned db;
            asm volatile("ld.acquire.gpu.global.u32 %0, [%1];" : "=r"(db) : "l"(&g_delta[t & 1]));
            sflag = (t > 0 && __uint_as_float(db) < EPS_CONV) ? 1.0f : 0.0f;
            g_delta[(t + 1) & 1] = 0u;
        }

        bool conv;
        {
            const float4* u4 = (const float4*)g_u;
            if (tid < N / 4) svec4[tid] = u4[tid];
            __syncthreads();
            conv = (sflag > 0.5f);

            float s = 0.0f;
#pragma unroll 4
            for (int jb = 0; jb < N / 8; jb += 32) {
                float4 e  = etrow[jb + lane];
                float4 uu = sv[jb + lane];
                s += e.x * uu.x + e.y * uu.y + e.z * uu.z + e.w * uu.w;
            }
#pragma unroll
            for (int o = 16; o > 0; o >>= 1) s += __shfl_xor_sync(0xffffffffu, s, o);
            if (lane == 0) spart[wid] = s;
            __syncthreads();
            if (half == 0 && lane == 0) {
                float tot = spart[wid] + spart[wid + 1];
                g_v[row] = 1.0f / tot;
            }
        }
        grid_sync();

        if (conv) break;
    }
}

// ---------------- F/G with bf16 hi/lo split --------------------------------------
__device__ __forceinline__ uint32_t pack_bf2(__nv_bfloat16 a, __nv_bfloat16 b) {
    __nv_bfloat162 t = __halves2bfloat162(a, b);
    return *(uint32_t*)&t;
}

__global__ void fg_kernel() {
    int row = blockIdx.x;
    int t   = threadIdx.x;
    float uu = g_u[row];

    const float4* erow = (const float4*)g_E + (size_t)row * (N / 4);
    const float4* v4   = (const float4*)g_v;

    float4 e0 = erow[t * 2], e1 = erow[t * 2 + 1];
    float4 w0 = v4[t * 2],   w1 = v4[t * 2 + 1];

    float m[8];
    m[0] = uu * e0.x * w0.x;  m[1] = uu * e0.y * w0.y;
    m[2] = uu * e0.z * w0.z;  m[3] = uu * e0.w * w0.w;
    m[4] = uu * e1.x * w1.x;  m[5] = uu * e1.y * w1.y;
    m[6] = uu * e1.z * w1.z;  m[7] = uu * e1.w * w1.w;

    float tsum = 0.0f;
#pragma unroll
    for (int e = 0; e < 8; ++e) tsum += m[e];

    __shared__ float ss[256];
    ss[t] = tsum;
    __syncthreads();
    float run = tsum;
#pragma unroll
    for (int o = 1; o < 256; o <<= 1) {
        float y = (t >= o) ? ss[t - o] : 0.0f;
        __syncthreads();
        run += y;
        ss[t] = run;
        __syncthreads();
    }
    float total = ss[255];
    float pf = run - tsum;

    float g[8];
#pragma unroll
    for (int e = 0; e < 8; ++e) { g[e] = total - pf; pf += m[e]; }

    __nv_bfloat16 fh[8], fl[8], gh[8], gl[8];
#pragma unroll
    for (int e = 0; e < 8; ++e) {
        fh[e] = __float2bfloat16(m[e]);
        fl[e] = __float2bfloat16(m[e] - __bfloat162float(fh[e]));
        gh[e] = __float2bfloat16(g[e]);
        gl[e] = __float2bfloat16(g[e] - __bfloat162float(gh[e]));
    }

    size_t base = ((size_t)row * N) / 8 + t;   // uint4 index (8 bf16 per uint4)
    ((uint4*)g_Fh)[base] = make_uint4(pack_bf2(fh[0],fh[1]), pack_bf2(fh[2],fh[3]),
                                      pack_bf2(fh[4],fh[5]), pack_bf2(fh[6],fh[7]));
    ((uint4*)g_Fl)[base] = make_uint4(pack_bf2(fl[0],fl[1]), pack_bf2(fl[2],fl[3]),
                                      pack_bf2(fl[4],fl[5]), pack_bf2(fl[6],fl[7]));
    ((uint4*)g_Gh)[base] = make_uint4(pack_bf2(gh[0],gh[1]), pack_bf2(gh[2],gh[3]),
                                      pack_bf2(gh[4],gh[5]), pack_bf2(gh[6],gh[7]));
    ((uint4*)g_Gl)[base] = make_uint4(pack_bf2(gl[0],gl[1]), pack_bf2(gl[2],gl[3]),
                                      pack_bf2(gl[4],gl[5]), pack_bf2(gl[6],gl[7]));
}

// ================= mma.sync bf16 split GEMM =======================================
// C[a,b] = dot(F[a,:], G[b,:]) ≈ Fh·Gh + Fh·Gl + Fl·Gh, fp32 accum.
// Tiles: BM=128, BN=128, BK=32. 256 threads = 8 warps (4 M x 2 N), warp tile 32x64.
// BOTH operands are stored reduction-dim-contiguous ([row][k]) -> non-trans ldmatrix.

#define BK       32
#define KCHUNKS  (N / BK)              // 64
#define PITCH    40                    // bf16 per smem row (32 + 8 pad) -> 80B
#define TILE_B   (128 * PITCH * 2)     // 10240 bytes per tile
#define STAGE_B  (4 * TILE_B)          // Ah,Al,Bh,Bl
#define GT       256

__device__ __forceinline__ uint32_t smem_u32(const void* p) {
    uint32_t a;
    asm("{ .reg .u64 t; cvta.to.shared.u64 t, %1; cvt.u32.u64 %0, t; }" : "=r"(a) : "l"(p));
    return a;
}
__device__ __forceinline__ void cp16(uint32_t dst, const void* src) {
    asm volatile("cp.async.cg.shared.global [%0], [%1], 16;" :: "r"(dst), "l"(src));
}
__device__ __forceinline__ void cp_commit() { asm volatile("cp.async.commit_group;" ::: "memory"); }
__device__ __forceinline__ void cp_wait1()  { asm volatile("cp.async.wait_group 1;" ::: "memory"); }

__device__ __forceinline__ void ldsm4(uint32_t addr, uint32_t* r) {
    asm volatile("ldmatrix.sync.aligned.m8n8.x4.shared.b16 {%0,%1,%2,%3}, [%4];"
                 : "=r"(r[0]), "=r"(r[1]), "=r"(r[2]), "=r"(r[3]) : "r"(addr));
}
__device__ __forceinline__ void mma16816(float* c, const uint32_t* a, uint32_t b0, uint32_t b1) {
    asm volatile("mma.sync.aligned.m16n8k16.row.col.f32.bf16.bf16.f32 "
                 "{%0,%1,%2,%3}, {%4,%5,%6,%7}, {%8,%9}, {%0,%1,%2,%3};"
                 : "+f"(c[0]), "+f"(c[1]), "+f"(c[2]), "+f"(c[3])
                 : "r"(a[0]), "r"(a[1]), "r"(a[2]), "r"(a[3]), "r"(b0), "r"(b1));
}

// load one stage: Ah,Al rows [bi,bi+128), Bh,Bl rows [bj,bj+128), k window [k0,k0+32)
__device__ __forceinline__ void load_stage(uint32_t S, int bi, int bj, int k0, int tid) {
    const __nv_bfloat16* gs0 = g_Fh + (size_t)bi * N + k0;
    const __nv_bfloat16* gs1 = g_Fl + (size_t)bi * N + k0;
    const __nv_bfloat16* gs2 = g_Gh + (size_t)bj * N + k0;
    const __nv_bfloat16* gs3 = g_Gl + (size_t)bj * N + k0;
#pragma unroll
    for (int i = 0; i < 8; ++i) {
        int p = tid + i * GT;              // 0..2047
        int tile = p >> 9;                 // 0..3
        int r = (p >> 2) & 127;
        int s = p & 3;
        const __nv_bfloat16* src = (tile == 0 ? gs0 : tile == 1 ? gs1 : tile == 2 ? gs2 : gs3)
                                   + (size_t)r * N + s * 8;
        uint32_t dst = S + tile * TILE_B + r * (PITCH * 2) + s * 16;
        cp16(dst, src);
    }
}

__global__ void __launch_bounds__(GT, 2) gemm_kernel(float* __restrict__ C) {
    extern __shared__ char smem[];
    const uint32_t SB = smem_u32(smem);

    const int tid  = threadIdx.x;
    const int lane = tid & 31;
    const int wid  = tid >> 5;
    const int wm   = wid & 3;          // warp M index (0..3)
    const int wn   = wid >> 2;         // warp N index (0..1)
    const int bi   = blockIdx.y * 128;
    const int bj   = blockIdx.x * 128;

    // ldmatrix lane address components (identical scheme for A and B; both [row][k])
    const int arow = lane & 15;                        // rows 0..15 within 16-row group
    const int asel = lane >> 4;                        // k half select
    const int brow = (lane & 7) + ((lane >> 4) << 3);  // n row: m0/m1->0..7, m2/m3->8..15
    const int bsel = (lane >> 3) & 1;                  // k half: m0->lo, m1->hi, m2->lo, m3->hi

    float acc[2][8][4];
#pragma unroll
    for (int mi = 0; mi < 2; ++mi)
#pragma unroll
        for (int ni = 0; ni < 8; ++ni)
#pragma unroll
            for (int q = 0; q < 4; ++q) acc[mi][ni][q] = 0.0f;

    // preload stages 0,1
    load_stage(SB,           bi, bj, 0,  tid); cp_commit();
    load_stage(SB + STAGE_B, bi, bj, BK, tid); cp_commit();

    for (int c = 0; c < KCHUNKS; ++c) {
        const uint32_t S = SB + (c & 1) * STAGE_B;
        cp_wait1();
        __syncthreads();

        const uint32_t Sah = S;
        const uint32_t Sal = S + TILE_B;
        const uint32_t Sbh = S + 2 * TILE_B;
        const uint32_t Sbl = S + 3 * TILE_B;

#pragma unroll
        for (int kk = 0; kk < BK; kk += 16) {
            uint32_t ah[2][4], al[2][4];
#pragma unroll
            for (int mi = 0; mi < 2; ++mi) {
                uint32_t off = (uint32_t)((wm * 32 + mi * 16 + arow) * (PITCH * 2) + (kk + asel * 8) * 2);
                ldsm4(Sah + off, ah[mi]);
                ldsm4(Sal + off, al[mi]);
            }
#pragma unroll
            for (int np = 0; np < 4; ++np) {
                uint32_t bh[4], bl[4];
                uint32_t off = (uint32_t)((wn * 64 + np * 16 + brow) * (PITCH * 2) + (kk + bsel * 8) * 2);
                ldsm4(Sbh + off, bh);   // NON-trans: B tile is [n][k], same as A
                ldsm4(Sbl + off, bl);
#pragma unroll
                for (int mi = 0; mi < 2; ++mi) {
                    mma16816(acc[mi][2 * np],     ah[mi], bh[0], bh[1]);
                    mma16816(acc[mi][2 * np + 1], ah[mi], bh[2], bh[3]);
                    mma16816(acc[mi][2 * np],     ah[mi], bl[0], bl[1]);
                    mma16816(acc[mi][2 * np + 1], ah[mi], bl[2], bl[3]);
                    mma16816(acc[mi][2 * np],     al[mi], bh[0], bh[1]);
                    mma16816(acc[mi][2 * np + 1], al[mi], bh[2], bh[3]);
                }
            }
        }

        __syncthreads();
        if (c + 2 < KCHUNKS) load_stage(S, bi, bj, (c + 2) * BK, tid);
        cp_commit();   // always commit (possibly empty) to keep wait_group bookkeeping
    }

    // epilogue: write fp32 accumulators
    const int gid = lane >> 2;   // group id 0..7
    const int tig = lane & 3;    // thread in group
#pragma unroll
    for (int mi = 0; mi < 2; ++mi) {
#pragma unroll
        for (int ni = 0; ni < 8; ++ni) {
            int a0 = bi + wm * 32 + mi * 16 + gid;
            int b0 = bj + wn * 64 + ni * 8 + tig * 2;
            *(float2*)(C + (size_t)a0 * N + b0)       = make_float2(acc[mi][ni][0], acc[mi][ni][1]);
            *(float2*)(C + (size_t)(a0 + 8) * N + b0) = make_float2(acc[mi][ni][2], acc[mi][ni][3]);
        }
    }
}

// ---------------- launch --------------------------------------------------------
extern "C" void kernel_launch(void* const* d_in, const int* in_sizes, int n_in,
                              void* d_out, int out_size) {
    const float* A = (const float*)d_in[0];
    float* out = (float*)d_out;

    static const int GEMM_SMEM = 2 * STAGE_B;   // 81920 bytes
    cudaFuncSetAttribute(gemm_kernel, cudaFuncAttributeMaxDynamicSharedMemorySize, GEMM_SMEM);

    rowmax_kernel<<<N, 256>>>(A);
    exp_kernel<<<dim3(N / 32, N / 32), dim3(32, 32)>>>(A);
    init_kernel<<<(N + 255) / 256, 256>>>();
    sinkhorn_kernel<<<SGRID, SBLOCK>>>();
    fg_kernel<<<N, 256>>>();
    gemm_kernel<<<dim3(N / 128, N / 128), GT, GEMM_SMEM>>>(out);
}

// round 6
// speedup vs baseline: 39.0444x; 1.5570x over previous
#include <cuda_runtime.h>
#include <cuda_bf16.h>
#include <math.h>
#include <stdint.h>

#define N       2048
#define ITERS   1000
#define TEMP    100.0f
#define EPS_CONV 1e-5f

#define SGRID   128
#define SBLOCK  1024
#define WPC     (SBLOCK/32)
#define RPC     (WPC/2)

// ---------------- scratch (static device globals; allocation-free) -------------
__device__ float g_E [N * N];
__device__ float g_ET[N * N];
__device__ __nv_bfloat16 g_Fh[N * N];
__device__ __nv_bfloat16 g_Fl[N * N];
__device__ __nv_bfloat16 g_Gh[N * N];
__device__ __nv_bfloat16 g_Gl[N * N];
__device__ float g_u[N];
__device__ float g_v[N];
__device__ float g_rowmax[N];

__device__ unsigned g_count = 0;
__device__ unsigned g_gen   = 0;
__device__ unsigned g_delta[2] = {0, 0};

// ---------------- acquire/release grid barrier ---------------------------------
__device__ __forceinline__ void grid_sync() {
    __syncthreads();
    if (threadIdx.x == 0) {
        unsigned my;
        asm volatile("ld.acquire.gpu.global.u32 %0, [%1];" : "=r"(my) : "l"(&g_gen));
        unsigned old;
        asm volatile("atom.release.gpu.global.add.u32 %0, [%1], %2;"
                     : "=r"(old) : "l"(&g_count), "r"(1u));
        if (old == SGRID - 1) {
            asm volatile("st.relaxed.gpu.global.u32 [%0], %1;" :: "l"(&g_count), "r"(0u));
            asm volatile("st.release.gpu.global.u32 [%0], %1;" :: "l"(&g_gen), "r"(my + 1u));
        } else {
            unsigned cur;
            do {
                asm volatile("ld.acquire.gpu.global.u32 %0, [%1];" : "=r"(cur) : "l"(&g_gen));
            } while (cur == my);
        }
    }
    __syncthreads();
}

// ---------------- prep kernels ---------------------------------------------------
__global__ void rowmax_kernel(const float* __restrict__ A) {
    int row = blockIdx.x;
    const float* a = A + (size_t)row * N;
    float m = -3.0e38f;
    for (int j = threadIdx.x; j < N; j += blockDim.x) m = fmaxf(m, a[j]);
    __shared__ float s[256];
    s[threadIdx.x] = m;
    __syncthreads();
    for (int o = 128; o > 0; o >>= 1) {
        if (threadIdx.x < o) s[threadIdx.x] = fmaxf(s[threadIdx.x], s[threadIdx.x + o]);
        __syncthreads();
    }
    if (threadIdx.x == 0) g_rowmax[row] = s[0];
}

__global__ void exp_kernel(const float* __restrict__ A) {
    __shared__ float tile[32][33];
    int x = blockIdx.x * 32 + threadIdx.x;
    int y = blockIdx.y * 32 + threadIdx.y;
    float rm = g_rowmax[y];
    float e = expf(TEMP * (A[(size_t)y * N + x] - rm));
    g_E[(size_t)y * N + x] = e;
    tile[threadIdx.y][threadIdx.x] = e;
    __syncthreads();
    int tx = blockIdx.y * 32 + threadIdx.x;
    int ty = blockIdx.x * 32 + threadIdx.y;
    g_ET[(size_t)ty * N + tx] = tile[threadIdx.x][threadIdx.y];
}

__global__ void init_kernel() {
    int i = blockIdx.x * blockDim.x + threadIdx.x;
    if (i < N) { g_v[i] = 1.0f; g_u[i] = 1.0f; }
    if (i < 2) g_delta[i] = 0u;
}

// ---------------- persistent Sinkhorn (early-exit) ------------------------------
__global__ void __launch_bounds__(SBLOCK, 1) sinkhorn_kernel() {
    const int tid  = threadIdx.x;
    const int wid  = tid >> 5;
    const int lane = tid & 31;
    const int rloc = wid >> 1;
    const int half = wid & 1;
    const int row  = blockIdx.x * RPC + rloc;

    __shared__ float svec[N];
    __shared__ float spart[WPC];
    __shared__ float sdel[RPC];
    __shared__ float sflag;
    float4* svec4 = (float4*)svec;

    const float4* erow  = (const float4*)g_E  + (size_t)row * (N / 4) + half * (N / 8);
    const float4* etrow = (const float4*)g_ET + (size_t)row * (N / 4) + half * (N / 8);
    const float4* sv = svec4 + half * (N / 8);

    float u_old = 1.0f;

    for (int t = 0; t < ITERS; ++t) {
        {
            const float4* v4 = (const float4*)g_v;
            if (tid < N / 4) svec4[tid] = v4[tid];
            __syncthreads();

            float s = 0.0f;
#pragma unroll 4
            for (int jb = 0; jb < N / 8; jb += 32) {
                float4 e  = erow[jb + lane];
                float4 vv = sv[jb + lane];
                s += e.x * vv.x + e.y * vv.y + e.z * vv.z + e.w * vv.w;
            }
#pragma unroll
            for (int o = 16; o > 0; o >>= 1) s += __shfl_xor_sync(0xffffffffu, s, o);
            if (lane == 0) spart[wid] = s;
            __syncthreads();

            if (half == 0 && lane == 0) {
                float tot = spart[wid] + spart[wid + 1];
                float un = 1.0f / tot;
                g_u[row] = un;
                sdel[rloc] = fabsf(un - u_old) / u_old;
                u_old = un;
            }
            __syncthreads();
            if (tid == 0) {
                float dm = 0.0f;
#pragma unroll
                for (int i = 0; i < RPC; ++i) dm = fmaxf(dm, sdel[i]);
                atomicMax(&g_delta[t & 1], __float_as_uint(dm));
            }
        }
        grid_sync();

        if (tid == 0) {
            unsigned db;
            asm volatile("ld.acquire.gpu.global.u32 %0, [%1];" : "=r"(db) : "l"(&g_delta[t & 1]));
            sflag = (t > 0 && __uint_as_float(db) < EPS_CONV) ? 1.0f : 0.0f;
            g_delta[(t + 1) & 1] = 0u;
        }

        bool conv;
        {
            const float4* u4 = (const float4*)g_u;
            if (tid < N / 4) svec4[tid] = u4[tid];
            __syncthreads();
            conv = (sflag > 0.5f);

            float s = 0.0f;
#pragma unroll 4
            for (int jb = 0; jb < N / 8; jb += 32) {
                float4 e  = etrow[jb + lane];
                float4 uu = sv[jb + lane];
                s += e.x * uu.x + e.y * uu.y + e.z * uu.z + e.w * uu.w;
            }
#pragma unroll
            for (int o = 16; o > 0; o >>= 1) s += __shfl_xor_sync(0xffffffffu, s, o);
            if (lane == 0) spart[wid] = s;
            __syncthreads();
            if (half == 0 && lane == 0) {
                float tot = spart[wid] + spart[wid + 1];
                g_v[row] = 1.0f / tot;
            }
        }
        grid_sync();

        if (conv) break;
    }
}

// ---------------- F/G with bf16 hi/lo split --------------------------------------
__device__ __forceinline__ uint32_t pack_bf2(__nv_bfloat16 a, __nv_bfloat16 b) {
    __nv_bfloat162 t = __halves2bfloat162(a, b);
    return *(uint32_t*)&t;
}

__global__ void fg_kernel() {
    int row = blockIdx.x;
    int t   = threadIdx.x;
    float uu = g_u[row];

    const float4* erow = (const float4*)g_E + (size_t)row * (N / 4);
    const float4* v4   = (const float4*)g_v;

    float4 e0 = erow[t * 2], e1 = erow[t * 2 + 1];
    float4 w0 = v4[t * 2],   w1 = v4[t * 2 + 1];

    float m[8];
    m[0] = uu * e0.x * w0.x;  m[1] = uu * e0.y * w0.y;
    m[2] = uu * e0.z * w0.z;  m[3] = uu * e0.w * w0.w;
    m[4] = uu * e1.x * w1.x;  m[5] = uu * e1.y * w1.y;
    m[6] = uu * e1.z * w1.z;  m[7] = uu * e1.w * w1.w;

    float tsum = 0.0f;
#pragma unroll
    for (int e = 0; e < 8; ++e) tsum += m[e];

    __shared__ float ss[256];
    ss[t] = tsum;
    __syncthreads();
    float run = tsum;
#pragma unroll
    for (int o = 1; o < 256; o <<= 1) {
        float y = (t >= o) ? ss[t - o] : 0.0f;
        __syncthreads();
        run += y;
        ss[t] = run;
        __syncthreads();
    }
    float total = ss[255];
    float pf = run - tsum;

    float g[8];
#pragma unroll
    for (int e = 0; e < 8; ++e) { g[e] = total - pf; pf += m[e]; }

    __nv_bfloat16 fh[8], fl[8], gh[8], gl[8];
#pragma unroll
    for (int e = 0; e < 8; ++e) {
        fh[e] = __float2bfloat16(m[e]);
        fl[e] = __float2bfloat16(m[e] - __bfloat162float(fh[e]));
        gh[e] = __float2bfloat16(g[e]);
        gl[e] = __float2bfloat16(g[e] - __bfloat162float(gh[e]));
    }

    size_t base = ((size_t)row * N) / 8 + t;   // uint4 index (8 bf16 per uint4)
    ((uint4*)g_Fh)[base] = make_uint4(pack_bf2(fh[0],fh[1]), pack_bf2(fh[2],fh[3]),
                                      pack_bf2(fh[4],fh[5]), pack_bf2(fh[6],fh[7]));
    ((uint4*)g_Fl)[base] = make_uint4(pack_bf2(fl[0],fl[1]), pack_bf2(fl[2],fl[3]),
                                      pack_bf2(fl[4],fl[5]), pack_bf2(fl[6],fl[7]));
    ((uint4*)g_Gh)[base] = make_uint4(pack_bf2(gh[0],gh[1]), pack_bf2(gh[2],gh[3]),
                                      pack_bf2(gh[4],gh[5]), pack_bf2(gh[6],gh[7]));
    ((uint4*)g_Gl)[base] = make_uint4(pack_bf2(gl[0],gl[1]), pack_bf2(gl[2],gl[3]),
                                      pack_bf2(gl[4],gl[5]), pack_bf2(gl[6],gl[7]));
}

// ================= mma.sync bf16 split GEMM =======================================
// C[a,b] = dot(F[a,:], G[b,:]) ≈ Fh·Gh + Fh·Gl + Fl·Gh, fp32 accum.
// BM=128, BN=128, BK=32. 8 warps (4M x 2N), warp tile 32x64.
// Inner loop restructured as independent-accumulator sweeps (acc reuse distance 8).

#define BK       32
#define KCHUNKS  (N / BK)              // 64
#define PITCH    40                    // bf16 per smem row (32 + 8 pad) -> 80B
#define TILE_B   (128 * PITCH * 2)     // 10240 bytes per tile
#define STAGE_B  (4 * TILE_B)          // Ah,Al,Bh,Bl
#define GT       256

__device__ __forceinline__ uint32_t smem_u32(const void* p) {
    uint32_t a;
    asm("{ .reg .u64 t; cvta.to.shared.u64 t, %1; cvt.u32.u64 %0, t; }" : "=r"(a) : "l"(p));
    return a;
}
__device__ __forceinline__ void cp16(uint32_t dst, const void* src) {
    asm volatile("cp.async.cg.shared.global [%0], [%1], 16;" :: "r"(dst), "l"(src));
}
__device__ __forceinline__ void cp_commit() { asm volatile("cp.async.commit_group;" ::: "memory"); }
__device__ __forceinline__ void cp_wait1()  { asm volatile("cp.async.wait_group 1;" ::: "memory"); }

__device__ __forceinline__ void ldsm4(uint32_t addr, uint32_t* r) {
    asm volatile("ldmatrix.sync.aligned.m8n8.x4.shared.b16 {%0,%1,%2,%3}, [%4];"
                 : "=r"(r[0]), "=r"(r[1]), "=r"(r[2]), "=r"(r[3]) : "r"(addr));
}
__device__ __forceinline__ void mma16816(float* c, const uint32_t* a, uint32_t b0, uint32_t b1) {
    asm volatile("mma.sync.aligned.m16n8k16.row.col.f32.bf16.bf16.f32 "
                 "{%0,%1,%2,%3}, {%4,%5,%6,%7}, {%8,%9}, {%0,%1,%2,%3};"
                 : "+f"(c[0]), "+f"(c[1]), "+f"(c[2]), "+f"(c[3])
                 : "r"(a[0]), "r"(a[1]), "r"(a[2]), "r"(a[3]), "r"(b0), "r"(b1));
}

// load one stage: Ah,Al rows [bi,bi+128), Bh,Bl rows [bj,bj+128), k window [k0,k0+32)
__device__ __forceinline__ void load_stage(uint32_t S, int bi, int bj, int k0, int tid) {
    const __nv_bfloat16* gs0 = g_Fh + (size_t)bi * N + k0;
    const __nv_bfloat16* gs1 = g_Fl + (size_t)bi * N + k0;
    const __nv_bfloat16* gs2 = g_Gh + (size_t)bj * N + k0;
    const __nv_bfloat16* gs3 = g_Gl + (size_t)bj * N + k0;
#pragma unroll
    for (int i = 0; i < 8; ++i) {
        int p = tid + i * GT;              // 0..2047
        int tile = p >> 9;                 // 0..3
        int r = (p >> 2) & 127;
        int s = p & 3;
        const __nv_bfloat16* src = (tile == 0 ? gs0 : tile == 1 ? gs1 : tile == 2 ? gs2 : gs3)
                                   + (size_t)r * N + s * 8;
        uint32_t dst = S + tile * TILE_B + r * (PITCH * 2) + s * 16;
        cp16(dst, src);
    }
}

__global__ void __launch_bounds__(GT, 2) gemm_kernel(float* __restrict__ C) {
    extern __shared__ char smem[];
    const uint32_t SB = smem_u32(smem);

    const int tid  = threadIdx.x;
    const int lane = tid & 31;
    const int wid  = tid >> 5;
    const int wm   = wid & 3;          // warp M index (0..3)
    const int wn   = wid >> 2;         // warp N index (0..1)
    const int bi   = blockIdx.y * 128;
    const int bj   = blockIdx.x * 128;

    // ldmatrix lane address components (both operands stored [row][k])
    const int arow = lane & 15;
    const int asel = lane >> 4;
    const int brow = (lane & 7) + ((lane >> 4) << 3);
    const int bsel = (lane >> 3) & 1;

    float acc[2][8][4];
#pragma unroll
    for (int mi = 0; mi < 2; ++mi)
#pragma unroll
        for (int ni = 0; ni < 8; ++ni)
#pragma unroll
            for (int q = 0; q < 4; ++q) acc[mi][ni][q] = 0.0f;

    // preload stages 0,1
    load_stage(SB,           bi, bj, 0,  tid); cp_commit();
    load_stage(SB + STAGE_B, bi, bj, BK, tid); cp_commit();

    for (int c = 0; c < KCHUNKS; ++c) {
        const uint32_t S = SB + (c & 1) * STAGE_B;
        cp_wait1();
        __syncthreads();

        const uint32_t Sah = S;
        const uint32_t Sal = S + TILE_B;
        const uint32_t Sbh = S + 2 * TILE_B;
        const uint32_t Sbl = S + 3 * TILE_B;

#pragma unroll
        for (int kk = 0; kk < BK; kk += 16) {
            // ---- A fragments for this k-slice (shared by all sweeps) ----
            uint32_t ah[2][4], al[2][4];
#pragma unroll
            for (int mi = 0; mi < 2; ++mi) {
                uint32_t off = (uint32_t)((wm * 32 + mi * 16 + arow) * (PITCH * 2) + (kk + asel * 8) * 2);
                ldsm4(Sah + off, ah[mi]);
                ldsm4(Sal + off, al[mi]);
            }
            // ---- process np in pairs; 3 sweeps of 8 independent-acc MMAs ----
#pragma unroll
            for (int h = 0; h < 2; ++h) {
                uint32_t bh[2][4], bl[2][4];
#pragma unroll
                for (int q = 0; q < 2; ++q) {
                    int np = h * 2 + q;
                    uint32_t off = (uint32_t)((wn * 64 + np * 16 + brow) * (PITCH * 2) + (kk + bsel * 8) * 2);
                    ldsm4(Sbh + off, bh[q]);
                    ldsm4(Sbl + off, bl[q]);
                }
                // sweep 1: Fh * Gh  (8 distinct accumulators)
#pragma unroll
                for (int q = 0; q < 2; ++q) {
                    int np = h * 2 + q;
#pragma unroll
                    for (int mi = 0; mi < 2; ++mi) {
                        mma16816(acc[mi][2 * np],     ah[mi], bh[q][0], bh[q][1]);
                        mma16816(acc[mi][2 * np + 1], ah[mi], bh[q][2], bh[q][3]);
                    }
                }
                // sweep 2: Fh * Gl
#pragma unroll
                for (int q = 0; q < 2; ++q) {
                    int np = h * 2 + q;
#pragma unroll
                    for (int mi = 0; mi < 2; ++mi) {
                        mma16816(acc[mi][2 * np],     ah[mi], bl[q][0], bl[q][1]);
                        mma16816(acc[mi][2 * np + 1], ah[mi], bl[q][2], bl[q][3]);
                    }
                }
                // sweep 3: Fl * Gh
#pragma unroll
                for (int q = 0; q < 2; ++q) {
                    int np = h * 2 + q;
#pragma unroll
                    for (int mi = 0; mi < 2; ++mi) {
                        mma16816(acc[mi][2 * np],     al[mi], bh[q][0], bh[q][1]);
                        mma16816(acc[mi][2 * np + 1], al[mi], bh[q][2], bh[q][3]);
                    }
                }
            }
        }

        __syncthreads();
        if (c + 2 < KCHUNKS) load_stage(S, bi, bj, (c + 2) * BK, tid);
        cp_commit();   // always commit (possibly empty) to keep wait_group bookkeeping
    }

    // epilogue
    const int gid = lane >> 2;
    const int tig = lane & 3;
#pragma unroll
    for (int mi = 0; mi < 2; ++mi) {
#pragma unroll
        for (int ni = 0; ni < 8; ++ni) {
            int a0 = bi + wm * 32 + mi * 16 + gid;
            int b0 = bj + wn * 64 + ni * 8 + tig * 2;
            *(float2*)(C + (size_t)a0 * N + b0)       = make_float2(acc[mi][ni][0], acc[mi][ni][1]);
            *(float2*)(C + (size_t)(a0 + 8) * N + b0) = make_float2(acc[mi][ni][2], acc[mi][ni][3]);
        }
    }
}

// ---------------- launch --------------------------------------------------------
extern "C" void kernel_launch(void* const* d_in, const int* in_sizes, int n_in,
                              void* d_out, int out_size) {
    const float* A = (const float*)d_in[0];
    float* out = (float*)d_out;

    static const int GEMM_SMEM = 2 * STAGE_B;   // 81920 bytes
    cudaFuncSetAttribute(gemm_kernel, cudaFuncAttributeMaxDynamicSharedMemorySize, GEMM_SMEM);

    rowmax_kernel<<<N, 256>>>(A);
    exp_kernel<<<dim3(N / 32, N / 32), dim3(32, 32)>>>(A);
    init_kernel<<<(N + 255) / 256, 256>>>();
    sinkhorn_kernel<<<SGRID, SBLOCK>>>();
    fg_kernel<<<N, 256>>>();
    gemm_kernel<<<dim3(N / 128, N / 128), GT, GEMM_SMEM>>>(out);
}

// round 7
// speedup vs baseline: 50.7311x; 1.2993x over previous
#include <cuda_runtime.h>
#include <cuda_fp16.h>
#include <math.h>
#include <stdint.h>

#define N       2048
#define ITERS   1000
#define TEMP    100.0f
#define EPS_CONV 1e-5f

#define SGRID   128
#define SBLOCK  1024
#define WPC     (SBLOCK/32)
#define RPC     (WPC/2)

// ---------------- scratch (static device globals; allocation-free) -------------
__device__ float g_E [N * N];
__device__ float g_ET[N * N];
__device__ __half g_Fh[N * N];
__device__ __half g_Fl[N * N];
__device__ __half g_Gh[N * N];
__device__ float g_u[N];
__device__ float g_v[N];
__device__ float g_rowmax[N];

__device__ unsigned g_count = 0;
__device__ unsigned g_gen   = 0;
__device__ unsigned g_delta[2] = {0, 0};

// ---------------- acquire/release grid barrier ---------------------------------
__device__ __forceinline__ void grid_sync() {
    __syncthreads();
    if (threadIdx.x == 0) {
        unsigned my;
        asm volatile("ld.acquire.gpu.global.u32 %0, [%1];" : "=r"(my) : "l"(&g_gen));
        unsigned old;
        asm volatile("atom.release.gpu.global.add.u32 %0, [%1], %2;"
                     : "=r"(old) : "l"(&g_count), "r"(1u));
        if (old == SGRID - 1) {
            asm volatile("st.relaxed.gpu.global.u32 [%0], %1;" :: "l"(&g_count), "r"(0u));
            asm volatile("st.release.gpu.global.u32 [%0], %1;" :: "l"(&g_gen), "r"(my + 1u));
        } else {
            unsigned cur;
            do {
                asm volatile("ld.acquire.gpu.global.u32 %0, [%1];" : "=r"(cur) : "l"(&g_gen));
            } while (cur == my);
        }
    }
    __syncthreads();
}

// ---------------- prep kernels ---------------------------------------------------
__global__ void rowmax_kernel(const float* __restrict__ A) {
    int row = blockIdx.x;
    const float* a = A + (size_t)row * N;
    float m = -3.0e38f;
    for (int j = threadIdx.x; j < N; j += blockDim.x) m = fmaxf(m, a[j]);
    __shared__ float s[256];
    s[threadIdx.x] = m;
    __syncthreads();
    for (int o = 128; o > 0; o >>= 1) {
        if (threadIdx.x < o) s[threadIdx.x] = fmaxf(s[threadIdx.x], s[threadIdx.x + o]);
        __syncthreads();
    }
    if (threadIdx.x == 0) g_rowmax[row] = s[0];
}

__global__ void exp_kernel(const float* __restrict__ A) {
    __shared__ float tile[32][33];
    int x = blockIdx.x * 32 + threadIdx.x;
    int y = blockIdx.y * 32 + threadIdx.y;
    float rm = g_rowmax[y];
    float e = expf(TEMP * (A[(size_t)y * N + x] - rm));
    g_E[(size_t)y * N + x] = e;
    tile[threadIdx.y][threadIdx.x] = e;
    __syncthreads();
    int tx = blockIdx.y * 32 + threadIdx.x;
    int ty = blockIdx.x * 32 + threadIdx.y;
    g_ET[(size_t)ty * N + tx] = tile[threadIdx.x][threadIdx.y];
}

__global__ void init_kernel() {
    int i = blockIdx.x * blockDim.x + threadIdx.x;
    if (i < N) { g_v[i] = 1.0f; g_u[i] = 1.0f; }
    if (i < 2) g_delta[i] = 0u;
}

// ---------------- persistent Sinkhorn (early-exit) ------------------------------
__global__ void __launch_bounds__(SBLOCK, 1) sinkhorn_kernel() {
    const int tid  = threadIdx.x;
    const int wid  = tid >> 5;
    const int lane = tid & 31;
    const int rloc = wid >> 1;
    const int half = wid & 1;
    const int row  = blockIdx.x * RPC + rloc;

    __shared__ float svec[N];
    __shared__ float spart[WPC];
    __shared__ float sdel[RPC];
    __shared__ float sflag;
    float4* svec4 = (float4*)svec;

    const float4* erow  = (const float4*)g_E  + (size_t)row * (N / 4) + half * (N / 8);
    const float4* etrow = (const float4*)g_ET + (size_t)row * (N / 4) + half * (N / 8);
    const float4* sv = svec4 + half * (N / 8);

    float u_old = 1.0f;

    for (int t = 0; t < ITERS; ++t) {
        {
            const float4* v4 = (const float4*)g_v;
            if (tid < N / 4) svec4[tid] = v4[tid];
            __syncthreads();

            float s = 0.0f;
#pragma unroll 4
            for (int jb = 0; jb < N / 8; jb += 32) {
                float4 e  = erow[jb + lane];
                float4 vv = sv[jb + lane];
                s += e.x * vv.x + e.y * vv.y + e.z * vv.z + e.w * vv.w;
            }
#pragma unroll
            for (int o = 16; o > 0; o >>= 1) s += __shfl_xor_sync(0xffffffffu, s, o);
            if (lane == 0) spart[wid] = s;
            __syncthreads();

            if (half == 0 && lane == 0) {
                float tot = spart[wid] + spart[wid + 1];
                float un = 1.0f / tot;
                g_u[row] = un;
                sdel[rloc] = fabsf(un - u_old) / u_old;
                u_old = un;
            }
            __syncthreads();
            if (tid == 0) {
                float dm = 0.0f;
#pragma unroll
                for (int i = 0; i < RPC; ++i) dm = fmaxf(dm, sdel[i]);
                atomicMax(&g_delta[t & 1], __float_as_uint(dm));
            }
        }
        grid_sync();

        if (tid == 0) {
            unsigned db;
            asm volatile("ld.acquire.gpu.global.u32 %0, [%1];" : "=r"(db) : "l"(&g_delta[t & 1]));
            sflag = (t > 0 && __uint_as_float(db) < EPS_CONV) ? 1.0f : 0.0f;
            g_delta[(t + 1) & 1] = 0u;
        }

        bool conv;
        {
            const float4* u4 = (const float4*)g_u;
            if (tid < N / 4) svec4[tid] = u4[tid];
            __syncthreads();
            conv = (sflag > 0.5f);

            float s = 0.0f;
#pragma unroll 4
            for (int jb = 0; jb < N / 8; jb += 32) {
                float4 e  = etrow[jb + lane];
                float4 uu = sv[jb + lane];
                s += e.x * uu.x + e.y * uu.y + e.z * uu.z + e.w * uu.w;
            }
#pragma unroll
            for (int o = 16; o > 0; o >>= 1) s += __shfl_xor_sync(0xffffffffu, s, o);
            if (lane == 0) spart[wid] = s;
            __syncthreads();
            if (half == 0 && lane == 0) {
                float tot = spart[wid] + spart[wid + 1];
                g_v[row] = 1.0f / tot;
            }
        }
        grid_sync();

        if (conv) break;
    }
}

// ---------------- F (fp16 hi/lo) and G (fp16 hi only) ----------------------------
__device__ __forceinline__ uint32_t pack_h2(__half a, __half b) {
    __half2 t = __halves2half2(a, b);
    return *(uint32_t*)&t;
}

__global__ void fg_kernel() {
    int row = blockIdx.x;
    int t   = threadIdx.x;
    float uu = g_u[row];

    const float4* erow = (const float4*)g_E + (size_t)row * (N / 4);
    const float4* v4   = (const float4*)g_v;

    float4 e0 = erow[t * 2], e1 = erow[t * 2 + 1];
    float4 w0 = v4[t * 2],   w1 = v4[t * 2 + 1];

    float m[8];
    m[0] = uu * e0.x * w0.x;  m[1] = uu * e0.y * w0.y;
    m[2] = uu * e0.z * w0.z;  m[3] = uu * e0.w * w0.w;
    m[4] = uu * e1.x * w1.x;  m[5] = uu * e1.y * w1.y;
    m[6] = uu * e1.z * w1.z;  m[7] = uu * e1.w * w1.w;

    float tsum = 0.0f;
#pragma unroll
    for (int e = 0; e < 8; ++e) tsum += m[e];

    __shared__ float ss[256];
    ss[t] = tsum;
    __syncthreads();
    float run = tsum;
#pragma unroll
    for (int o = 1; o < 256; o <<= 1) {
        float y = (t >= o) ? ss[t - o] : 0.0f;
        __syncthreads();
        run += y;
        ss[t] = run;
        __syncthreads();
    }
    float total = ss[255];
    float pf = run - tsum;

    float g[8];
#pragma unroll
    for (int e = 0; e < 8; ++e) { g[e] = total - pf; pf += m[e]; }

    __half fh[8], fl[8], gh[8];
#pragma unroll
    for (int e = 0; e < 8; ++e) {
        fh[e] = __float2half_rn(m[e]);
        fl[e] = __float2half_rn(m[e] - __half2float(fh[e]));
        gh[e] = __float2half_rn(g[e]);
    }

    size_t base = ((size_t)row * N) / 8 + t;   // uint4 index (8 halves per uint4)
    ((uint4*)g_Fh)[base] = make_uint4(pack_h2(fh[0],fh[1]), pack_h2(fh[2],fh[3]),
                                      pack_h2(fh[4],fh[5]), pack_h2(fh[6],fh[7]));
    ((uint4*)g_Fl)[base] = make_uint4(pack_h2(fl[0],fl[1]), pack_h2(fl[2],fl[3]),
                                      pack_h2(fl[4],fl[5]), pack_h2(fl[6],fl[7]));
    ((uint4*)g_Gh)[base] = make_uint4(pack_h2(gh[0],gh[1]), pack_h2(gh[2],gh[3]),
                                      pack_h2(gh[4],gh[5]), pack_h2(gh[6],gh[7]));
}

// ================= mma.sync fp16 2-term GEMM ======================================
// C[a,b] = dot(F[a,:], G[b,:]) ≈ Fh·Gh + Fl·Gh  (G rounded to fp16, err ≤ 2^-11)
// BM=128, BN=128, BK=32. 8 warps (4M x 2N), warp tile 32x64, indep-acc sweeps.

#define BK       32
#define KCHUNKS  (N / BK)              // 64
#define PITCH    40                    // halves per smem row (32 + 8 pad) -> 80B
#define TILE_B   (128 * PITCH * 2)     // 10240 bytes per tile
#define STAGE_B  (3 * TILE_B)          // Ah, Al, Bh
#define GT       256

__device__ __forceinline__ uint32_t smem_u32(const void* p) {
    uint32_t a;
    asm("{ .reg .u64 t; cvta.to.shared.u64 t, %1; cvt.u32.u64 %0, t; }" : "=r"(a) : "l"(p));
    return a;
}
__device__ __forceinline__ void cp16(uint32_t dst, const void* src) {
    asm volatile("cp.async.cg.shared.global [%0], [%1], 16;" :: "r"(dst), "l"(src));
}
__device__ __forceinline__ void cp_commit() { asm volatile("cp.async.commit_group;" ::: "memory"); }
__device__ __forceinline__ void cp_wait1()  { asm volatile("cp.async.wait_group 1;" ::: "memory"); }

__device__ __forceinline__ void ldsm4(uint32_t addr, uint32_t* r) {
    asm volatile("ldmatrix.sync.aligned.m8n8.x4.shared.b16 {%0,%1,%2,%3}, [%4];"
                 : "=r"(r[0]), "=r"(r[1]), "=r"(r[2]), "=r"(r[3]) : "r"(addr));
}
__device__ __forceinline__ void mma16816(float* c, const uint32_t* a, uint32_t b0, uint32_t b1) {
    asm volatile("mma.sync.aligned.m16n8k16.row.col.f32.f16.f16.f32 "
                 "{%0,%1,%2,%3}, {%4,%5,%6,%7}, {%8,%9}, {%0,%1,%2,%3};"
                 : "+f"(c[0]), "+f"(c[1]), "+f"(c[2]), "+f"(c[3])
                 : "r"(a[0]), "r"(a[1]), "r"(a[2]), "r"(a[3]), "r"(b0), "r"(b1));
}

// load one stage: Ah,Al rows [bi,bi+128), Bh rows [bj,bj+128), k window [k0,k0+32)
__device__ __forceinline__ void load_stage(uint32_t S, int bi, int bj, int k0, int tid) {
    const __half* gs0 = g_Fh + (size_t)bi * N + k0;
    const __half* gs1 = g_Fl + (size_t)bi * N + k0;
    const __half* gs2 = g_Gh + (size_t)bj * N + k0;
#pragma unroll
    for (int i = 0; i < 6; ++i) {
        int p = tid + i * GT;              // 0..1535
        int tile = p >> 9;                 // 0..2
        int r = (p >> 2) & 127;
        int s = p & 3;
        const __half* src = (tile == 0 ? gs0 : tile == 1 ? gs1 : gs2)
                            + (size_t)r * N + s * 8;
        uint32_t dst = S + tile * TILE_B + r * (PITCH * 2) + s * 16;
        cp16(dst, src);
    }
}

__global__ void __launch_bounds__(GT, 2) gemm_kernel(float* __restrict__ C) {
    extern __shared__ char smem[];
    const uint32_t SB = smem_u32(smem);

    const int tid  = threadIdx.x;
    const int lane = tid & 31;
    const int wid  = tid >> 5;
    const int wm   = wid & 3;          // warp M index (0..3)
    const int wn   = wid >> 2;         // warp N index (0..1)
    const int bi   = blockIdx.y * 128;
    const int bj   = blockIdx.x * 128;

    // ldmatrix lane address components (both operands stored [row][k])
    const int arow = lane & 15;
    const int asel = lane >> 4;
    const int brow = (lane & 7) + ((lane >> 4) << 3);
    const int bsel = (lane >> 3) & 1;

    float acc[2][8][4];
#pragma unroll
    for (int mi = 0; mi < 2; ++mi)
#pragma unroll
        for (int ni = 0; ni < 8; ++ni)
#pragma unroll
            for (int q = 0; q < 4; ++q) acc[mi][ni][q] = 0.0f;

    // preload stages 0,1
    load_stage(SB,           bi, bj, 0,  tid); cp_commit();
    load_stage(SB + STAGE_B, bi, bj, BK, tid); cp_commit();

    for (int c = 0; c < KCHUNKS; ++c) {
        const uint32_t S = SB + (c & 1) * STAGE_B;
        cp_wait1();
        __syncthreads();

        const uint32_t Sah = S;
        const uint32_t Sal = S + TILE_B;
        const uint32_t Sbh = S + 2 * TILE_B;

#pragma unroll
        for (int kk = 0; kk < BK; kk += 16) {
            // ---- A fragments for this k-slice ----
            uint32_t ah[2][4], al[2][4];
#pragma unroll
            for (int mi = 0; mi < 2; ++mi) {
                uint32_t off = (uint32_t)((wm * 32 + mi * 16 + arow) * (PITCH * 2) + (kk + asel * 8) * 2);
                ldsm4(Sah + off, ah[mi]);
                ldsm4(Sal + off, al[mi]);
            }
            // ---- np pairs; 2 sweeps of 8 independent-acc MMAs each ----
#pragma unroll
            for (int h = 0; h < 2; ++h) {
                uint32_t bh[2][4];
#pragma unroll
                for (int q = 0; q < 2; ++q) {
                    int np = h * 2 + q;
                    uint32_t off = (uint32_t)((wn * 64 + np * 16 + brow) * (PITCH * 2) + (kk + bsel * 8) * 2);
                    ldsm4(Sbh + off, bh[q]);
                }
                // sweep 1: Fh * Gh
#pragma unroll
                for (int q = 0; q < 2; ++q) {
                    int np = h * 2 + q;
#pragma unroll
                    for (int mi = 0; mi < 2; ++mi) {
                        mma16816(acc[mi][2 * np],     ah[mi], bh[q][0], bh[q][1]);
                        mma16816(acc[mi][2 * np + 1], ah[mi], bh[q][2], bh[q][3]);
                    }
                }
                // sweep 2: Fl * Gh
#pragma unroll
                for (int q = 0; q < 2; ++q) {
                    int np = h * 2 + q;
#pragma unroll
                    for (int mi = 0; mi < 2; ++mi) {
                        mma16816(acc[mi][2 * np],     al[mi], bh[q][0], bh[q][1]);
                        mma16816(acc[mi][2 * np + 1], al[mi], bh[q][2], bh[q][3]);
                    }
                }
            }
        }

        __syncthreads();
        if (c + 2 < KCHUNKS) load_stage(S, bi, bj, (c + 2) * BK, tid);
        cp_commit();   // always commit (possibly empty) to keep wait_group bookkeeping
    }

    // epilogue
    const int gid = lane >> 2;
    const int tig = lane & 3;
#pragma unroll
    for (int mi = 0; mi < 2; ++mi) {
#pragma unroll
        for (int ni = 0; ni < 8; ++ni) {
            int a0 = bi + wm * 32 + mi * 16 + gid;
            int b0 = bj + wn * 64 + ni * 8 + tig * 2;
            *(float2*)(C + (size_t)a0 * N + b0)       = make_float2(acc[mi][ni][0], acc[mi][ni][1]);
            *(float2*)(C + (size_t)(a0 + 8) * N + b0) = make_float2(acc[mi][ni][2], acc[mi][ni][3]);
        }
    }
}

// ---------------- launch --------------------------------------------------------
extern "C" void kernel_launch(void* const* d_in, const int* in_sizes, int n_in,
                              void* d_out, int out_size) {
    const float* A = (const float*)d_in[0];
    float* out = (float*)d_out;

    static const int GEMM_SMEM = 2 * STAGE_B;   // 61440 bytes
    cudaFuncSetAttribute(gemm_kernel, cudaFuncAttributeMaxDynamicSharedMemorySize, GEMM_SMEM);

    rowmax_kernel<<<N, 256>>>(A);
    exp_kernel<<<dim3(N / 32, N / 32), dim3(32, 32)>>>(A);
    init_kernel<<<(N + 255) / 256, 256>>>();
    sinkhorn_kernel<<<SGRID, SBLOCK>>>();
    fg_kernel<<<N, 256>>>();
    gemm_kernel<<<dim3(N / 128, N / 128), GT, GEMM_SMEM>>>(out);
}

// round 8
// speedup vs baseline: 70.1411x; 1.3826x over previous
#include <cuda_runtime.h>
#include <cuda_fp16.h>
#include <math.h>
#include <stdint.h>

#define N       2048
#define ITERS   1000
#define TEMP    100.0f
#define EPS_CONV 1e-5f

#define SGRID   128
#define SBLOCK  1024
#define WPC     (SBLOCK/32)
#define RPC     (WPC/2)

// ---------------- scratch (static device globals; allocation-free) -------------
__device__ float g_E [N * N];
__device__ float g_ET[N * N];
__device__ __half g_Fh[N * N];
__device__ __half g_Gh[N * N];
__device__ float g_u[N];
__device__ float g_v[N];
__device__ float g_rowmax[N];

__device__ unsigned g_count = 0;
__device__ unsigned g_gen   = 0;
__device__ unsigned g_delta[2] = {0, 0};

// ---------------- acquire/release grid barrier ---------------------------------
__device__ __forceinline__ void grid_sync() {
    __syncthreads();
    if (threadIdx.x == 0) {
        unsigned my;
        asm volatile("ld.acquire.gpu.global.u32 %0, [%1];" : "=r"(my) : "l"(&g_gen));
        unsigned old;
        asm volatile("atom.release.gpu.global.add.u32 %0, [%1], %2;"
                     : "=r"(old) : "l"(&g_count), "r"(1u));
        if (old == SGRID - 1) {
            asm volatile("st.relaxed.gpu.global.u32 [%0], %1;" :: "l"(&g_count), "r"(0u));
            asm volatile("st.release.gpu.global.u32 [%0], %1;" :: "l"(&g_gen), "r"(my + 1u));
        } else {
            unsigned cur;
            do {
                asm volatile("ld.acquire.gpu.global.u32 %0, [%1];" : "=r"(cur) : "l"(&g_gen));
            } while (cur == my);
        }
    }
    __syncthreads();
}

// ---------------- prep kernels ---------------------------------------------------
__global__ void rowmax_kernel(const float* __restrict__ A) {
    int row = blockIdx.x;
    const float* a = A + (size_t)row * N;
    float m = -3.0e38f;
    for (int j = threadIdx.x; j < N; j += blockDim.x) m = fmaxf(m, a[j]);
    __shared__ float s[256];
    s[threadIdx.x] = m;
    __syncthreads();
    for (int o = 128; o > 0; o >>= 1) {
        if (threadIdx.x < o) s[threadIdx.x] = fmaxf(s[threadIdx.x], s[threadIdx.x + o]);
        __syncthreads();
    }
    if (threadIdx.x == 0) g_rowmax[row] = s[0];
}

__global__ void exp_kernel(const float* __restrict__ A) {
    __shared__ float tile[32][33];
    int x = blockIdx.x * 32 + threadIdx.x;
    int y = blockIdx.y * 32 + threadIdx.y;
    float rm = g_rowmax[y];
    float e = expf(TEMP * (A[(size_t)y * N + x] - rm));
    g_E[(size_t)y * N + x] = e;
    tile[threadIdx.y][threadIdx.x] = e;
    __syncthreads();
    int tx = blockIdx.y * 32 + threadIdx.x;
    int ty = blockIdx.x * 32 + threadIdx.y;
    g_ET[(size_t)ty * N + tx] = tile[threadIdx.x][threadIdx.y];
}

__global__ void init_kernel() {
    int i = blockIdx.x * blockDim.x + threadIdx.x;
    if (i < N) { g_v[i] = 1.0f; g_u[i] = 1.0f; }
    if (i < 2) g_delta[i] = 0u;
}

// ---------------- persistent Sinkhorn (early-exit) ------------------------------
__global__ void __launch_bounds__(SBLOCK, 1) sinkhorn_kernel() {
    const int tid  = threadIdx.x;
    const int wid  = tid >> 5;
    const int lane = tid & 31;
    const int rloc = wid >> 1;
    const int half = wid & 1;
    const int row  = blockIdx.x * RPC + rloc;

    __shared__ float svec[N];
    __shared__ float spart[WPC];
    __shared__ float sdel[RPC];
    __shared__ float sflag;
    float4* svec4 = (float4*)svec;

    const float4* erow  = (const float4*)g_E  + (size_t)row * (N / 4) + half * (N / 8);
    const float4* etrow = (const float4*)g_ET + (size_t)row * (N / 4) + half * (N / 8);
    const float4* sv = svec4 + half * (N / 8);

    float u_old = 1.0f;

    for (int t = 0; t < ITERS; ++t) {
        {
            const float4* v4 = (const float4*)g_v;
            if (tid < N / 4) svec4[tid] = v4[tid];
            __syncthreads();

            float s = 0.0f;
#pragma unroll 4
            for (int jb = 0; jb < N / 8; jb += 32) {
                float4 e  = erow[jb + lane];
                float4 vv = sv[jb + lane];
                s += e.x * vv.x + e.y * vv.y + e.z * vv.z + e.w * vv.w;
            }
#pragma unroll
            for (int o = 16; o > 0; o >>= 1) s += __shfl_xor_sync(0xffffffffu, s, o);
            if (lane == 0) spart[wid] = s;
            __syncthreads();

            if (half == 0 && lane == 0) {
                float tot = spart[wid] + spart[wid + 1];
                float un = 1.0f / tot;
                g_u[row] = un;
                sdel[rloc] = fabsf(un - u_old) / u_old;
                u_old = un;
            }
            __syncthreads();
            if (tid == 0) {
                float dm = 0.0f;
#pragma unroll
                for (int i = 0; i < RPC; ++i) dm = fmaxf(dm, sdel[i]);
                atomicMax(&g_delta[t & 1], __float_as_uint(dm));
            }
        }
        grid_sync();

        if (tid == 0) {
            unsigned db;
            asm volatile("ld.acquire.gpu.global.u32 %0, [%1];" : "=r"(db) : "l"(&g_delta[t & 1]));
            sflag = (t > 0 && __uint_as_float(db) < EPS_CONV) ? 1.0f : 0.0f;
            g_delta[(t + 1) & 1] = 0u;
        }

        bool conv;
        {
            const float4* u4 = (const float4*)g_u;
            if (tid < N / 4) svec4[tid] = u4[tid];
            __syncthreads();
            conv = (sflag > 0.5f);

            float s = 0.0f;
#pragma unroll 4
            for (int jb = 0; jb < N / 8; jb += 32) {
                float4 e  = etrow[jb + lane];
                float4 uu = sv[jb + lane];
                s += e.x * uu.x + e.y * uu.y + e.z * uu.z + e.w * uu.w;
            }
#pragma unroll
            for (int o = 16; o > 0; o >>= 1) s += __shfl_xor_sync(0xffffffffu, s, o);
            if (lane == 0) spart[wid] = s;
            __syncthreads();
            if (half == 0 && lane == 0) {
                float tot = spart[wid] + spart[wid + 1];
                g_v[row] = 1.0f / tot;
            }
        }
        grid_sync();

        if (conv) break;
    }
}

// ---------------- F (fp16) and G (fp16) ------------------------------------------
__device__ __forceinline__ uint32_t pack_h2(__half a, __half b) {
    __half2 t = __halves2half2(a, b);
    return *(uint32_t*)&t;
}

__global__ void fg_kernel() {
    int row = blockIdx.x;
    int t   = threadIdx.x;
    float uu = g_u[row];

    const float4* erow = (const float4*)g_E + (size_t)row * (N / 4);
    const float4* v4   = (const float4*)g_v;

    float4 e0 = erow[t * 2], e1 = erow[t * 2 + 1];
    float4 w0 = v4[t * 2],   w1 = v4[t * 2 + 1];

    float m[8];
    m[0] = uu * e0.x * w0.x;  m[1] = uu * e0.y * w0.y;
    m[2] = uu * e0.z * w0.z;  m[3] = uu * e0.w * w0.w;
    m[4] = uu * e1.x * w1.x;  m[5] = uu * e1.y * w1.y;
    m[6] = uu * e1.z * w1.z;  m[7] = uu * e1.w * w1.w;

    float tsum = 0.0f;
#pragma unroll
    for (int e = 0; e < 8; ++e) tsum += m[e];

    __shared__ float ss[256];
    ss[t] = tsum;
    __syncthreads();
    float run = tsum;
#pragma unroll
    for (int o = 1; o < 256; o <<= 1) {
        float y = (t >= o) ? ss[t - o] : 0.0f;
        __syncthreads();
        run += y;
        ss[t] = run;
        __syncthreads();
    }
    float total = ss[255];
    float pf = run - tsum;

    float g[8];
#pragma unroll
    for (int e = 0; e < 8; ++e) { g[e] = total - pf; pf += m[e]; }

    __half fh[8], gh[8];
#pragma unroll
    for (int e = 0; e < 8; ++e) {
        fh[e] = __float2half_rn(m[e]);
        gh[e] = __float2half_rn(g[e]);
    }

    size_t base = ((size_t)row * N) / 8 + t;   // uint4 index (8 halves per uint4)
    ((uint4*)g_Fh)[base] = make_uint4(pack_h2(fh[0],fh[1]), pack_h2(fh[2],fh[3]),
                                      pack_h2(fh[4],fh[5]), pack_h2(fh[6],fh[7]));
    ((uint4*)g_Gh)[base] = make_uint4(pack_h2(gh[0],gh[1]), pack_h2(gh[2],gh[3]),
                                      pack_h2(gh[4],gh[5]), pack_h2(gh[6],gh[7]));
}

// ================= mma.sync fp16 single-term GEMM =================================
// C[a,b] = dot(F[a,:], G[b,:]) ≈ Fh·Gh  (both operands fp16, fp32 accum)
// BM=128, BN=128, BK=32. 8 warps (4M x 2N), warp tile 32x64, indep-acc sweeps.

#define BK       32
#define KCHUNKS  (N / BK)              // 64
#define PITCH    40                    // halves per smem row (32 + 8 pad) -> 80B
#define TILE_B   (128 * PITCH * 2)     // 10240 bytes per tile
#define STAGE_B  (2 * TILE_B)          // Ah, Bh
#define GT       256

__device__ __forceinline__ uint32_t smem_u32(const void* p) {
    uint32_t a;
    asm("{ .reg .u64 t; cvta.to.shared.u64 t, %1; cvt.u32.u64 %0, t; }" : "=r"(a) : "l"(p));
    return a;
}
__device__ __forceinline__ void cp16(uint32_t dst, const void* src) {
    asm volatile("cp.async.cg.shared.global [%0], [%1], 16;" :: "r"(dst), "l"(src));
}
__device__ __forceinline__ void cp_commit() { asm volatile("cp.async.commit_group;" ::: "memory"); }
__device__ __forceinline__ void cp_wait1()  { asm volatile("cp.async.wait_group 1;" ::: "memory"); }

__device__ __forceinline__ void ldsm4(uint32_t addr, uint32_t* r) {
    asm volatile("ldmatrix.sync.aligned.m8n8.x4.shared.b16 {%0,%1,%2,%3}, [%4];"
                 : "=r"(r[0]), "=r"(r[1]), "=r"(r[2]), "=r"(r[3]) : "r"(addr));
}
__device__ __forceinline__ void mma16816(float* c, const uint32_t* a, uint32_t b0, uint32_t b1) {
    asm volatile("mma.sync.aligned.m16n8k16.row.col.f32.f16.f16.f32 "
                 "{%0,%1,%2,%3}, {%4,%5,%6,%7}, {%8,%9}, {%0,%1,%2,%3};"
                 : "+f"(c[0]), "+f"(c[1]), "+f"(c[2]), "+f"(c[3])
                 : "r"(a[0]), "r"(a[1]), "r"(a[2]), "r"(a[3]), "r"(b0), "r"(b1));
}

// load one stage: Ah rows [bi,bi+128), Bh rows [bj,bj+128), k window [k0,k0+32)
__device__ __forceinline__ void load_stage(uint32_t S, int bi, int bj, int k0, int tid) {
    const __half* gs0 = g_Fh + (size_t)bi * N + k0;
    const __half* gs1 = g_Gh + (size_t)bj * N + k0;
#pragma unroll
    for (int i = 0; i < 4; ++i) {
        int p = tid + i * GT;              // 0..1023
        int tile = p >> 9;                 // 0..1
        int r = (p >> 2) & 127;
        int s = p & 3;
        const __half* src = (tile == 0 ? gs0 : gs1) + (size_t)r * N + s * 8;
        uint32_t dst = S + tile * TILE_B + r * (PITCH * 2) + s * 16;
        cp16(dst, src);
    }
}

__global__ void __launch_bounds__(GT, 2) gemm_kernel(float* __restrict__ C) {
    extern __shared__ char smem[];
    const uint32_t SB = smem_u32(smem);

    const int tid  = threadIdx.x;
    const int lane = tid & 31;
    const int wid  = tid >> 5;
    const int wm   = wid & 3;          // warp M index (0..3)
    const int wn   = wid >> 2;         // warp N index (0..1)
    const int bi   = blockIdx.y * 128;
    const int bj   = blockIdx.x * 128;

    // ldmatrix lane address components (both operands stored [row][k])
    const int arow = lane & 15;
    const int asel = lane >> 4;
    const int brow = (lane & 7) + ((lane >> 4) << 3);
    const int bsel = (lane >> 3) & 1;

    float acc[2][8][4];
#pragma unroll
    for (int mi = 0; mi < 2; ++mi)
#pragma unroll
        for (int ni = 0; ni < 8; ++ni)
#pragma unroll
            for (int q = 0; q < 4; ++q) acc[mi][ni][q] = 0.0f;

    // preload stages 0,1
    load_stage(SB,           bi, bj, 0,  tid); cp_commit();
    load_stage(SB + STAGE_B, bi, bj, BK, tid); cp_commit();

    for (int c = 0; c < KCHUNKS; ++c) {
        const uint32_t S = SB + (c & 1) * STAGE_B;
        cp_wait1();
        __syncthreads();

        const uint32_t Sah = S;
        const uint32_t Sbh = S + TILE_B;

#pragma unroll
        for (int kk = 0; kk < BK; kk += 16) {
            // ---- A fragments for this k-slice ----
            uint32_t ah[2][4];
#pragma unroll
            for (int mi = 0; mi < 2; ++mi) {
                uint32_t off = (uint32_t)((wm * 32 + mi * 16 + arow) * (PITCH * 2) + (kk + asel * 8) * 2);
                ldsm4(Sah + off, ah[mi]);
            }
            // ---- np pairs; 1 sweep of 8 independent-acc MMAs each ----
#pragma unroll
            for (int h = 0; h < 2; ++h) {
                uint32_t bh[2][4];
#pragma unroll
                for (int q = 0; q < 2; ++q) {
                    int np = h * 2 + q;
                    uint32_t off = (uint32_t)((wn * 64 + np * 16 + brow) * (PITCH * 2) + (kk + bsel * 8) * 2);
                    ldsm4(Sbh + off, bh[q]);
                }
#pragma unroll
                for (int q = 0; q < 2; ++q) {
                    int np = h * 2 + q;
#pragma unroll
                    for (int mi = 0; mi < 2; ++mi) {
                        mma16816(acc[mi][2 * np],     ah[mi], bh[q][0], bh[q][1]);
                        mma16816(acc[mi][2 * np + 1], ah[mi], bh[q][2], bh[q][3]);
                    }
                }
            }
        }

        __syncthreads();
        if (c + 2 < KCHUNKS) load_stage(S, bi, bj, (c + 2) * BK, tid);
        cp_commit();   // always commit (possibly empty) to keep wait_group bookkeeping
    }

    // epilogue
    const int gid = lane >> 2;
    const int tig = lane & 3;
#pragma unroll
    for (int mi = 0; mi < 2; ++mi) {
#pragma unroll
        for (int ni = 0; ni < 8; ++ni) {
            int a0 = bi + wm * 32 + mi * 16 + gid;
            int b0 = bj + wn * 64 + ni * 8 + tig * 2;
            *(float2*)(C + (size_t)a0 * N + b0)       = make_float2(acc[mi][ni][0], acc[mi][ni][1]);
            *(float2*)(C + (size_t)(a0 + 8) * N + b0) = make_float2(acc[mi][ni][2], acc[mi][ni][3]);
        }
    }
}

// ---------------- launch --------------------------------------------------------
extern "C" void kernel_launch(void* const* d_in, const int* in_sizes, int n_in,
                              void* d_out, int out_size) {
    const float* A = (const float*)d_in[0];
    float* out = (float*)d_out;

    static const int GEMM_SMEM = 2 * STAGE_B;   // 40960 bytes
    cudaFuncSetAttribute(gemm_kernel, cudaFuncAttributeMaxDynamicSharedMemorySize, GEMM_SMEM);

    rowmax_kernel<<<N, 256>>>(A);
    exp_kernel<<<dim3(N / 32, N / 32), dim3(32, 32)>>>(A);
    init_kernel<<<(N + 255) / 256, 256>>>();
    sinkhorn_kernel<<<SGRID, SBLOCK>>>();
    fg_kernel<<<N, 256>>>();
    gemm_kernel<<<dim3(N / 128, N / 128), GT, GEMM_SMEM>>>(out);
}

// round 9
// speedup vs baseline: 70.9434x; 1.0114x over previous
#include <cuda_runtime.h>
#include <cuda_fp16.h>
#include <math.h>
#include <stdint.h>

#define N       2048
#define ITERS   1000
#define TEMP    100.0f
#define EPS_CONV 1e-5f

#define SGRID   128
#define SBLOCK  1024
#define WPC     (SBLOCK/32)
#define RPC     (WPC/2)

// ---------------- scratch (static device globals; allocation-free) -------------
__device__ float g_E [N * N];
__device__ float g_ET[N * N];
__device__ __half g_Fh[N * N];
__device__ __half g_Gh[N * N];
__device__ float g_u[N];
__device__ float g_v[N];
__device__ float g_rowmax[N];

__device__ unsigned g_count = 0;
__device__ unsigned g_gen   = 0;
__device__ unsigned g_delta[2] = {0, 0};

// ---------------- acquire/release grid barrier ---------------------------------
__device__ __forceinline__ void grid_sync() {
    __syncthreads();
    if (threadIdx.x == 0) {
        unsigned my;
        asm volatile("ld.acquire.gpu.global.u32 %0, [%1];" : "=r"(my) : "l"(&g_gen));
        unsigned old;
        asm volatile("atom.release.gpu.global.add.u32 %0, [%1], %2;"
                     : "=r"(old) : "l"(&g_count), "r"(1u));
        if (old == SGRID - 1) {
            asm volatile("st.relaxed.gpu.global.u32 [%0], %1;" :: "l"(&g_count), "r"(0u));
            asm volatile("st.release.gpu.global.u32 [%0], %1;" :: "l"(&g_gen), "r"(my + 1u));
        } else {
            unsigned cur;
            do {
                asm volatile("ld.acquire.gpu.global.u32 %0, [%1];" : "=r"(cur) : "l"(&g_gen));
            } while (cur == my);
        }
    }
    __syncthreads();
}

// ---------------- prep kernels ---------------------------------------------------
__global__ void rowmax_kernel(const float* __restrict__ A) {
    int row = blockIdx.x;
    const float* a = A + (size_t)row * N;
    float m = -3.0e38f;
    for (int j = threadIdx.x; j < N; j += blockDim.x) m = fmaxf(m, a[j]);
    __shared__ float s[256];
    s[threadIdx.x] = m;
    __syncthreads();
    for (int o = 128; o > 0; o >>= 1) {
        if (threadIdx.x < o) s[threadIdx.x] = fmaxf(s[threadIdx.x], s[threadIdx.x + o]);
        __syncthreads();
    }
    if (threadIdx.x == 0) {
        g_rowmax[row] = s[0];
        g_u[row] = 1.0f; g_v[row] = 1.0f;
        if (row < 2) g_delta[row] = 0u;
    }
}

__global__ void exp_kernel(const float* __restrict__ A) {
    __shared__ float tile[32][33];
    int x = blockIdx.x * 32 + threadIdx.x;
    int y = blockIdx.y * 32 + threadIdx.y;
    float rm = g_rowmax[y];
    float e = expf(TEMP * (A[(size_t)y * N + x] - rm));
    g_E[(size_t)y * N + x] = e;
    tile[threadIdx.y][threadIdx.x] = e;
    __syncthreads();
    int tx = blockIdx.y * 32 + threadIdx.x;
    int ty = blockIdx.x * 32 + threadIdx.y;
    g_ET[(size_t)ty * N + tx] = tile[threadIdx.x][threadIdx.y];
}

// ---------------- persistent Sinkhorn (early-exit) ------------------------------
__global__ void __launch_bounds__(SBLOCK, 1) sinkhorn_kernel() {
    const int tid  = threadIdx.x;
    const int wid  = tid >> 5;
    const int lane = tid & 31;
    const int rloc = wid >> 1;
    const int half = wid & 1;
    const int row  = blockIdx.x * RPC + rloc;

    __shared__ float svec[N];
    __shared__ float spart[WPC];
    __shared__ float sdel[RPC];
    __shared__ float sflag;
    float4* svec4 = (float4*)svec;

    const float4* erow  = (const float4*)g_E  + (size_t)row * (N / 4) + half * (N / 8);
    const float4* etrow = (const float4*)g_ET + (size_t)row * (N / 4) + half * (N / 8);
    const float4* sv = svec4 + half * (N / 8);

    float u_old = 1.0f;

    for (int t = 0; t < ITERS; ++t) {
        {
            const float4* v4 = (const float4*)g_v;
            if (tid < N / 4) svec4[tid] = v4[tid];
            __syncthreads();

            float s = 0.0f;
#pragma unroll
            for (int jb = 0; jb < N / 8; jb += 32) {
                float4 e  = erow[jb + lane];
                float4 vv = sv[jb + lane];
                s += e.x * vv.x + e.y * vv.y + e.z * vv.z + e.w * vv.w;
            }
#pragma unroll
            for (int o = 16; o > 0; o >>= 1) s += __shfl_xor_sync(0xffffffffu, s, o);
            if (lane == 0) spart[wid] = s;
            __syncthreads();

            if (half == 0 && lane == 0) {
                float tot = spart[wid] + spart[wid + 1];
                float un = 1.0f / tot;
                g_u[row] = un;
                sdel[rloc] = fabsf(un - u_old) / u_old;
                u_old = un;
            }
            __syncthreads();
            if (tid == 0) {
                float dm = 0.0f;
#pragma unroll
                for (int i = 0; i < RPC; ++i) dm = fmaxf(dm, sdel[i]);
                atomicMax(&g_delta[t & 1], __float_as_uint(dm));
            }
        }
        grid_sync();

        if (tid == 0) {
            unsigned db;
            asm volatile("ld.acquire.gpu.global.u32 %0, [%1];" : "=r"(db) : "l"(&g_delta[t & 1]));
            sflag = (t > 0 && __uint_as_float(db) < EPS_CONV) ? 1.0f : 0.0f;
            g_delta[(t + 1) & 1] = 0u;
        }

        bool conv;
        {
            const float4* u4 = (const float4*)g_u;
            if (tid < N / 4) svec4[tid] = u4[tid];
            __syncthreads();
            conv = (sflag > 0.5f);

            float s = 0.0f;
#pragma unroll
            for (int jb = 0; jb < N / 8; jb += 32) {
                float4 e  = etrow[jb + lane];
                float4 uu = sv[jb + lane];
                s += e.x * uu.x + e.y * uu.y + e.z * uu.z + e.w * uu.w;
            }
#pragma unroll
            for (int o = 16; o > 0; o >>= 1) s += __shfl_xor_sync(0xffffffffu, s, o);
            if (lane == 0) spart[wid] = s;
            __syncthreads();
            if (half == 0 && lane == 0) {
                float tot = spart[wid] + spart[wid + 1];
                g_v[row] = 1.0f / tot;
            }
        }
        grid_sync();

        if (conv) break;
    }
}

// ---------------- F (fp16) and G (fp16) ------------------------------------------
__device__ __forceinline__ uint32_t pack_h2(__half a, __half b) {
    __half2 t = __halves2half2(a, b);
    return *(uint32_t*)&t;
}

__global__ void fg_kernel() {
    int row = blockIdx.x;
    int t   = threadIdx.x;
    float uu = g_u[row];

    const float4* erow = (const float4*)g_E + (size_t)row * (N / 4);
    const float4* v4   = (const float4*)g_v;

    float4 e0 = erow[t * 2], e1 = erow[t * 2 + 1];
    float4 w0 = v4[t * 2],   w1 = v4[t * 2 + 1];

    float m[8];
    m[0] = uu * e0.x * w0.x;  m[1] = uu * e0.y * w0.y;
    m[2] = uu * e0.z * w0.z;  m[3] = uu * e0.w * w0.w;
    m[4] = uu * e1.x * w1.x;  m[5] = uu * e1.y * w1.y;
    m[6] = uu * e1.z * w1.z;  m[7] = uu * e1.w * w1.w;

    float tsum = 0.0f;
#pragma unroll
    for (int e = 0; e < 8; ++e) tsum += m[e];

    __shared__ float ss[256];
    ss[t] = tsum;
    __syncthreads();
    float run = tsum;
#pragma unroll
    for (int o = 1; o < 256; o <<= 1) {
        float y = (t >= o) ? ss[t - o] : 0.0f;
        __syncthreads();
        run += y;
        ss[t] = run;
        __syncthreads();
    }
    float total = ss[255];
    float pf = run - tsum;

    float g[8];
#pragma unroll
    for (int e = 0; e < 8; ++e) { g[e] = total - pf; pf += m[e]; }

    __half fh[8], gh[8];
#pragma unroll
    for (int e = 0; e < 8; ++e) {
        fh[e] = __float2half_rn(m[e]);
        gh[e] = __float2half_rn(g[e]);
    }

    size_t base = ((size_t)row * N) / 8 + t;
    ((uint4*)g_Fh)[base] = make_uint4(pack_h2(fh[0],fh[1]), pack_h2(fh[2],fh[3]),
                                      pack_h2(fh[4],fh[5]), pack_h2(fh[6],fh[7]));
    ((uint4*)g_Gh)[base] = make_uint4(pack_h2(gh[0],gh[1]), pack_h2(gh[2],gh[3]),
                                      pack_h2(gh[4],gh[5]), pack_h2(gh[6],gh[7]));
}

// ================= mma.sync fp16 single-term GEMM, 4-stage pipeline ==============
// C[a,b] = dot(F[a,:], G[b,:]) ≈ Fh·Gh  (fp32 accum)
// BM=128, BN=128, BK=32. 8 warps (4M x 2N), warp tile 32x64.
// 4 smem stages, 3 cp.async groups in flight, ONE __syncthreads per chunk.

#define BK       32
#define KCHUNKS  (N / BK)              // 64
#define PITCH    40                    // halves per smem row (32 + 8 pad) -> 80B
#define TILE_B   (128 * PITCH * 2)     // 10240 bytes per tile
#define STAGE_B  (2 * TILE_B)          // Ah, Bh = 20480 bytes
#define NSTAGE   4
#define GT       256

__device__ __forceinline__ uint32_t smem_u32(const void* p) {
    uint32_t a;
    asm("{ .reg .u64 t; cvta.to.shared.u64 t, %1; cvt.u32.u64 %0, t; }" : "=r"(a) : "l"(p));
    return a;
}
__device__ __forceinline__ void cp16(uint32_t dst, const void* src) {
    asm volatile("cp.async.cg.shared.global [%0], [%1], 16;" :: "r"(dst), "l"(src));
}
__device__ __forceinline__ void cp_commit() { asm volatile("cp.async.commit_group;" ::: "memory"); }
__device__ __forceinline__ void cp_wait2()  { asm volatile("cp.async.wait_group 2;" ::: "memory"); }

__device__ __forceinline__ void ldsm4(uint32_t addr, uint32_t* r) {
    asm volatile("ldmatrix.sync.aligned.m8n8.x4.shared.b16 {%0,%1,%2,%3}, [%4];"
                 : "=r"(r[0]), "=r"(r[1]), "=r"(r[2]), "=r"(r[3]) : "r"(addr));
}
__device__ __forceinline__ void mma16816(float* c, const uint32_t* a, uint32_t b0, uint32_t b1) {
    asm volatile("mma.sync.aligned.m16n8k16.row.col.f32.f16.f16.f32 "
                 "{%0,%1,%2,%3}, {%4,%5,%6,%7}, {%8,%9}, {%0,%1,%2,%3};"
                 : "+f"(c[0]), "+f"(c[1]), "+f"(c[2]), "+f"(c[3])
                 : "r"(a[0]), "r"(a[1]), "r"(a[2]), "r"(a[3]), "r"(b0), "r"(b1));
}

// load one stage: Ah rows [bi,bi+128), Bh rows [bj,bj+128), k window [k0,k0+32)
__device__ __forceinline__ void load_stage(uint32_t S, int bi, int bj, int k0, int tid) {
    const __half* gs0 = g_Fh + (size_t)bi * N + k0;
    const __half* gs1 = g_Gh + (size_t)bj * N + k0;
#pragma unroll
    for (int i = 0; i < 4; ++i) {
        int p = tid + i * GT;              // 0..1023
        int tile = p >> 9;                 // 0..1
        int r = (p >> 2) & 127;
        int s = p & 3;
        const __half* src = (tile == 0 ? gs0 : gs1) + (size_t)r * N + s * 8;
        uint32_t dst = S + tile * TILE_B + r * (PITCH * 2) + s * 16;
        cp16(dst, src);
    }
}

__global__ void __launch_bounds__(GT, 2) gemm_kernel(float* __restrict__ C) {
    extern __shared__ char smem[];
    const uint32_t SB = smem_u32(smem);

    const int tid  = threadIdx.x;
    const int lane = tid & 31;
    const int wid  = tid >> 5;
    const int wm   = wid & 3;          // warp M index (0..3)
    const int wn   = wid >> 2;         // warp N index (0..1)
    const int bi   = blockIdx.y * 128;
    const int bj   = blockIdx.x * 128;

    const int arow = lane & 15;
    const int asel = lane >> 4;
    const int brow = (lane & 7) + ((lane >> 4) << 3);
    const int bsel = (lane >> 3) & 1;

    float acc[2][8][4];
#pragma unroll
    for (int mi = 0; mi < 2; ++mi)
#pragma unroll
        for (int ni = 0; ni < 8; ++ni)
#pragma unroll
            for (int q = 0; q < 4; ++q) acc[mi][ni][q] = 0.0f;

    // prologue: stages 0..2
#pragma unroll
    for (int s = 0; s < NSTAGE - 1; ++s) {
        load_stage(SB + s * STAGE_B, bi, bj, s * BK, tid);
        cp_commit();
    }

    for (int c = 0; c < KCHUNKS; ++c) {
        cp_wait2();          // stage c complete (<=2 groups pending)
        __syncthreads();     // all warps done with buffer (c-1)%4 from prev chunk

        // issue next loads FIRST (into buffer (c+3)%4 == (c-1)%4) to overlap with compute
        if (c + NSTAGE - 1 < KCHUNKS)
            load_stage(SB + ((c + NSTAGE - 1) % NSTAGE) * STAGE_B, bi, bj, (c + NSTAGE - 1) * BK, tid);
        cp_commit();         // exactly one group per chunk

        const uint32_t S = SB + (c % NSTAGE) * STAGE_B;
        const uint32_t Sah = S;
        const uint32_t Sbh = S + TILE_B;

#pragma unroll
        for (int kk = 0; kk < BK; kk += 16) {
            uint32_t ah[2][4];
#pragma unroll
            for (int mi = 0; mi < 2; ++mi) {
                uint32_t off = (uint32_t)((wm * 32 + mi * 16 + arow) * (PITCH * 2) + (kk + asel * 8) * 2);
                ldsm4(Sah + off, ah[mi]);
            }
#pragma unroll
            for (int h = 0; h < 2; ++h) {
                uint32_t bh[2][4];
#pragma unroll
                for (int q = 0; q < 2; ++q) {
                    int np = h * 2 + q;
                    uint32_t off = (uint32_t)((wn * 64 + np * 16 + brow) * (PITCH * 2) + (kk + bsel * 8) * 2);
                    ldsm4(Sbh + off, bh[q]);
                }
#pragma unroll
                for (int q = 0; q < 2; ++q) {
                    int np = h * 2 + q;
#pragma unroll
                    for (int mi = 0; mi < 2; ++mi) {
                        mma16816(acc[mi][2 * np],     ah[mi], bh[q][0], bh[q][1]);
                        mma16816(acc[mi][2 * np + 1], ah[mi], bh[q][2], bh[q][3]);
                    }
                }
            }
        }
    }

    // epilogue
    const int gid = lane >> 2;
    const int tig = lane & 3;
#pragma unroll
    for (int mi = 0; mi < 2; ++mi) {
#pragma unroll
        for (int ni = 0; ni < 8; ++ni) {
            int a0 = bi + wm * 32 + mi * 16 + gid;
            int b0 = bj + wn * 64 + ni * 8 + tig * 2;
            *(float2*)(C + (size_t)a0 * N + b0)       = make_float2(acc[mi][ni][0], acc[mi][ni][1]);
            *(float2*)(C + (size_t)(a0 + 8) * N + b0) = make_float2(acc[mi][ni][2], acc[mi][ni][3]);
        }
    }
}

// ---------------- launch --------------------------------------------------------
extern "C" void kernel_launch(void* const* d_in, const int* in_sizes, int n_in,
                              void* d_out, int out_size) {
    const float* A = (const float*)d_in[0];
    float* out = (float*)d_out;

    static const int GEMM_SMEM = NSTAGE * STAGE_B;   // 81920 bytes
    cudaFuncSetAttribute(gemm_kernel, cudaFuncAttributeMaxDynamicSharedMemorySize, GEMM_SMEM);

    rowmax_kernel<<<N, 256>>>(A);
    exp_kernel<<<dim3(N / 32, N / 32), dim3(32, 32)>>>(A);
    sinkhorn_kernel<<<SGRID, SBLOCK>>>();
    fg_kernel<<<N, 256>>>();
    gemm_kernel<<<dim3(N / 128, N / 128), GT, GEMM_SMEM>>>(out);
}

// round 10
// speedup vs baseline: 73.8181x; 1.0405x over previous
#include <cuda_runtime.h>
#include <cuda_fp16.h>
#include <math.h>
#include <stdint.h>

#define N       2048
#define ITERS   1000
#define TEMP    100.0f
#define EPS_CONV 1e-5f

#define SGRID   128
#define SBLOCK  1024
#define WPC     (SBLOCK/32)
#define RPC     (WPC/2)

// ---------------- scratch (static device globals; allocation-free) -------------
__device__ __half g_Eh [N * N];   // exp matrix, fp16
__device__ __half g_ETh[N * N];   // transpose, fp16
__device__ __half g_Fh[N * N];
__device__ __half g_Gh[N * N];
__device__ float g_u[N];
__device__ float g_v[N];
__device__ float g_rowmax[N];

__device__ unsigned g_count = 0;
__device__ unsigned g_gen   = 0;
__device__ unsigned g_delta[2] = {0, 0};

// ---------------- acquire/release grid barrier ---------------------------------
__device__ __forceinline__ void grid_sync() {
    __syncthreads();
    if (threadIdx.x == 0) {
        unsigned my;
        asm volatile("ld.acquire.gpu.global.u32 %0, [%1];" : "=r"(my) : "l"(&g_gen));
        unsigned old;
        asm volatile("atom.release.gpu.global.add.u32 %0, [%1], %2;"
                     : "=r"(old) : "l"(&g_count), "r"(1u));
        if (old == SGRID - 1) {
            asm volatile("st.relaxed.gpu.global.u32 [%0], %1;" :: "l"(&g_count), "r"(0u));
            asm volatile("st.release.gpu.global.u32 [%0], %1;" :: "l"(&g_gen), "r"(my + 1u));
        } else {
            unsigned cur;
            do {
                asm volatile("ld.acquire.gpu.global.u32 %0, [%1];" : "=r"(cur) : "l"(&g_gen));
            } while (cur == my);
        }
    }
    __syncthreads();
}

// ---------------- prep kernels ---------------------------------------------------
__global__ void rowmax_kernel(const float* __restrict__ A) {
    int row = blockIdx.x;
    const float* a = A + (size_t)row * N;
    float m = -3.0e38f;
    for (int j = threadIdx.x; j < N; j += blockDim.x) m = fmaxf(m, a[j]);
    __shared__ float s[256];
    s[threadIdx.x] = m;
    __syncthreads();
    for (int o = 128; o > 0; o >>= 1) {
        if (threadIdx.x < o) s[threadIdx.x] = fmaxf(s[threadIdx.x], s[threadIdx.x + o]);
        __syncthreads();
    }
    if (threadIdx.x == 0) {
        g_rowmax[row] = s[0];
        g_u[row] = 1.0f; g_v[row] = 1.0f;
        if (row < 2) g_delta[row] = 0u;
    }
}

__global__ void exp_kernel(const float* __restrict__ A) {
    __shared__ __half tile[32][33];
    int x = blockIdx.x * 32 + threadIdx.x;
    int y = blockIdx.y * 32 + threadIdx.y;
    float rm = g_rowmax[y];
    __half e = __float2half_rn(expf(TEMP * (A[(size_t)y * N + x] - rm)));
    g_Eh[(size_t)y * N + x] = e;
    tile[threadIdx.y][threadIdx.x] = e;
    __syncthreads();
    int tx = blockIdx.y * 32 + threadIdx.x;
    int ty = blockIdx.x * 32 + threadIdx.y;
    g_ETh[(size_t)ty * N + tx] = tile[threadIdx.x][threadIdx.y];
}

// ---------------- persistent Sinkhorn (early-exit, fp16 E) ----------------------
__device__ __forceinline__ float dot8(uint4 e, const float4* sv2i) {
    __half2 h0 = *(__half2*)&e.x, h1 = *(__half2*)&e.y,
            h2 = *(__half2*)&e.z, h3 = *(__half2*)&e.w;
    float2 f0 = __half22float2(h0), f1 = __half22float2(h1),
           f2 = __half22float2(h2), f3 = __half22float2(h3);
    float4 v0 = sv2i[0], v1 = sv2i[1];
    return f0.x*v0.x + f0.y*v0.y + f1.x*v0.z + f1.y*v0.w
         + f2.x*v1.x + f2.y*v1.y + f3.x*v1.z + f3.y*v1.w;
}

__global__ void __launch_bounds__(SBLOCK, 1) sinkhorn_kernel() {
    const int tid  = threadIdx.x;
    const int wid  = tid >> 5;
    const int lane = tid & 31;
    const int rloc = wid >> 1;
    const int half = wid & 1;
    const int row  = blockIdx.x * RPC + rloc;

    __shared__ float svec[N];
    __shared__ float spart[WPC];
    __shared__ float sdel[RPC];
    __shared__ float sflag;
    float4* svec4 = (float4*)svec;

    // uint4 = 8 halves; row has N/8 = 256 uint4; half-row = 128
    const uint4* erow  = (const uint4*)g_Eh  + (size_t)row * (N / 8) + half * (N / 16);
    const uint4* etrow = (const uint4*)g_ETh + (size_t)row * (N / 8) + half * (N / 16);
    const float4* sv = svec4 + half * (N / 8);   // float4 view of this half

    float u_old = 1.0f;

    for (int t = 0; t < ITERS; ++t) {
        {
            const float4* v4 = (const float4*)g_v;
            if (tid < N / 4) svec4[tid] = v4[tid];
            __syncthreads();

            float s = 0.0f;
#pragma unroll
            for (int jb = 0; jb < N / 16; jb += 32) {
                uint4 e = erow[jb + lane];
                s += dot8(e, sv + 2 * (jb + lane));
            }
#pragma unroll
            for (int o = 16; o > 0; o >>= 1) s += __shfl_xor_sync(0xffffffffu, s, o);
            if (lane == 0) spart[wid] = s;
            __syncthreads();

            if (half == 0 && lane == 0) {
                float tot = spart[wid] + spart[wid + 1];
                float un = 1.0f / tot;
                g_u[row] = un;
                sdel[rloc] = fabsf(un - u_old) / u_old;
                u_old = un;
            }
            __syncthreads();
            if (tid == 0) {
                float dm = 0.0f;
#pragma unroll
                for (int i = 0; i < RPC; ++i) dm = fmaxf(dm, sdel[i]);
                atomicMax(&g_delta[t & 1], __float_as_uint(dm));
            }
        }
        grid_sync();

        if (tid == 0) {
            unsigned db;
            asm volatile("ld.acquire.gpu.global.u32 %0, [%1];" : "=r"(db) : "l"(&g_delta[t & 1]));
            sflag = (t > 0 && __uint_as_float(db) < EPS_CONV) ? 1.0f : 0.0f;
            g_delta[(t + 1) & 1] = 0u;
        }

        bool conv;
        {
            const float4* u4 = (const float4*)g_u;
            if (tid < N / 4) svec4[tid] = u4[tid];
            __syncthreads();
            conv = (sflag > 0.5f);

            float s = 0.0f;
#pragma unroll
            for (int jb = 0; jb < N / 16; jb += 32) {
                uint4 e = etrow[jb + lane];
                s += dot8(e, sv + 2 * (jb + lane));
            }
#pragma unroll
            for (int o = 16; o > 0; o >>= 1) s += __shfl_xor_sync(0xffffffffu, s, o);
            if (lane == 0) spart[wid] = s;
            __syncthreads();
            if (half == 0 && lane == 0) {
                float tot = spart[wid] + spart[wid + 1];
                g_v[row] = 1.0f / tot;
            }
        }
        grid_sync();

        if (conv) break;
    }
}

// ---------------- F (fp16) and G (fp16), warp-shuffle scan -----------------------
__device__ __forceinline__ uint32_t pack_h2(__half a, __half b) {
    __half2 t = __halves2half2(a, b);
    return *(uint32_t*)&t;
}

__global__ void fg_kernel() {
    int row  = blockIdx.x;
    int t    = threadIdx.x;
    int lane = t & 31;
    int wid  = t >> 5;
    float uu = g_u[row];

    // 8 elements per thread (uint4 of 8 halves)
    uint4 e = ((const uint4*)g_Eh)[(size_t)row * (N / 8) + t];
    const float4* v4 = (const float4*)g_v;
    float4 w0 = v4[t * 2], w1 = v4[t * 2 + 1];

    __half2 h0 = *(__half2*)&e.x, h1 = *(__half2*)&e.y,
            h2 = *(__half2*)&e.z, h3 = *(__half2*)&e.w;
    float2 f0 = __half22float2(h0), f1 = __half22float2(h1),
           f2 = __half22float2(h2), f3 = __half22float2(h3);

    float m[8];
    m[0] = uu * f0.x * w0.x;  m[1] = uu * f0.y * w0.y;
    m[2] = uu * f1.x * w0.z;  m[3] = uu * f1.y * w0.w;
    m[4] = uu * f2.x * w1.x;  m[5] = uu * f2.y * w1.y;
    m[6] = uu * f3.x * w1.z;  m[7] = uu * f3.y * w1.w;

    float tsum = 0.0f;
#pragma unroll
    for (int q = 0; q < 8; ++q) tsum += m[q];

    // inclusive warp scan of tsum
    float x = tsum;
#pragma unroll
    for (int o = 1; o < 32; o <<= 1) {
        float y = __shfl_up_sync(0xffffffffu, x, o);
        if (lane >= o) x += y;
    }

    __shared__ float wsum[8];
    if (lane == 31) wsum[wid] = x;
    __syncthreads();

    float woff = 0.0f, total = 0.0f;
#pragma unroll
    for (int i = 0; i < 8; ++i) {
        float w = wsum[i];
        if (i < wid) woff += w;
        total += w;
    }

    float run = woff + x;      // inclusive prefix through this thread's chunk
    float pf  = run - tsum;    // exclusive prefix before this thread's chunk

    float g[8];
#pragma unroll
    for (int q = 0; q < 8; ++q) { g[q] = total - pf; pf += m[q]; }

    __half fh[8], gh[8];
#pragma unroll
    for (int q = 0; q < 8; ++q) {
        fh[q] = __float2half_rn(m[q]);
        gh[q] = __float2half_rn(g[q]);
    }

    size_t base = ((size_t)row * N) / 8 + t;
    ((uint4*)g_Fh)[base] = make_uint4(pack_h2(fh[0],fh[1]), pack_h2(fh[2],fh[3]),
                                      pack_h2(fh[4],fh[5]), pack_h2(fh[6],fh[7]));
    ((uint4*)g_Gh)[base] = make_uint4(pack_h2(gh[0],gh[1]), pack_h2(gh[2],gh[3]),
                                      pack_h2(gh[4],gh[5]), pack_h2(gh[6],gh[7]));
}

// ================= mma.sync fp16 single-term GEMM, 4-stage pipeline ==============
#define BK       32
#define KCHUNKS  (N / BK)              // 64
#define PITCH    40                    // halves per smem row (32 + 8 pad) -> 80B
#define TILE_B   (128 * PITCH * 2)     // 10240 bytes per tile
#define STAGE_B  (2 * TILE_B)          // Ah, Bh = 20480 bytes
#define NSTAGE   4
#define GT       256

__device__ __forceinline__ uint32_t smem_u32(const void* p) {
    uint32_t a;
    asm("{ .reg .u64 t; cvta.to.shared.u64 t, %1; cvt.u32.u64 %0, t; }" : "=r"(a) : "l"(p));
    return a;
}
__device__ __forceinline__ void cp16(uint32_t dst, const void* src) {
    asm volatile("cp.async.cg.shared.global [%0], [%1], 16;" :: "r"(dst), "l"(src));
}
__device__ __forceinline__ void cp_commit() { asm volatile("cp.async.commit_group;" ::: "memory"); }
__device__ __forceinline__ void cp_wait2()  { asm volatile("cp.async.wait_group 2;" ::: "memory"); }

__device__ __forceinline__ void ldsm4(uint32_t addr, uint32_t* r) {
    asm volatile("ldmatrix.sync.aligned.m8n8.x4.shared.b16 {%0,%1,%2,%3}, [%4];"
                 : "=r"(r[0]), "=r"(r[1]), "=r"(r[2]), "=r"(r[3]) : "r"(addr));
}
__device__ __forceinline__ void mma16816(float* c, const uint32_t* a, uint32_t b0, uint32_t b1) {
    asm volatile("mma.sync.aligned.m16n8k16.row.col.f32.f16.f16.f32 "
                 "{%0,%1,%2,%3}, {%4,%5,%6,%7}, {%8,%9}, {%0,%1,%2,%3};"
                 : "+f"(c[0]), "+f"(c[1]), "+f"(c[2]), "+f"(c[3])
                 : "r"(a[0]), "r"(a[1]), "r"(a[2]), "r"(a[3]), "r"(b0), "r"(b1));
}

__device__ __forceinline__ void load_stage(uint32_t S, int bi, int bj, int k0, int tid) {
    const __half* gs0 = g_Fh + (size_t)bi * N + k0;
    const __half* gs1 = g_Gh + (size_t)bj * N + k0;
#pragma unroll
    for (int i = 0; i < 4; ++i) {
        int p = tid + i * GT;
        int tile = p >> 9;
        int r = (p >> 2) & 127;
        int s = p & 3;
        const __half* src = (tile == 0 ? gs0 : gs1) + (size_t)r * N + s * 8;
        uint32_t dst = S + tile * TILE_B + r * (PITCH * 2) + s * 16;
        cp16(dst, src);
    }
}

__global__ void __launch_bounds__(GT, 2) gemm_kernel(float* __restrict__ C) {
    extern __shared__ char smem[];
    const uint32_t SB = smem_u32(smem);

    const int tid  = threadIdx.x;
    const int lane = tid & 31;
    const int wid  = tid >> 5;
    const int wm   = wid & 3;
    const int wn   = wid >> 2;
    const int bi   = blockIdx.y * 128;
    const int bj   = blockIdx.x * 128;

    const int arow = lane & 15;
    const int asel = lane >> 4;
    const int brow = (lane & 7) + ((lane >> 4) << 3);
    const int bsel = (lane >> 3) & 1;

    float acc[2][8][4];
#pragma unroll
    for (int mi = 0; mi < 2; ++mi)
#pragma unroll
        for (int ni = 0; ni < 8; ++ni)
#pragma unroll
            for (int q = 0; q < 4; ++q) acc[mi][ni][q] = 0.0f;

#pragma unroll
    for (int s = 0; s < NSTAGE - 1; ++s) {
        load_stage(SB + s * STAGE_B, bi, bj, s * BK, tid);
        cp_commit();
    }

    for (int c = 0; c < KCHUNKS; ++c) {
        cp_wait2();
        __syncthreads();

        if (c + NSTAGE - 1 < KCHUNKS)
            load_stage(SB + ((c + NSTAGE - 1) % NSTAGE) * STAGE_B, bi, bj, (c + NSTAGE - 1) * BK, tid);
        cp_commit();

        const uint32_t S = SB + (c % NSTAGE) * STAGE_B;
        const uint32_t Sah = S;
        const uint32_t Sbh = S + TILE_B;

#pragma unroll
        for (int kk = 0; kk < BK; kk += 16) {
            uint32_t ah[2][4];
#pragma unroll
            for (int mi = 0; mi < 2; ++mi) {
                uint32_t off = (uint32_t)((wm * 32 + mi * 16 + arow) * (PITCH * 2) + (kk + asel * 8) * 2);
                ldsm4(Sah + off, ah[mi]);
            }
#pragma unroll
            for (int h = 0; h < 2; ++h) {
                uint32_t bh[2][4];
#pragma unroll
                for (int q = 0; q < 2; ++q) {
                    int np = h * 2 + q;
                    uint32_t off = (uint32_t)((wn * 64 + np * 16 + brow) * (PITCH * 2) + (kk + bsel * 8) * 2);
                    ldsm4(Sbh + off, bh[q]);
                }
#pragma unroll
                for (int q = 0; q < 2; ++q) {
                    int np = h * 2 + q;
#pragma unroll
                    for (int mi = 0; mi < 2; ++mi) {
                        mma16816(acc[mi][2 * np],     ah[mi], bh[q][0], bh[q][1]);
                        mma16816(acc[mi][2 * np + 1], ah[mi], bh[q][2], bh[q][3]);
                    }
                }
            }
        }
    }

    const int gid = lane >> 2;
    const int tig = lane & 3;
#pragma unroll
    for (int mi = 0; mi < 2; ++mi) {
#pragma unroll
        for (int ni = 0; ni < 8; ++ni) {
            int a0 = bi + wm * 32 + mi * 16 + gid;
            int b0 = bj + wn * 64 + ni * 8 + tig * 2;
            *(float2*)(C + (size_t)a0 * N + b0)       = make_float2(acc[mi][ni][0], acc[mi][ni][1]);
            *(float2*)(C + (size_t)(a0 + 8) * N + b0) = make_float2(acc[mi][ni][2], acc[mi][ni][3]);
        }
    }
}

// ---------------- launch --------------------------------------------------------
extern "C" void kernel_launch(void* const* d_in, const int* in_sizes, int n_in,
                              void* d_out, int out_size) {
    const float* A = (const float*)d_in[0];
    float* out = (float*)d_out;

    static const int GEMM_SMEM = NSTAGE * STAGE_B;   // 81920 bytes
    cudaFuncSetAttribute(gemm_kernel, cudaFuncAttributeMaxDynamicSharedMemorySize, GEMM_SMEM);

    rowmax_kernel<<<N, 256>>>(A);
    exp_kernel<<<dim3(N / 32, N / 32), dim3(32, 32)>>>(A);
    sinkhorn_kernel<<<SGRID, SBLOCK>>>();
    fg_kernel<<<N, 256>>>();
    gemm_kernel<<<dim3(N / 128, N / 128), GT, GEMM_SMEM>>>(out);
}

// round 11
// speedup vs baseline: 76.4390x; 1.0355x over previous
#include <cuda_runtime.h>
#include <cuda_fp16.h>
#include <math.h>
#include <stdint.h>

#define N       2048
#define ITERS   1000
#define TEMP    100.0f
#define EPS_CONV 1e-5f

#define SGRID   128
#define SBLOCK  512
#define WPC     16              // warps per CTA = rows per CTA (1 warp : 1 row)

// ---------------- scratch (static device globals; allocation-free) -------------
__device__ __half g_Eh [N * N];   // exp matrix, fp16
__device__ __half g_ETh[N * N];   // transpose, fp16
__device__ __half g_Gp[N * N];    // G' = v ⊙ rowSuffixSum(m), fp16
__device__ float g_u[N];
__device__ float g_v[N];
__device__ float g_rowmax[N];

__device__ unsigned g_count = 0;
__device__ unsigned g_gen   = 0;
__device__ unsigned g_delta[2] = {0, 0};

// ---------------- acquire/release grid barrier ---------------------------------
__device__ __forceinline__ void grid_sync() {
    __syncthreads();
    if (threadIdx.x == 0) {
        unsigned my;
        asm volatile("ld.acquire.gpu.global.u32 %0, [%1];" : "=r"(my) : "l"(&g_gen));
        unsigned old;
        asm volatile("atom.release.gpu.global.add.u32 %0, [%1], %2;"
                     : "=r"(old) : "l"(&g_count), "r"(1u));
        if (old == SGRID - 1) {
            asm volatile("st.relaxed.gpu.global.u32 [%0], %1;" :: "l"(&g_count), "r"(0u));
            asm volatile("st.release.gpu.global.u32 [%0], %1;" :: "l"(&g_gen), "r"(my + 1u));
        } else {
            unsigned cur;
            do {
                asm volatile("ld.acquire.gpu.global.u32 %0, [%1];" : "=r"(cur) : "l"(&g_gen));
            } while (cur == my);
        }
    }
    __syncthreads();
}

// ---------------- prep kernels ---------------------------------------------------
__global__ void rowmax_kernel(const float* __restrict__ A) {
    int row = blockIdx.x;
    const float* a = A + (size_t)row * N;
    float m = -3.0e38f;
    for (int j = threadIdx.x; j < N; j += blockDim.x) m = fmaxf(m, a[j]);
    __shared__ float s[256];
    s[threadIdx.x] = m;
    __syncthreads();
    for (int o = 128; o > 0; o >>= 1) {
        if (threadIdx.x < o) s[threadIdx.x] = fmaxf(s[threadIdx.x], s[threadIdx.x + o]);
        __syncthreads();
    }
    if (threadIdx.x == 0) {
        g_rowmax[row] = s[0];
        g_u[row] = 1.0f; g_v[row] = 1.0f;
        if (row < 2) g_delta[row] = 0u;
    }
}

__global__ void exp_kernel(const float* __restrict__ A) {
    __shared__ __half tile[32][33];
    int x = blockIdx.x * 32 + threadIdx.x;
    int y = blockIdx.y * 32 + threadIdx.y;
    float rm = g_rowmax[y];
    __half e = __float2half_rn(expf(TEMP * (A[(size_t)y * N + x] - rm)));
    g_Eh[(size_t)y * N + x] = e;
    tile[threadIdx.y][threadIdx.x] = e;
    __syncthreads();
    int tx = blockIdx.y * 32 + threadIdx.x;
    int ty = blockIdx.x * 32 + threadIdx.y;
    g_ETh[(size_t)ty * N + tx] = tile[threadIdx.x][threadIdx.y];
}

// ---------------- persistent Sinkhorn: E rows held in REGISTERS -----------------
__device__ __forceinline__ float dot8(uint4 e, const float4* sv2i) {
    __half2 h0 = *(__half2*)&e.x, h1 = *(__half2*)&e.y,
            h2 = *(__half2*)&e.z, h3 = *(__half2*)&e.w;
    float2 f0 = __half22float2(h0), f1 = __half22float2(h1),
           f2 = __half22float2(h2), f3 = __half22float2(h3);
    float4 v0 = sv2i[0], v1 = sv2i[1];
    return f0.x*v0.x + f0.y*v0.y + f1.x*v0.z + f1.y*v0.w
         + f2.x*v1.x + f2.y*v1.y + f3.x*v1.z + f3.y*v1.w;
}

__global__ void __launch_bounds__(SBLOCK, 1) sinkhorn_kernel() {
    const int tid  = threadIdx.x;
    const int wid  = tid >> 5;
    const int lane = tid & 31;
    const int row  = blockIdx.x * WPC + wid;   // 128 * 16 = 2048 rows

    __shared__ float svec[N];
    __shared__ float sdel[WPC];
    __shared__ float sflag;
    float4* svec4 = (float4*)svec;

    // Load this warp's E row and ET row into registers ONCE (loop-invariant).
    const uint4* erow  = (const uint4*)g_Eh  + (size_t)row * (N / 8);
    const uint4* etrow = (const uint4*)g_ETh + (size_t)row * (N / 8);
    uint4 eR[8], etR[8];
#pragma unroll
    for (int i = 0; i < 8; ++i) {
        eR[i]  = erow [i * 32 + lane];
        etR[i] = etrow[i * 32 + lane];
    }

    float u_old = 1.0f;

    for (int t = 0; t < ITERS; ++t) {
        // ---------- phase A: u = 1 / (E v) ----------
        {
            const float4* v4 = (const float4*)g_v;
            svec4[tid] = v4[tid];            // 512 threads x float4 = N floats
            __syncthreads();

            float s = 0.0f;
#pragma unroll
            for (int i = 0; i < 8; ++i)
                s += dot8(eR[i], svec4 + 2 * (i * 32 + lane));
#pragma unroll
            for (int o = 16; o > 0; o >>= 1) s += __shfl_xor_sync(0xffffffffu, s, o);
            if (lane == 0) {
                float un = 1.0f / s;
                g_u[row] = un;
                sdel[wid] = fabsf(un - u_old) / u_old;
                u_old = un;
            }
            __syncthreads();
            if (tid == 0) {
                float dm = 0.0f;
#pragma unroll
                for (int i = 0; i < WPC; ++i) dm = fmaxf(dm, sdel[i]);
                atomicMax(&g_delta[t & 1], __float_as_uint(dm));
            }
        }
        grid_sync();

        if (tid == 0) {
            unsigned db;
            asm volatile("ld.acquire.gpu.global.u32 %0, [%1];" : "=r"(db) : "l"(&g_delta[t & 1]));
            sflag = (t > 0 && __uint_as_float(db) < EPS_CONV) ? 1.0f : 0.0f;
            g_delta[(t + 1) & 1] = 0u;
        }

        // ---------- phase B: v = 1 / (ET u) ----------
        bool conv;
        {
            const float4* u4 = (const float4*)g_u;
            svec4[tid] = u4[tid];
            __syncthreads();
            conv = (sflag > 0.5f);

            float s = 0.0f;
#pragma unroll
            for (int i = 0; i < 8; ++i)
                s += dot8(etR[i], svec4 + 2 * (i * 32 + lane));
#pragma unroll
            for (int o = 16; o > 0; o >>= 1) s += __shfl_xor_sync(0xffffffffu, s, o);
            if (lane == 0) g_v[row] = 1.0f / s;
        }
        grid_sync();

        if (conv) break;
    }
}

// ---------------- G' = v ⊙ rowSuffixSum(m), fp16 ---------------------------------
__device__ __forceinline__ uint32_t pack_h2(__half a, __half b) {
    __half2 t = __halves2half2(a, b);
    return *(uint32_t*)&t;
}

__global__ void g_kernel() {
    int row  = blockIdx.x;
    int t    = threadIdx.x;
    int lane = t & 31;
    int wid  = t >> 5;
    float uu = g_u[row];

    uint4 e = ((const uint4*)g_Eh)[(size_t)row * (N / 8) + t];
    const float4* v4 = (const float4*)g_v;
    float4 w0 = v4[t * 2], w1 = v4[t * 2 + 1];

    __half2 h0 = *(__half2*)&e.x, h1 = *(__half2*)&e.y,
            h2 = *(__half2*)&e.z, h3 = *(__half2*)&e.w;
    float2 f0 = __half22float2(h0), f1 = __half22float2(h1),
           f2 = __half22float2(h2), f3 = __half22float2(h3);

    float m[8], vv[8];
    vv[0] = w0.x; vv[1] = w0.y; vv[2] = w0.z; vv[3] = w0.w;
    vv[4] = w1.x; vv[5] = w1.y; vv[6] = w1.z; vv[7] = w1.w;
    m[0] = uu * f0.x * vv[0];  m[1] = uu * f0.y * vv[1];
    m[2] = uu * f1.x * vv[2];  m[3] = uu * f1.y * vv[3];
    m[4] = uu * f2.x * vv[4];  m[5] = uu * f2.y * vv[5];
    m[6] = uu * f3.x * vv[6];  m[7] = uu * f3.y * vv[7];

    float tsum = 0.0f;
#pragma unroll
    for (int q = 0; q < 8; ++q) tsum += m[q];

    // inclusive warp scan of tsum
    float x = tsum;
#pragma unroll
    for (int o = 1; o < 32; o <<= 1) {
        float y = __shfl_up_sync(0xffffffffu, x, o);
        if (lane >= o) x += y;
    }

    __shared__ float wsum[8];
    if (lane == 31) wsum[wid] = x;
    __syncthreads();

    float woff = 0.0f, total = 0.0f;
#pragma unroll
    for (int i = 0; i < 8; ++i) {
        float w = wsum[i];
        if (i < wid) woff += w;
        total += w;
    }

    float run = woff + x;      // inclusive prefix through this thread's chunk
    float pf  = run - tsum;    // exclusive prefix before this thread's chunk

    __half gh[8];
#pragma unroll
    for (int q = 0; q < 8; ++q) {
        float g = total - pf;          // suffix sum at column t*8+q
        pf += m[q];
        gh[q] = __float2half_rn(g * vv[q]);   // G' = v_k * G
    }

    ((uint4*)g_Gp)[(size_t)row * (N / 8) + t] =
        make_uint4(pack_h2(gh[0],gh[1]), pack_h2(gh[2],gh[3]),
                   pack_h2(gh[4],gh[5]), pack_h2(gh[6],gh[7]));
}

// ================= mma.sync fp16 GEMM: C[a,b] = u_a * dot(E[a,:], G'[b,:]) =======
#define BK       32
#define KCHUNKS  (N / BK)              // 64
#define PITCH    40                    // halves per smem row (32 + 8 pad) -> 80B
#define TILE_B   (128 * PITCH * 2)     // 10240 bytes per tile
#define STAGE_B  (2 * TILE_B)          // A(E), B(G') = 20480 bytes
#define NSTAGE   4
#define GT       256

__device__ __forceinline__ uint32_t smem_u32(const void* p) {
    uint32_t a;
    asm("{ .reg .u64 t; cvta.to.shared.u64 t, %1; cvt.u32.u64 %0, t; }" : "=r"(a) : "l"(p));
    return a;
}
__device__ __forceinline__ void cp16(uint32_t dst, const void* src) {
    asm volatile("cp.async.cg.shared.global [%0], [%1], 16;" :: "r"(dst), "l"(src));
}
__device__ __forceinline__ void cp_commit() { asm volatile("cp.async.commit_group;" ::: "memory"); }
__device__ __forceinline__ void cp_wait2()  { asm volatile("cp.async.wait_group 2;" ::: "memory"); }

__device__ __forceinline__ void ldsm4(uint32_t addr, uint32_t* r) {
    asm volatile("ldmatrix.sync.aligned.m8n8.x4.shared.b16 {%0,%1,%2,%3}, [%4];"
                 : "=r"(r[0]), "=r"(r[1]), "=r"(r[2]), "=r"(r[3]) : "r"(addr));
}
__device__ __forceinline__ void mma16816(float* c, const uint32_t* a, uint32_t b0, uint32_t b1) {
    asm volatile("mma.sync.aligned.m16n8k16.row.col.f32.f16.f16.f32 "
                 "{%0,%1,%2,%3}, {%4,%5,%6,%7}, {%8,%9}, {%0,%1,%2,%3};"
                 : "+f"(c[0]), "+f"(c[1]), "+f"(c[2]), "+f"(c[3])
                 : "r"(a[0]), "r"(a[1]), "r"(a[2]), "r"(a[3]), "r"(b0), "r"(b1));
}

__device__ __forceinline__ void load_stage(uint32_t S, int bi, int bj, int k0, int tid) {
    const __half* gs0 = g_Eh + (size_t)bi * N + k0;
    const __half* gs1 = g_Gp + (size_t)bj * N + k0;
#pragma unroll
    for (int i = 0; i < 4; ++i) {
        int p = tid + i * GT;
        int tile = p >> 9;
        int r = (p >> 2) & 127;
        int s = p & 3;
        const __half* src = (tile == 0 ? gs0 : gs1) + (size_t)r * N + s * 8;
        uint32_t dst = S + tile * TILE_B + r * (PITCH * 2) + s * 16;
        cp16(dst, src);
    }
}

__global__ void __launch_bounds__(GT, 2) gemm_kernel(float* __restrict__ C) {
    extern __shared__ char smem[];
    const uint32_t SB = smem_u32(smem);

    const int tid  = threadIdx.x;
    const int lane = tid & 31;
    const int wid  = tid >> 5;
    const int wm   = wid & 3;
    const int wn   = wid >> 2;
    const int bi   = blockIdx.y * 128;
    const int bj   = blockIdx.x * 128;

    const int arow = lane & 15;
    const int asel = lane >> 4;
    const int brow = (lane & 7) + ((lane >> 4) << 3);
    const int bsel = (lane >> 3) & 1;

    float acc[2][8][4];
#pragma unroll
    for (int mi = 0; mi < 2; ++mi)
#pragma unroll
        for (int ni = 0; ni < 8; ++ni)
#pragma unroll
            for (int q = 0; q < 4; ++q) acc[mi][ni][q] = 0.0f;

#pragma unroll
    for (int s = 0; s < NSTAGE - 1; ++s) {
        load_stage(SB + s * STAGE_B, bi, bj, s * BK, tid);
        cp_commit();
    }

    for (int c = 0; c < KCHUNKS; ++c) {
        cp_wait2();
        __syncthreads();

        if (c + NSTAGE - 1 < KCHUNKS)
            load_stage(SB + ((c + NSTAGE - 1) % NSTAGE) * STAGE_B, bi, bj, (c + NSTAGE - 1) * BK, tid);
        cp_commit();

        const uint32_t S = SB + (c % NSTAGE) * STAGE_B;
        const uint32_t Sah = S;
        const uint32_t Sbh = S + TILE_B;

#pragma unroll
        for (int kk = 0; kk < BK; kk += 16) {
            uint32_t ah[2][4];
#pragma unroll
            for (int mi = 0; mi < 2; ++mi) {
                uint32_t off = (uint32_t)((wm * 32 + mi * 16 + arow) * (PITCH * 2) + (kk + asel * 8) * 2);
                ldsm4(Sah + off, ah[mi]);
            }
#pragma unroll
            for (int h = 0; h < 2; ++h) {
                uint32_t bh[2][4];
#pragma unroll
                for (int q = 0; q < 2; ++q) {
                    int np = h * 2 + q;
                    uint32_t off = (uint32_t)((wn * 64 + np * 16 + brow) * (PITCH * 2) + (kk + bsel * 8) * 2);
                    ldsm4(Sbh + off, bh[q]);
                }
#pragma unroll
                for (int q = 0; q < 2; ++q) {
                    int np = h * 2 + q;
#pragma unroll
                    for (int mi = 0; mi < 2; ++mi) {
                        mma16816(acc[mi][2 * np],     ah[mi], bh[q][0], bh[q][1]);
                        mma16816(acc[mi][2 * np + 1], ah[mi], bh[q][2], bh[q][3]);
                    }
                }
            }
        }
    }

    // epilogue: scale by u_a and store
    const int gid = lane >> 2;
    const int tig = lane & 3;
#pragma unroll
    for (int mi = 0; mi < 2; ++mi) {
        int a0 = bi + wm * 32 + mi * 16 + gid;
        float u0 = g_u[a0];
        float u8 = g_u[a0 + 8];
#pragma unroll
        for (int ni = 0; ni < 8; ++ni) {
            int b0 = bj + wn * 64 + ni * 8 + tig * 2;
            *(float2*)(C + (size_t)a0 * N + b0) =
                make_float2(acc[mi][ni][0] * u0, acc[mi][ni][1] * u0);
            *(float2*)(C + (size_t)(a0 + 8) * N + b0) =
                make_float2(acc[mi][ni][2] * u8, acc[mi][ni][3] * u8);
        }
    }
}

// ---------------- launch --------------------------------------------------------
extern "C" void kernel_launch(void* const* d_in, const int* in_sizes, int n_in,
                              void* d_out, int out_size) {
    const float* A = (const float*)d_in[0];
    float* out = (float*)d_out;

    static const int GEMM_SMEM = NSTAGE * STAGE_B;   // 81920 bytes
    cudaFuncSetAttribute(gemm_kernel, cudaFuncAttributeMaxDynamicSharedMemorySize, GEMM_SMEM);

    rowmax_kernel<<<N, 256>>>(A);
    exp_kernel<<<dim3(N / 32, N / 32), dim3(32, 32)>>>(A);
    sinkhorn_kernel<<<SGRID, SBLOCK>>>();
    g_kernel<<<N, 256>>>();
    gemm_kernel<<<dim3(N / 128, N / 128), GT, GEMM_SMEM>>>(out);
}

// round 12
// speedup vs baseline: 77.7160x; 1.0167x over previous
#include <cuda_runtime.h>
#include <cuda_fp16.h>
#include <math.h>
#include <stdint.h>

#define N       2048
#define ITERS   1000
#define TEMP    100.0f
#define EPS_CONV 1e-4f

#define SGRID   128
#define SBLOCK  512
#define WPC     16              // warps per CTA = rows per CTA (1 warp : 1 row)

// ---------------- scratch (static device globals; allocation-free) -------------
__device__ __half g_Eh [N * N];   // exp matrix, fp16
__device__ __half g_ETh[N * N];   // transpose, fp16
__device__ __half g_Gp[N * N];    // G' = v ⊙ rowSuffixSum(m), fp16
__device__ float g_u[N];
__device__ float g_v[N];
__device__ float g_rowmax[N];

__device__ unsigned g_count = 0;
__device__ unsigned g_gen   = 0;
__device__ unsigned g_delta[2] = {0, 0};

// ---------------- acquire/release grid barrier ---------------------------------
__device__ __forceinline__ void grid_sync() {
    __syncthreads();
    if (threadIdx.x == 0) {
        unsigned my;
        asm volatile("ld.acquire.gpu.global.u32 %0, [%1];" : "=r"(my) : "l"(&g_gen));
        unsigned old;
        asm volatile("atom.release.gpu.global.add.u32 %0, [%1], %2;"
                     : "=r"(old) : "l"(&g_count), "r"(1u));
        if (old == SGRID - 1) {
            asm volatile("st.relaxed.gpu.global.u32 [%0], %1;" :: "l"(&g_count), "r"(0u));
            asm volatile("st.release.gpu.global.u32 [%0], %1;" :: "l"(&g_gen), "r"(my + 1u));
        } else {
            unsigned cur;
            do {
                asm volatile("ld.acquire.gpu.global.u32 %0, [%1];" : "=r"(cur) : "l"(&g_gen));
            } while (cur == my);
        }
    }
    __syncthreads();
}

// ---------------- prep kernels ---------------------------------------------------
__global__ void rowmax_kernel(const float* __restrict__ A) {
    int row = blockIdx.x;
    const float* a = A + (size_t)row * N;
    float m = -3.0e38f;
    for (int j = threadIdx.x; j < N; j += blockDim.x) m = fmaxf(m, a[j]);
    __shared__ float s[256];
    s[threadIdx.x] = m;
    __syncthreads();
    for (int o = 128; o > 0; o >>= 1) {
        if (threadIdx.x < o) s[threadIdx.x] = fmaxf(s[threadIdx.x], s[threadIdx.x + o]);
        __syncthreads();
    }
    if (threadIdx.x == 0) {
        g_rowmax[row] = s[0];
        g_u[row] = 1.0f; g_v[row] = 1.0f;
        if (row < 2) g_delta[row] = 0u;
    }
}

__global__ void exp_kernel(const float* __restrict__ A) {
    __shared__ __half tile[32][33];
    int x = blockIdx.x * 32 + threadIdx.x;
    int y = blockIdx.y * 32 + threadIdx.y;
    float rm = g_rowmax[y];
    __half e = __float2half_rn(expf(TEMP * (A[(size_t)y * N + x] - rm)));
    g_Eh[(size_t)y * N + x] = e;
    tile[threadIdx.y][threadIdx.x] = e;
    __syncthreads();
    int tx = blockIdx.y * 32 + threadIdx.x;
    int ty = blockIdx.x * 32 + threadIdx.y;
    g_ETh[(size_t)ty * N + tx] = tile[threadIdx.x][threadIdx.y];
}

// ---------------- persistent Sinkhorn: E rows held in REGISTERS -----------------
__device__ __forceinline__ float dot8(uint4 e, const float4* sv2i) {
    __half2 h0 = *(__half2*)&e.x, h1 = *(__half2*)&e.y,
            h2 = *(__half2*)&e.z, h3 = *(__half2*)&e.w;
    float2 f0 = __half22float2(h0), f1 = __half22float2(h1),
           f2 = __half22float2(h2), f3 = __half22float2(h3);
    float4 v0 = sv2i[0], v1 = sv2i[1];
    return f0.x*v0.x + f0.y*v0.y + f1.x*v0.z + f1.y*v0.w
         + f2.x*v1.x + f2.y*v1.y + f3.x*v1.z + f3.y*v1.w;
}

__global__ void __launch_bounds__(SBLOCK, 1) sinkhorn_kernel() {
    const int tid  = threadIdx.x;
    const int wid  = tid >> 5;
    const int lane = tid & 31;
    const int row  = blockIdx.x * WPC + wid;   // 128 * 16 = 2048 rows

    __shared__ float svec[N];
    __shared__ float sdel[WPC];
    __shared__ float sflag;
    float4* svec4 = (float4*)svec;

    // Load this warp's E row and ET row into registers ONCE (loop-invariant).
    const uint4* erow  = (const uint4*)g_Eh  + (size_t)row * (N / 8);
    const uint4* etrow = (const uint4*)g_ETh + (size_t)row * (N / 8);
    uint4 eR[8], etR[8];
#pragma unroll
    for (int i = 0; i < 8; ++i) {
        eR[i]  = erow [i * 32 + lane];
        etR[i] = etrow[i * 32 + lane];
    }

    float u_old = 1.0f;

    for (int t = 0; t < ITERS; ++t) {
        // ---------- phase A: u = 1 / (E v) ----------
        {
            const float4* v4 = (const float4*)g_v;
            svec4[tid] = v4[tid];
            __syncthreads();

            float s = 0.0f;
#pragma unroll
            for (int i = 0; i < 8; ++i)
                s += dot8(eR[i], svec4 + 2 * (i * 32 + lane));
#pragma unroll
            for (int o = 16; o > 0; o >>= 1) s += __shfl_xor_sync(0xffffffffu, s, o);
            if (lane == 0) {
                float un = 1.0f / s;
                g_u[row] = un;
                sdel[wid] = fabsf(un - u_old) / u_old;
                u_old = un;
            }
            __syncthreads();
            if (tid == 0) {
                float dm = 0.0f;
#pragma unroll
                for (int i = 0; i < WPC; ++i) dm = fmaxf(dm, sdel[i]);
                atomicMax(&g_delta[t & 1], __float_as_uint(dm));
            }
        }
        grid_sync();

        if (tid == 0) {
            unsigned db;
            asm volatile("ld.acquire.gpu.global.u32 %0, [%1];" : "=r"(db) : "l"(&g_delta[t & 1]));
            sflag = (t > 0 && __uint_as_float(db) < EPS_CONV) ? 1.0f : 0.0f;
            g_delta[(t + 1) & 1] = 0u;
        }

        // ---------- phase B: v = 1 / (ET u) ----------
        bool conv;
        {
            const float4* u4 = (const float4*)g_u;
            svec4[tid] = u4[tid];
            __syncthreads();
            conv = (sflag > 0.5f);

            float s = 0.0f;
#pragma unroll
            for (int i = 0; i < 8; ++i)
                s += dot8(etR[i], svec4 + 2 * (i * 32 + lane));
#pragma unroll
            for (int o = 16; o > 0; o >>= 1) s += __shfl_xor_sync(0xffffffffu, s, o);
            if (lane == 0) g_v[row] = 1.0f / s;
        }
        grid_sync();

        if (conv) break;
    }
}

// ---------------- G' = v ⊙ rowSuffixSum(m), fp16 ---------------------------------
__device__ __forceinline__ uint32_t pack_h2(__half a, __half b) {
    __half2 t = __halves2half2(a, b);
    return *(uint32_t*)&t;
}

__global__ void g_kernel() {
    int row  = blockIdx.x;
    int t    = threadIdx.x;
    int lane = t & 31;
    int wid  = t >> 5;
    float uu = g_u[row];

    uint4 e = ((const uint4*)g_Eh)[(size_t)row * (N / 8) + t];
    const float4* v4 = (const float4*)g_v;
    float4 w0 = v4[t * 2], w1 = v4[t * 2 + 1];

    __half2 h0 = *(__half2*)&e.x, h1 = *(__half2*)&e.y,
            h2 = *(__half2*)&e.z, h3 = *(__half2*)&e.w;
    float2 f0 = __half22float2(h0), f1 = __half22float2(h1),
           f2 = __half22float2(h2), f3 = __half22float2(h3);

    float m[8], vv[8];
    vv[0] = w0.x; vv[1] = w0.y; vv[2] = w0.z; vv[3] = w0.w;
    vv[4] = w1.x; vv[5] = w1.y; vv[6] = w1.z; vv[7] = w1.w;
    m[0] = uu * f0.x * vv[0];  m[1] = uu * f0.y * vv[1];
    m[2] = uu * f1.x * vv[2];  m[3] = uu * f1.y * vv[3];
    m[4] = uu * f2.x * vv[4];  m[5] = uu * f2.y * vv[5];
    m[6] = uu * f3.x * vv[6];  m[7] = uu * f3.y * vv[7];

    float tsum = 0.0f;
#pragma unroll
    for (int q = 0; q < 8; ++q) tsum += m[q];

    float x = tsum;
#pragma unroll
    for (int o = 1; o < 32; o <<= 1) {
        float y = __shfl_up_sync(0xffffffffu, x, o);
        if (lane >= o) x += y;
    }

    __shared__ float wsum[8];
    if (lane == 31) wsum[wid] = x;
    __syncthreads();

    float woff = 0.0f, total = 0.0f;
#pragma unroll
    for (int i = 0; i < 8; ++i) {
        float w = wsum[i];
        if (i < wid) woff += w;
        total += w;
    }

    float run = woff + x;
    float pf  = run - tsum;

    __half gh[8];
#pragma unroll
    for (int q = 0; q < 8; ++q) {
        float g = total - pf;
        pf += m[q];
        gh[q] = __float2half_rn(g * vv[q]);
    }

    ((uint4*)g_Gp)[(size_t)row * (N / 8) + t] =
        make_uint4(pack_h2(gh[0],gh[1]), pack_h2(gh[2],gh[3]),
                   pack_h2(gh[4],gh[5]), pack_h2(gh[6],gh[7]));
}

// ================= mma.sync fp16 GEMM: C[a,b] = u_a * dot(E[a,:], G'[b,:]) =======
// Software-pipelined fragments: A frags for both k-slices preloaded; B frags
// double-buffered so each ldsm is one full 8-MMA sweep ahead of its consumers.
#define BK       32
#define KCHUNKS  (N / BK)              // 64
#define PITCH    40                    // halves per smem row (32 + 8 pad) -> 80B
#define TILE_B   (128 * PITCH * 2)     // 10240 bytes per tile
#define STAGE_B  (2 * TILE_B)          // A(E), B(G') = 20480 bytes
#define NSTAGE   4
#define GT       256

__device__ __forceinline__ uint32_t smem_u32(const void* p) {
    uint32_t a;
    asm("{ .reg .u64 t; cvta.to.shared.u64 t, %1; cvt.u32.u64 %0, t; }" : "=r"(a) : "l"(p));
    return a;
}
__device__ __forceinline__ void cp16(uint32_t dst, const void* src) {
    asm volatile("cp.async.cg.shared.global [%0], [%1], 16;" :: "r"(dst), "l"(src));
}
__device__ __forceinline__ void cp_commit() { asm volatile("cp.async.commit_group;" ::: "memory"); }
__device__ __forceinline__ void cp_wait2()  { asm volatile("cp.async.wait_group 2;" ::: "memory"); }

__device__ __forceinline__ void ldsm4(uint32_t addr, uint32_t* r) {
    asm volatile("ldmatrix.sync.aligned.m8n8.x4.shared.b16 {%0,%1,%2,%3}, [%4];"
                 : "=r"(r[0]), "=r"(r[1]), "=r"(r[2]), "=r"(r[3]) : "r"(addr));
}
__device__ __forceinline__ void mma16816(float* c, const uint32_t* a, uint32_t b0, uint32_t b1) {
    asm volatile("mma.sync.aligned.m16n8k16.row.col.f32.f16.f16.f32 "
                 "{%0,%1,%2,%3}, {%4,%5,%6,%7}, {%8,%9}, {%0,%1,%2,%3};"
                 : "+f"(c[0]), "+f"(c[1]), "+f"(c[2]), "+f"(c[3])
                 : "r"(a[0]), "r"(a[1]), "r"(a[2]), "r"(a[3]), "r"(b0), "r"(b1));
}

__device__ __forceinline__ void load_stage(uint32_t S, int bi, int bj, int k0, int tid) {
    const __half* gs0 = g_Eh + (size_t)bi * N + k0;
    const __half* gs1 = g_Gp + (size_t)bj * N + k0;
#pragma unroll
    for (int i = 0; i < 4; ++i) {
        int p = tid + i * GT;
        int tile = p >> 9;
        int r = (p >> 2) & 127;
        int s = p & 3;
        const __half* src = (tile == 0 ? gs0 : gs1) + (size_t)r * N + s * 8;
        uint32_t dst = S + tile * TILE_B + r * (PITCH * 2) + s * 16;
        cp16(dst, src);
    }
}

__global__ void __launch_bounds__(GT, 2) gemm_kernel(float* __restrict__ C) {
    extern __shared__ char smem[];
    const uint32_t SB = smem_u32(smem);

    const int tid  = threadIdx.x;
    const int lane = tid & 31;
    const int wid  = tid >> 5;
    const int wm   = wid & 3;
    const int wn   = wid >> 2;
    const int bi   = blockIdx.y * 128;
    const int bj   = blockIdx.x * 128;

    const int arow = lane & 15;
    const int asel = lane >> 4;
    const int brow = (lane & 7) + ((lane >> 4) << 3);
    const int bsel = (lane >> 3) & 1;

    // Hoisted in-stage byte offsets (constant across chunks).
    // A slice s (kk = s*16), warp-row group mi; B slice s, np group.
    uint32_t aOff[2][2], bOff[2][4];
#pragma unroll
    for (int s = 0; s < 2; ++s) {
#pragma unroll
        for (int mi = 0; mi < 2; ++mi)
            aOff[s][mi] = (uint32_t)((wm * 32 + mi * 16 + arow) * (PITCH * 2) + (s * 16 + asel * 8) * 2);
#pragma unroll
        for (int np = 0; np < 4; ++np)
            bOff[s][np] = (uint32_t)((wn * 64 + np * 16 + brow) * (PITCH * 2) + (s * 16 + bsel * 8) * 2) + TILE_B;
    }

    float acc[2][8][4];
#pragma unroll
    for (int mi = 0; mi < 2; ++mi)
#pragma unroll
        for (int ni = 0; ni < 8; ++ni)
#pragma unroll
            for (int q = 0; q < 4; ++q) acc[mi][ni][q] = 0.0f;

#pragma unroll
    for (int s = 0; s < NSTAGE - 1; ++s) {
        load_stage(SB + s * STAGE_B, bi, bj, s * BK, tid);
        cp_commit();
    }

    for (int c = 0; c < KCHUNKS; ++c) {
        cp_wait2();
        __syncthreads();

        if (c + NSTAGE - 1 < KCHUNKS)
            load_stage(SB + ((c + NSTAGE - 1) % NSTAGE) * STAGE_B, bi, bj, (c + NSTAGE - 1) * BK, tid);
        cp_commit();

        const uint32_t S = SB + (c % NSTAGE) * STAGE_B;

        uint32_t aF[2][2][4];   // [slice][mi][4]
        uint32_t bF[2][2][4];   // [parity][q][4]

        // chunk prologue: all A frags + first B pair
        ldsm4(S + aOff[0][0], aF[0][0]);
        ldsm4(S + aOff[0][1], aF[0][1]);
        ldsm4(S + aOff[1][0], aF[1][0]);
        ldsm4(S + aOff[1][1], aF[1][1]);
        ldsm4(S + bOff[0][0], bF[0][0]);
        ldsm4(S + bOff[0][1], bF[0][1]);

        // step0: prefetch B(kk0, np2/3) -> bF[1]; MMA aF[0] x bF[0] (np 0,1)
        ldsm4(S + bOff[0][2], bF[1][0]);
        ldsm4(S + bOff[0][3], bF[1][1]);
#pragma unroll
        for (int q = 0; q < 2; ++q)
#pragma unroll
            for (int mi = 0; mi < 2; ++mi) {
                mma16816(acc[mi][2 * q],     aF[0][mi], bF[0][q][0], bF[0][q][1]);
                mma16816(acc[mi][2 * q + 1], aF[0][mi], bF[0][q][2], bF[0][q][3]);
            }

        // step1: prefetch B(kk1, np0/1) -> bF[0]; MMA aF[0] x bF[1] (np 2,3)
        ldsm4(S + bOff[1][0], bF[0][0]);
        ldsm4(S + bOff[1][1], bF[0][1]);
#pragma unroll
        for (int q = 0; q < 2; ++q)
#pragma unroll
            for (int mi = 0; mi < 2; ++mi) {
                mma16816(acc[mi][4 + 2 * q],     aF[0][mi], bF[1][q][0], bF[1][q][1]);
                mma16816(acc[mi][4 + 2 * q + 1], aF[0][mi], bF[1][q][2], bF[1][q][3]);
            }

        // step2: prefetch B(kk1, np2/3) -> bF[1]; MMA aF[1] x bF[0] (np 0,1)
        ldsm4(S + bOff[1][2], bF[1][0]);
        ldsm4(S + bOff[1][3], bF[1][1]);
#pragma unroll
        for (int q = 0; q < 2; ++q)
#pragma unroll
            for (int mi = 0; mi < 2; ++mi) {
                mma16816(acc[mi][2 * q],     aF[1][mi], bF[0][q][0], bF[0][q][1]);
                mma16816(acc[mi][2 * q + 1], aF[1][mi], bF[0][q][2], bF[0][q][3]);
            }

        // step3: MMA aF[1] x bF[1] (np 2,3)
#pragma unroll
        for (int q = 0; q < 2; ++q)
#pragma unroll
            for (int mi = 0; mi < 2; ++mi) {
                mma16816(acc[mi][4 + 2 * q],     aF[1][mi], bF[1][q][0], bF[1][q][1]);
                mma16816(acc[mi][4 + 2 * q + 1], aF[1][mi], bF[1][q][2], bF[1][q][3]);
            }
    }

    // epilogue: scale by u_a and store
    const int gid = lane >> 2;
    const int tig = lane & 3;
#pragma unroll
    for (int mi = 0; mi < 2; ++mi) {
        int a0 = bi + wm * 32 + mi * 16 + gid;
        float u0 = g_u[a0];
        float u8 = g_u[a0 + 8];
#pragma unroll
        for (int ni = 0; ni < 8; ++ni) {
            int b0 = bj + wn * 64 + ni * 8 + tig * 2;
            *(float2*)(C + (size_t)a0 * N + b0) =
                make_float2(acc[mi][ni][0] * u0, acc[mi][ni][1] * u0);
            *(float2*)(C + (size_t)(a0 + 8) * N + b0) =
                make_float2(acc[mi][ni][2] * u8, acc[mi][ni][3] * u8);
        }
    }
}

// ---------------- launch --------------------------------------------------------
extern "C" void kernel_launch(void* const* d_in, const int* in_sizes, int n_in,
                              void* d_out, int out_size) {
    const float* A = (const float*)d_in[0];
    float* out = (float*)d_out;

    static const int GEMM_SMEM = NSTAGE * STAGE_B;   // 81920 bytes
    cudaFuncSetAttribute(gemm_kernel, cudaFuncAttributeMaxDynamicSharedMemorySize, GEMM_SMEM);

    rowmax_kernel<<<N, 256>>>(A);
    exp_kernel<<<dim3(N / 32, N / 32), dim3(32, 32)>>>(A);
    sinkhorn_kernel<<<SGRID, SBLOCK>>>();
    g_kernel<<<N, 256>>>();
    gemm_kernel<<<dim3(N / 128, N / 128), GT, GEMM_SMEM>>>(out);
}

// round 13
// speedup vs baseline: 79.2528x; 1.0198x over previous
#include <cuda_runtime.h>
#include <cuda_fp16.h>
#include <math.h>
#include <stdint.h>

#define N       2048
#define ITERS   1000
#define TEMP    100.0f
#define EPS_CONV 1e-4f

#define SGRID   128
#define SBLOCK  512
#define WPC     16              // warps per CTA = rows per CTA (1 warp : 1 row)

// ---------------- scratch (static device globals; allocation-free) -------------
__device__ __half g_Eh [N * N];   // exp matrix, fp16
__device__ __half g_ETh[N * N];   // transpose, fp16
__device__ __half g_Gp[N * N];    // G' = v ⊙ rowSuffixSum(m), fp16
__device__ float g_u[N];
__device__ float g_v[N];
__device__ float g_rowmax[N];

__device__ unsigned g_count = 0;
__device__ unsigned g_gen   = 0;
__device__ unsigned g_delta[2] = {0, 0};

// ---------------- acquire/release grid barrier ---------------------------------
__device__ __forceinline__ void grid_sync() {
    __syncthreads();
    if (threadIdx.x == 0) {
        unsigned my;
        asm volatile("ld.acquire.gpu.global.u32 %0, [%1];" : "=r"(my) : "l"(&g_gen));
        unsigned old;
        asm volatile("atom.release.gpu.global.add.u32 %0, [%1], %2;"
                     : "=r"(old) : "l"(&g_count), "r"(1u));
        if (old == SGRID - 1) {
            asm volatile("st.relaxed.gpu.global.u32 [%0], %1;" :: "l"(&g_count), "r"(0u));
            asm volatile("st.release.gpu.global.u32 [%0], %1;" :: "l"(&g_gen), "r"(my + 1u));
        } else {
            unsigned cur;
            do {
                asm volatile("ld.acquire.gpu.global.u32 %0, [%1];" : "=r"(cur) : "l"(&g_gen));
            } while (cur == my);
        }
    }
    __syncthreads();
}

// ---------------- prep kernels ---------------------------------------------------
__global__ void rowmax_kernel(const float* __restrict__ A) {
    int row = blockIdx.x;
    const float* a = A + (size_t)row * N;
    float m = -3.0e38f;
    for (int j = threadIdx.x; j < N; j += blockDim.x) m = fmaxf(m, a[j]);
    __shared__ float s[256];
    s[threadIdx.x] = m;
    __syncthreads();
    for (int o = 128; o > 0; o >>= 1) {
        if (threadIdx.x < o) s[threadIdx.x] = fmaxf(s[threadIdx.x], s[threadIdx.x + o]);
        __syncthreads();
    }
    if (threadIdx.x == 0) {
        g_rowmax[row] = s[0];
        g_u[row] = 1.0f; g_v[row] = 1.0f;
        if (row < 2) g_delta[row] = 0u;
    }
}

__global__ void exp_kernel(const float* __restrict__ A) {
    __shared__ __half tile[32][33];
    int x = blockIdx.x * 32 + threadIdx.x;
    int y = blockIdx.y * 32 + threadIdx.y;
    float rm = g_rowmax[y];
    __half e = __float2half_rn(expf(TEMP * (A[(size_t)y * N + x] - rm)));
    g_Eh[(size_t)y * N + x] = e;
    tile[threadIdx.y][threadIdx.x] = e;
    __syncthreads();
    int tx = blockIdx.y * 32 + threadIdx.x;
    int ty = blockIdx.x * 32 + threadIdx.y;
    g_ETh[(size_t)ty * N + tx] = tile[threadIdx.x][threadIdx.y];
}

// ---------------- persistent Sinkhorn + fused G' epilogue -----------------------
__device__ __forceinline__ float dot8(uint4 e, const float4* sv2i) {
    __half2 h0 = *(__half2*)&e.x, h1 = *(__half2*)&e.y,
            h2 = *(__half2*)&e.z, h3 = *(__half2*)&e.w;
    float2 f0 = __half22float2(h0), f1 = __half22float2(h1),
           f2 = __half22float2(h2), f3 = __half22float2(h3);
    float4 v0 = sv2i[0], v1 = sv2i[1];
    return f0.x*v0.x + f0.y*v0.y + f1.x*v0.z + f1.y*v0.w
         + f2.x*v1.x + f2.y*v1.y + f3.x*v1.z + f3.y*v1.w;
}

__device__ __forceinline__ uint32_t pack_h2(__half a, __half b) {
    __half2 t = __halves2half2(a, b);
    return *(uint32_t*)&t;
}

__global__ void __launch_bounds__(SBLOCK, 1) sinkhorn_kernel() {
    const int tid  = threadIdx.x;
    const int wid  = tid >> 5;
    const int lane = tid & 31;
    const int row  = blockIdx.x * WPC + wid;   // 128 * 16 = 2048 rows

    __shared__ float svec[N];
    __shared__ float sdel[WPC];
    __shared__ float sflag;
    float4* svec4 = (float4*)svec;

    // Load this warp's E row and ET row into registers ONCE (loop-invariant).
    const uint4* erow  = (const uint4*)g_Eh  + (size_t)row * (N / 8);
    const uint4* etrow = (const uint4*)g_ETh + (size_t)row * (N / 8);
    uint4 eR[8], etR[8];
#pragma unroll
    for (int i = 0; i < 8; ++i) {
        eR[i]  = erow [i * 32 + lane];
        etR[i] = etrow[i * 32 + lane];
    }

    float u_old = 1.0f;

    for (int t = 0; t < ITERS; ++t) {
        // ---------- phase A: u = 1 / (E v) ----------
        {
            const float4* v4 = (const float4*)g_v;
            svec4[tid] = v4[tid];
            __syncthreads();

            float s = 0.0f;
#pragma unroll
            for (int i = 0; i < 8; ++i)
                s += dot8(eR[i], svec4 + 2 * (i * 32 + lane));
#pragma unroll
            for (int o = 16; o > 0; o >>= 1) s += __shfl_xor_sync(0xffffffffu, s, o);
            if (lane == 0) {
                float un = 1.0f / s;
                g_u[row] = un;
                sdel[wid] = fabsf(un - u_old) / u_old;
                u_old = un;
            }
            __syncthreads();
            if (tid == 0) {
                float dm = 0.0f;
#pragma unroll
                for (int i = 0; i < WPC; ++i) dm = fmaxf(dm, sdel[i]);
                atomicMax(&g_delta[t & 1], __float_as_uint(dm));
            }
        }
        grid_sync();

        if (tid == 0) {
            unsigned db;
            asm volatile("ld.acquire.gpu.global.u32 %0, [%1];" : "=r"(db) : "l"(&g_delta[t & 1]));
            sflag = (t > 0 && __uint_as_float(db) < EPS_CONV) ? 1.0f : 0.0f;
            g_delta[(t + 1) & 1] = 0u;
        }

        // ---------- phase B: v = 1 / (ET u) ----------
        bool conv;
        {
            const float4* u4 = (const float4*)g_u;
            svec4[tid] = u4[tid];
            __syncthreads();
            conv = (sflag > 0.5f);

            float s = 0.0f;
#pragma unroll
            for (int i = 0; i < 8; ++i)
                s += dot8(etR[i], svec4 + 2 * (i * 32 + lane));
#pragma unroll
            for (int o = 16; o > 0; o >>= 1) s += __shfl_xor_sync(0xffffffffu, s, o);
            if (lane == 0) g_v[row] = 1.0f / s;
        }
        grid_sync();

        if (conv) break;
    }

    // ---------- fused epilogue: G'[row,k] = v_k * suffixSum_k(u_row * E[row,:] ⊙ v) ----------
    {
        const float4* v4 = (const float4*)g_v;
        svec4[tid] = v4[tid];     // stage final v (visible after the last grid_sync)
        __syncthreads();

        float uu = __shfl_sync(0xffffffffu, u_old, 0);   // u[row] lives on lane 0

        // chunk sums: chunk (i,lane) covers elements (i*32+lane)*8 .. +7
        float cs[8], ics[8], T[8];
#pragma unroll
        for (int i = 0; i < 8; ++i)
            cs[i] = uu * dot8(eR[i], svec4 + 2 * (i * 32 + lane));

#pragma unroll
        for (int i = 0; i < 8; ++i) {
            float x = cs[i];
#pragma unroll
            for (int o = 1; o < 32; o <<= 1) {
                float y = __shfl_up_sync(0xffffffffu, x, o);
                if (lane >= o) x += y;
            }
            ics[i] = x;                                   // inclusive scan over lanes
            T[i] = __shfl_sync(0xffffffffu, x, 31);       // chunk-group total
        }

        float offi[8], tot = 0.0f;
#pragma unroll
        for (int i = 0; i < 8; ++i) { offi[i] = tot; tot += T[i]; }

        uint4* gp = (uint4*)g_Gp + (size_t)row * (N / 8);
#pragma unroll
        for (int i = 0; i < 8; ++i) {
            float pf = offi[i] + ics[i] - cs[i];          // exclusive prefix before this chunk

            const float4* sv2 = svec4 + 2 * (i * 32 + lane);
            float4 v0 = sv2[0], v1 = sv2[1];
            float vv[8] = {v0.x, v0.y, v0.z, v0.w, v1.x, v1.y, v1.z, v1.w};

            uint4 e = eR[i];
            __half2 h0 = *(__half2*)&e.x, h1 = *(__half2*)&e.y,
                    h2 = *(__half2*)&e.z, h3 = *(__half2*)&e.w;
            float2 f0 = __half22float2(h0), f1 = __half22float2(h1),
                   f2 = __half22float2(h2), f3 = __half22float2(h3);
            float m[8];
            m[0] = uu * f0.x * vv[0];  m[1] = uu * f0.y * vv[1];
            m[2] = uu * f1.x * vv[2];  m[3] = uu * f1.y * vv[3];
            m[4] = uu * f2.x * vv[4];  m[5] = uu * f2.y * vv[5];
            m[6] = uu * f3.x * vv[6];  m[7] = uu * f3.y * vv[7];

            __half gh[8];
#pragma unroll
            for (int q = 0; q < 8; ++q) {
                float g = tot - pf;                       // suffix sum incl. element k
                pf += m[q];
                gh[q] = __float2half_rn(g * vv[q]);
            }
            gp[i * 32 + lane] =
                make_uint4(pack_h2(gh[0],gh[1]), pack_h2(gh[2],gh[3]),
                           pack_h2(gh[4],gh[5]), pack_h2(gh[6],gh[7]));
        }
    }
}

// ================= mma.sync fp16 GEMM: C[a,b] = u_a * dot(E[a,:], G'[b,:]) =======
#define BK       32
#define KCHUNKS  (N / BK)              // 64
#define PITCH    40                    // halves per smem row (32 + 8 pad) -> 80B
#define TILE_B   (128 * PITCH * 2)     // 10240 bytes per tile
#define STAGE_B  (2 * TILE_B)          // A(E), B(G') = 20480 bytes
#define NSTAGE   4
#define GT       256

__device__ __forceinline__ uint32_t smem_u32(const void* p) {
    uint32_t a;
    asm("{ .reg .u64 t; cvta.to.shared.u64 t, %1; cvt.u32.u64 %0, t; }" : "=r"(a) : "l"(p));
    return a;
}
__device__ __forceinline__ void cp16(uint32_t dst, const void* src) {
    asm volatile("cp.async.cg.shared.global [%0], [%1], 16;" :: "r"(dst), "l"(src));
}
__device__ __forceinline__ void cp_commit() { asm volatile("cp.async.commit_group;" ::: "memory"); }
__device__ __forceinline__ void cp_wait2()  { asm volatile("cp.async.wait_group 2;" ::: "memory"); }

__device__ __forceinline__ void ldsm4(uint32_t addr, uint32_t* r) {
    asm volatile("ldmatrix.sync.aligned.m8n8.x4.shared.b16 {%0,%1,%2,%3}, [%4];"
                 : "=r"(r[0]), "=r"(r[1]), "=r"(r[2]), "=r"(r[3]) : "r"(addr));
}
__device__ __forceinline__ void mma16816(float* c, const uint32_t* a, uint32_t b0, uint32_t b1) {
    asm volatile("mma.sync.aligned.m16n8k16.row.col.f32.f16.f16.f32 "
                 "{%0,%1,%2,%3}, {%4,%5,%6,%7}, {%8,%9}, {%0,%1,%2,%3};"
                 : "+f"(c[0]), "+f"(c[1]), "+f"(c[2]), "+f"(c[3])
                 : "r"(a[0]), "r"(a[1]), "r"(a[2]), "r"(a[3]), "r"(b0), "r"(b1));
}

__device__ __forceinline__ void load_stage(uint32_t S, int bi, int bj, int k0, int tid) {
    const __half* gs0 = g_Eh + (size_t)bi * N + k0;
    const __half* gs1 = g_Gp + (size_t)bj * N + k0;
#pragma unroll
    for (int i = 0; i < 4; ++i) {
        int p = tid + i * GT;
        int tile = p >> 9;
        int r = (p >> 2) & 127;
        int s = p & 3;
        const __half* src = (tile == 0 ? gs0 : gs1) + (size_t)r * N + s * 8;
        uint32_t dst = S + tile * TILE_B + r * (PITCH * 2) + s * 16;
        cp16(dst, src);
    }
}

__global__ void __launch_bounds__(GT, 2) gemm_kernel(float* __restrict__ C) {
    extern __shared__ char smem[];
    const uint32_t SB = smem_u32(smem);

    const int tid  = threadIdx.x;
    const int lane = tid & 31;
    const int wid  = tid >> 5;
    const int wm   = wid & 3;
    const int wn   = wid >> 2;
    const int bi   = blockIdx.y * 128;
    const int bj   = blockIdx.x * 128;

    const int arow = lane & 15;
    const int asel = lane >> 4;
    const int brow = (lane & 7) + ((lane >> 4) << 3);
    const int bsel = (lane >> 3) & 1;

    uint32_t aOff[2][2], bOff[2][4];
#pragma unroll
    for (int s = 0; s < 2; ++s) {
#pragma unroll
        for (int mi = 0; mi < 2; ++mi)
            aOff[s][mi] = (uint32_t)((wm * 32 + mi * 16 + arow) * (PITCH * 2) + (s * 16 + asel * 8) * 2);
#pragma unroll
        for (int np = 0; np < 4; ++np)
            bOff[s][np] = (uint32_t)((wn * 64 + np * 16 + brow) * (PITCH * 2) + (s * 16 + bsel * 8) * 2) + TILE_B;
    }

    float acc[2][8][4];
#pragma unroll
    for (int mi = 0; mi < 2; ++mi)
#pragma unroll
        for (int ni = 0; ni < 8; ++ni)
#pragma unroll
            for (int q = 0; q < 4; ++q) acc[mi][ni][q] = 0.0f;

#pragma unroll
    for (int s = 0; s < NSTAGE - 1; ++s) {
        load_stage(SB + s * STAGE_B, bi, bj, s * BK, tid);
        cp_commit();
    }

    for (int c = 0; c < KCHUNKS; ++c) {
        cp_wait2();
        __syncthreads();

        if (c + NSTAGE - 1 < KCHUNKS)
            load_stage(SB + ((c + NSTAGE - 1) % NSTAGE) * STAGE_B, bi, bj, (c + NSTAGE - 1) * BK, tid);
        cp_commit();

        const uint32_t S = SB + (c % NSTAGE) * STAGE_B;

        uint32_t aF[2][2][4];
        uint32_t bF[2][2][4];

        ldsm4(S + aOff[0][0], aF[0][0]);
        ldsm4(S + aOff[0][1], aF[0][1]);
        ldsm4(S + aOff[1][0], aF[1][0]);
        ldsm4(S + aOff[1][1], aF[1][1]);
        ldsm4(S + bOff[0][0], bF[0][0]);
        ldsm4(S + bOff[0][1], bF[0][1]);

        ldsm4(S + bOff[0][2], bF[1][0]);
        ldsm4(S + bOff[0][3], bF[1][1]);
#pragma unroll
        for (int q = 0; q < 2; ++q)
#pragma unroll
            for (int mi = 0; mi < 2; ++mi) {
                mma16816(acc[mi][2 * q],     aF[0][mi], bF[0][q][0], bF[0][q][1]);
                mma16816(acc[mi][2 * q + 1], aF[0][mi], bF[0][q][2], bF[0][q][3]);
            }

        ldsm4(S + bOff[1][0], bF[0][0]);
        ldsm4(S + bOff[1][1], bF[0][1]);
#pragma unroll
        for (int q = 0; q < 2; ++q)
#pragma unroll
            for (int mi = 0; mi < 2; ++mi) {
                mma16816(acc[mi][4 + 2 * q],     aF[0][mi], bF[1][q][0], bF[1][q][1]);
                mma16816(acc[mi][4 + 2 * q + 1], aF[0][mi], bF[1][q][2], bF[1][q][3]);
            }

        ldsm4(S + bOff[1][2], bF[1][0]);
        ldsm4(S + bOff[1][3], bF[1][1]);
#pragma unroll
        for (int q = 0; q < 2; ++q)
#pragma unroll
            for (int mi = 0; mi < 2; ++mi) {
                mma16816(acc[mi][2 * q],     aF[1][mi], bF[0][q][0], bF[0][q][1]);
                mma16816(acc[mi][2 * q + 1], aF[1][mi], bF[0][q][2], bF[0][q][3]);
            }

#pragma unroll
        for (int q = 0; q < 2; ++q)
#pragma unroll
            for (int mi = 0; mi < 2; ++mi) {
                mma16816(acc[mi][4 + 2 * q],     aF[1][mi], bF[1][q][0], bF[1][q][1]);
                mma16816(acc[mi][4 + 2 * q + 1], aF[1][mi], bF[1][q][2], bF[1][q][3]);
            }
    }

    const int gid = lane >> 2;
    const int tig = lane & 3;
#pragma unroll
    for (int mi = 0; mi < 2; ++mi) {
        int a0 = bi + wm * 32 + mi * 16 + gid;
        float u0 = g_u[a0];
        float u8 = g_u[a0 + 8];
#pragma unroll
        for (int ni = 0; ni < 8; ++ni) {
            int b0 = bj + wn * 64 + ni * 8 + tig * 2;
            *(float2*)(C + (size_t)a0 * N + b0) =
                make_float2(acc[mi][ni][0] * u0, acc[mi][ni][1] * u0);
            *(float2*)(C + (size_t)(a0 + 8) * N + b0) =
                make_float2(acc[mi][ni][2] * u8, acc[mi][ni][3] * u8);
        }
    }
}

// ---------------- launch --------------------------------------------------------
extern "C" void kernel_launch(void* const* d_in, const int* in_sizes, int n_in,
                              void* d_out, int out_size) {
    const float* A = (const float*)d_in[0];
    float* out = (float*)d_out;

    static const int GEMM_SMEM = NSTAGE * STAGE_B;   // 81920 bytes
    cudaFuncSetAttribute(gemm_kernel, cudaFuncAttributeMaxDynamicSharedMemorySize, GEMM_SMEM);

    rowmax_kernel<<<N, 256>>>(A);
    exp_kernel<<<dim3(N / 32, N / 32), dim3(32, 32)>>>(A);
    sinkhorn_kernel<<<SGRID, SBLOCK>>>();
    gemm_kernel<<<dim3(N / 128, N / 128), GT, GEMM_SMEM>>>(out);
}

// round 14
// speedup vs baseline: 81.0781x; 1.0230x over previous
#include <cuda_runtime.h>
#include <cuda_fp16.h>
#include <math.h>
#include <stdint.h>

#define N       2048
#define ITERS   1000
#define TEMP    100.0f
#define EPS_CONV 1e-4f

#define SGRID   128
#define SBLOCK  512
#define WPC     16              // warps per CTA = rows per CTA (1 warp : 1 row)

// ---------------- scratch (static device globals; allocation-free) -------------
__device__ __half g_Eh [N * N];   // exp matrix, fp16
__device__ __half g_ETh[N * N];   // transpose, fp16
__device__ __half g_Gp[N * N];    // G' = v ⊙ rowSuffixSum(m), fp16
__device__ float g_u[N];
__device__ float g_v[N];
__device__ float g_rowmax[N];

__device__ unsigned g_count = 0;
__device__ unsigned g_gen   = 0;
__device__ unsigned g_delta[2] = {0, 0};

// ---------------- acquire/release grid barrier ---------------------------------
__device__ __forceinline__ void grid_sync() {
    __syncthreads();
    if (threadIdx.x == 0) {
        unsigned my;
        asm volatile("ld.acquire.gpu.global.u32 %0, [%1];" : "=r"(my) : "l"(&g_gen));
        unsigned old;
        asm volatile("atom.release.gpu.global.add.u32 %0, [%1], %2;"
                     : "=r"(old) : "l"(&g_count), "r"(1u));
        if (old == SGRID - 1) {
            asm volatile("st.relaxed.gpu.global.u32 [%0], %1;" :: "l"(&g_count), "r"(0u));
            asm volatile("st.release.gpu.global.u32 [%0], %1;" :: "l"(&g_gen), "r"(my + 1u));
        } else {
            unsigned cur;
            do {
                asm volatile("ld.acquire.gpu.global.u32 %0, [%1];" : "=r"(cur) : "l"(&g_gen));
            } while (cur == my);
        }
    }
    __syncthreads();
}

// ---------------- prep kernels ---------------------------------------------------
__global__ void rowmax_kernel(const float* __restrict__ A) {
    int row = blockIdx.x;
    const float* a = A + (size_t)row * N;
    float m = -3.0e38f;
    for (int j = threadIdx.x; j < N; j += blockDim.x) m = fmaxf(m, a[j]);
    __shared__ float s[256];
    s[threadIdx.x] = m;
    __syncthreads();
    for (int o = 128; o > 0; o >>= 1) {
        if (threadIdx.x < o) s[threadIdx.x] = fmaxf(s[threadIdx.x], s[threadIdx.x + o]);
        __syncthreads();
    }
    if (threadIdx.x == 0) {
        g_rowmax[row] = s[0];
        g_u[row] = 1.0f; g_v[row] = 1.0f;
        if (row < 2) g_delta[row] = 0u;
    }
}

__global__ void exp_kernel(const float* __restrict__ A) {
    __shared__ __half tile[32][33];
    int x = blockIdx.x * 32 + threadIdx.x;
    int y = blockIdx.y * 32 + threadIdx.y;
    float rm = g_rowmax[y];
    __half e = __float2half_rn(expf(TEMP * (A[(size_t)y * N + x] - rm)));
    g_Eh[(size_t)y * N + x] = e;
    tile[threadIdx.y][threadIdx.x] = e;
    __syncthreads();
    int tx = blockIdx.y * 32 + threadIdx.x;
    int ty = blockIdx.x * 32 + threadIdx.y;
    g_ETh[(size_t)ty * N + tx] = tile[threadIdx.x][threadIdx.y];
}

// ---------------- persistent Sinkhorn + fused G' epilogue -----------------------
__device__ __forceinline__ float dot8(uint4 e, const float4* sv2i) {
    __half2 h0 = *(__half2*)&e.x, h1 = *(__half2*)&e.y,
            h2 = *(__half2*)&e.z, h3 = *(__half2*)&e.w;
    float2 f0 = __half22float2(h0), f1 = __half22float2(h1),
           f2 = __half22float2(h2), f3 = __half22float2(h3);
    float4 v0 = sv2i[0], v1 = sv2i[1];
    return f0.x*v0.x + f0.y*v0.y + f1.x*v0.z + f1.y*v0.w
         + f2.x*v1.x + f2.y*v1.y + f3.x*v1.z + f3.y*v1.w;
}

__device__ __forceinline__ uint32_t pack_h2(__half a, __half b) {
    __half2 t = __halves2half2(a, b);
    return *(uint32_t*)&t;
}

__global__ void __launch_bounds__(SBLOCK, 1) sinkhorn_kernel() {
    const int tid  = threadIdx.x;
    const int wid  = tid >> 5;
    const int lane = tid & 31;
    const int row  = blockIdx.x * WPC + wid;   // 128 * 16 = 2048 rows

    __shared__ float svec[N];
    __shared__ float sdel[WPC];
    __shared__ float sflag;
    float4* svec4 = (float4*)svec;

    const uint4* erow  = (const uint4*)g_Eh  + (size_t)row * (N / 8);
    const uint4* etrow = (const uint4*)g_ETh + (size_t)row * (N / 8);
    uint4 eR[8], etR[8];
#pragma unroll
    for (int i = 0; i < 8; ++i) {
        eR[i]  = erow [i * 32 + lane];
        etR[i] = etrow[i * 32 + lane];
    }

    float u_old = 1.0f;

    for (int t = 0; t < ITERS; ++t) {
        // ---------- phase A: u = 1 / (E v) ----------
        {
            const float4* v4 = (const float4*)g_v;
            svec4[tid] = v4[tid];
            __syncthreads();

            float s = 0.0f;
#pragma unroll
            for (int i = 0; i < 8; ++i)
                s += dot8(eR[i], svec4 + 2 * (i * 32 + lane));
#pragma unroll
            for (int o = 16; o > 0; o >>= 1) s += __shfl_xor_sync(0xffffffffu, s, o);
            if (lane == 0) {
                float un = 1.0f / s;
                g_u[row] = un;
                sdel[wid] = fabsf(un - u_old) / u_old;
                u_old = un;
            }
            __syncthreads();
            if (tid == 0) {
                float dm = 0.0f;
#pragma unroll
                for (int i = 0; i < WPC; ++i) dm = fmaxf(dm, sdel[i]);
                atomicMax(&g_delta[t & 1], __float_as_uint(dm));
            }
        }
        grid_sync();

        if (tid == 0) {
            unsigned db;
            asm volatile("ld.acquire.gpu.global.u32 %0, [%1];" : "=r"(db) : "l"(&g_delta[t & 1]));
            sflag = (t > 0 && __uint_as_float(db) < EPS_CONV) ? 1.0f : 0.0f;
            g_delta[(t + 1) & 1] = 0u;
        }

        // ---------- phase B: v = 1 / (ET u) ----------
        bool conv;
        {
            const float4* u4 = (const float4*)g_u;
            svec4[tid] = u4[tid];
            __syncthreads();
            conv = (sflag > 0.5f);

            float s = 0.0f;
#pragma unroll
            for (int i = 0; i < 8; ++i)
                s += dot8(etR[i], svec4 + 2 * (i * 32 + lane));
#pragma unroll
            for (int o = 16; o > 0; o >>= 1) s += __shfl_xor_sync(0xffffffffu, s, o);
            if (lane == 0) g_v[row] = 1.0f / s;
        }
        grid_sync();

        if (conv) break;
    }

    // ---------- fused epilogue: G'[row,k] = v_k * suffixSum_k(u_row * E[row,:] ⊙ v) ----------
    {
        const float4* v4 = (const float4*)g_v;
        svec4[tid] = v4[tid];
        __syncthreads();

        float uu = __shfl_sync(0xffffffffu, u_old, 0);

        float cs[8], ics[8], T[8];
#pragma unroll
        for (int i = 0; i < 8; ++i)
            cs[i] = uu * dot8(eR[i], svec4 + 2 * (i * 32 + lane));

#pragma unroll
        for (int i = 0; i < 8; ++i) {
            float x = cs[i];
#pragma unroll
            for (int o = 1; o < 32; o <<= 1) {
                float y = __shfl_up_sync(0xffffffffu, x, o);
                if (lane >= o) x += y;
            }
            ics[i] = x;
            T[i] = __shfl_sync(0xffffffffu, x, 31);
        }

        float offi[8], tot = 0.0f;
#pragma unroll
        for (int i = 0; i < 8; ++i) { offi[i] = tot; tot += T[i]; }

        uint4* gp = (uint4*)g_Gp + (size_t)row * (N / 8);
#pragma unroll
        for (int i = 0; i < 8; ++i) {
            float pf = offi[i] + ics[i] - cs[i];

            const float4* sv2 = svec4 + 2 * (i * 32 + lane);
            float4 v0 = sv2[0], v1 = sv2[1];
            float vv[8] = {v0.x, v0.y, v0.z, v0.w, v1.x, v1.y, v1.z, v1.w};

            uint4 e = eR[i];
            __half2 h0 = *(__half2*)&e.x, h1 = *(__half2*)&e.y,
                    h2 = *(__half2*)&e.z, h3 = *(__half2*)&e.w;
            float2 f0 = __half22float2(h0), f1 = __half22float2(h1),
                   f2 = __half22float2(h2), f3 = __half22float2(h3);
            float m[8];
            m[0] = uu * f0.x * vv[0];  m[1] = uu * f0.y * vv[1];
            m[2] = uu * f1.x * vv[2];  m[3] = uu * f1.y * vv[3];
            m[4] = uu * f2.x * vv[4];  m[5] = uu * f2.y * vv[5];
            m[6] = uu * f3.x * vv[6];  m[7] = uu * f3.y * vv[7];

            __half gh[8];
#pragma unroll
            for (int q = 0; q < 8; ++q) {
                float g = tot - pf;
                pf += m[q];
                gh[q] = __float2half_rn(g * vv[q]);
            }
            gp[i * 32 + lane] =
                make_uint4(pack_h2(gh[0],gh[1]), pack_h2(gh[2],gh[3]),
                           pack_h2(gh[4],gh[5]), pack_h2(gh[6],gh[7]));
        }
    }
}

// ================= mma.sync fp16 GEMM: C[a,b] = u_a * dot(E[a,:], G'[b,:]) =======
// BK=64 (32 chunks, half the barriers), 3-stage cp.async pipeline, occ 2.
#define BK       64
#define KCHUNKS  (N / BK)              // 32
#define PITCH    72                    // halves per smem row (64 + 8 pad) -> 144B
#define TILE_B   (128 * PITCH * 2)     // 18432 bytes per tile
#define STAGE_B  (2 * TILE_B)          // A(E), B(G') = 36864 bytes
#define NSTAGE   3
#define GT       256

__device__ __forceinline__ uint32_t smem_u32(const void* p) {
    uint32_t a;
    asm("{ .reg .u64 t; cvta.to.shared.u64 t, %1; cvt.u32.u64 %0, t; }" : "=r"(a) : "l"(p));
    return a;
}
__device__ __forceinline__ void cp16(uint32_t dst, const void* src) {
    asm volatile("cp.async.cg.shared.global [%0], [%1], 16;" :: "r"(dst), "l"(src));
}
__device__ __forceinline__ void cp_commit() { asm volatile("cp.async.commit_group;" ::: "memory"); }
__device__ __forceinline__ void cp_wait1()  { asm volatile("cp.async.wait_group 1;" ::: "memory"); }

__device__ __forceinline__ void ldsm4(uint32_t addr, uint32_t* r) {
    asm volatile("ldmatrix.sync.aligned.m8n8.x4.shared.b16 {%0,%1,%2,%3}, [%4];"
                 : "=r"(r[0]), "=r"(r[1]), "=r"(r[2]), "=r"(r[3]) : "r"(addr));
}
__device__ __forceinline__ void mma16816(float* c, const uint32_t* a, uint32_t b0, uint32_t b1) {
    asm volatile("mma.sync.aligned.m16n8k16.row.col.f32.f16.f16.f32 "
                 "{%0,%1,%2,%3}, {%4,%5,%6,%7}, {%8,%9}, {%0,%1,%2,%3};"
                 : "+f"(c[0]), "+f"(c[1]), "+f"(c[2]), "+f"(c[3])
                 : "r"(a[0]), "r"(a[1]), "r"(a[2]), "r"(a[3]), "r"(b0), "r"(b1));
}

// load one stage: A rows [bi,bi+128), B rows [bj,bj+128), k window [k0,k0+64)
__device__ __forceinline__ void load_stage(uint32_t S, int bi, int bj, int k0, int tid) {
    const __half* gs0 = g_Eh + (size_t)bi * N + k0;
    const __half* gs1 = g_Gp + (size_t)bj * N + k0;
#pragma unroll
    for (int i = 0; i < 8; ++i) {
        int p = tid + i * GT;              // 0..2047
        int tile = p >> 10;                // 0..1
        int r = (p >> 3) & 127;
        int s = p & 7;
        const __half* src = (tile == 0 ? gs0 : gs1) + (size_t)r * N + s * 8;
        uint32_t dst = S + tile * TILE_B + r * (PITCH * 2) + s * 16;
        cp16(dst, src);
    }
}

__global__ void __launch_bounds__(GT, 2) gemm_kernel(float* __restrict__ C) {
    extern __shared__ char smem[];
    const uint32_t SB = smem_u32(smem);

    const int tid  = threadIdx.x;
    const int lane = tid & 31;
    const int wid  = tid >> 5;
    const int wm   = wid & 3;
    const int wn   = wid >> 2;
    const int bi   = blockIdx.y * 128;
    const int bj   = blockIdx.x * 128;

    const int arow = lane & 15;
    const int asel = lane >> 4;
    const int brow = (lane & 7) + ((lane >> 4) << 3);
    const int bsel = (lane >> 3) & 1;

    // base in-stage byte offsets at kk=0; per k-slice add ks*32 bytes (16 halves)
    uint32_t aBase[2], bBase[4];
#pragma unroll
    for (int mi = 0; mi < 2; ++mi)
        aBase[mi] = (uint32_t)((wm * 32 + mi * 16 + arow) * (PITCH * 2) + (asel * 8) * 2);
#pragma unroll
    for (int np = 0; np < 4; ++np)
        bBase[np] = (uint32_t)((wn * 64 + np * 16 + brow) * (PITCH * 2) + (bsel * 8) * 2) + TILE_B;

    float acc[2][8][4];
#pragma unroll
    for (int mi = 0; mi < 2; ++mi)
#pragma unroll
        for (int ni = 0; ni < 8; ++ni)
#pragma unroll
            for (int q = 0; q < 4; ++q) acc[mi][ni][q] = 0.0f;

    // prologue: stages 0,1
#pragma unroll
    for (int s = 0; s < NSTAGE - 1; ++s) {
        load_stage(SB + s * STAGE_B, bi, bj, s * BK, tid);
        cp_commit();
    }

    for (int c = 0; c < KCHUNKS; ++c) {
        cp_wait1();          // chunk c's stage complete (<=1 group pending)
        __syncthreads();     // all warps done with buffer (c-1)%3 from prev chunk

        if (c + NSTAGE - 1 < KCHUNKS)
            load_stage(SB + ((c + NSTAGE - 1) % NSTAGE) * STAGE_B, bi, bj, (c + NSTAGE - 1) * BK, tid);
        cp_commit();

        const uint32_t S = SB + (c % NSTAGE) * STAGE_B;

#pragma unroll
        for (int ks = 0; ks < 4; ++ks) {
            const uint32_t kOff = ks * 32;   // 16 halves per k-slice
            uint32_t aF[2][4];
#pragma unroll
            for (int mi = 0; mi < 2; ++mi)
                ldsm4(S + aBase[mi] + kOff, aF[mi]);

            uint32_t bF[4][4];
#pragma unroll
            for (int np = 0; np < 4; ++np)
                ldsm4(S + bBase[np] + kOff, bF[np]);

            // 16 MMAs, all-independent accumulators
#pragma unroll
            for (int np = 0; np < 4; ++np)
#pragma unroll
                for (int mi = 0; mi < 2; ++mi) {
                    mma16816(acc[mi][2 * np],     aF[mi], bF[np][0], bF[np][1]);
                    mma16816(acc[mi][2 * np + 1], aF[mi], bF[np][2], bF[np][3]);
                }
        }
    }

    // epilogue: scale by u_a and store
    const int gid = lane >> 2;
    const int tig = lane & 3;
#pragma unroll
    for (int mi = 0; mi < 2; ++mi) {
        int a0 = bi + wm * 32 + mi * 16 + gid;
        float u0 = g_u[a0];
        float u8 = g_u[a0 + 8];
#pragma unroll
        for (int ni = 0; ni < 8; ++ni) {
            int b0 = bj + wn * 64 + ni * 8 + tig * 2;
            *(float2*)(C + (size_t)a0 * N + b0) =
                make_float2(acc[mi][ni][0] * u0, acc[mi][ni][1] * u0);
            *(float2*)(C + (size_t)(a0 + 8) * N + b0) =
                make_float2(acc[mi][ni][2] * u8, acc[mi][ni][3] * u8);
        }
    }
}

// ---------------- launch --------------------------------------------------------
extern "C" void kernel_launch(void* const* d_in, const int* in_sizes, int n_in,
                              void* d_out, int out_size) {
    const float* A = (const float*)d_in[0];
    float* out = (float*)d_out;

    static const int GEMM_SMEM = NSTAGE * STAGE_B;   // 110592 bytes
    cudaFuncSetAttribute(gemm_kernel, cudaFuncAttributeMaxDynamicSharedMemorySize, GEMM_SMEM);

    rowmax_kernel<<<N, 256>>>(A);
    exp_kernel<<<dim3(N / 32, N / 32), dim3(32, 32)>>>(A);
    sinkhorn_kernel<<<SGRID, SBLOCK>>>();
    gemm_kernel<<<dim3(N / 128, N / 128), GT, GEMM_SMEM>>>(out);
}

// round 15
// speedup vs baseline: 81.2298x; 1.0019x over previous
#include <cuda_runtime.h>
#include <cuda_fp16.h>
#include <math.h>
#include <stdint.h>

#define N       2048
#define ITERS   1000
#define TEMP    100.0f
#define EPS_CONV 1e-4f

#define SGRID   128
#define SBLOCK  512
#define WPC     16              // warps per CTA = rows per CTA (1 warp : 1 row)

// ---------------- scratch (static device globals; allocation-free) -------------
__device__ __half g_Eh [N * N];   // exp matrix, fp16
__device__ __half g_ETh[N * N];   // transpose, fp16
__device__ __half g_Gp[N * N];    // G' = v ⊙ rowSuffixSum(m), fp16
__device__ float g_u[N];
__device__ float g_v[N];
__device__ float g_rowmax[N];

__device__ unsigned g_count = 0;
__device__ unsigned g_gen   = 0;
__device__ unsigned g_delta[2] = {0, 0};

// ---------------- acquire/release grid barrier ---------------------------------
__device__ __forceinline__ void grid_sync() {
    __syncthreads();
    if (threadIdx.x == 0) {
        unsigned my;
        asm volatile("ld.acquire.gpu.global.u32 %0, [%1];" : "=r"(my) : "l"(&g_gen));
        unsigned old;
        asm volatile("atom.release.gpu.global.add.u32 %0, [%1], %2;"
                     : "=r"(old) : "l"(&g_count), "r"(1u));
        if (old == SGRID - 1) {
            asm volatile("st.relaxed.gpu.global.u32 [%0], %1;" :: "l"(&g_count), "r"(0u));
            asm volatile("st.release.gpu.global.u32 [%0], %1;" :: "l"(&g_gen), "r"(my + 1u));
        } else {
            unsigned cur;
            do {
                asm volatile("ld.acquire.gpu.global.u32 %0, [%1];" : "=r"(cur) : "l"(&g_gen));
            } while (cur == my);
        }
    }
    __syncthreads();
}

// ---------------- prep kernels ---------------------------------------------------
__global__ void rowmax_kernel(const float* __restrict__ A) {
    int row = blockIdx.x;
    const float* a = A + (size_t)row * N;
    float m = -3.0e38f;
    for (int j = threadIdx.x; j < N; j += blockDim.x) m = fmaxf(m, a[j]);
    __shared__ float s[256];
    s[threadIdx.x] = m;
    __syncthreads();
    for (int o = 128; o > 0; o >>= 1) {
        if (threadIdx.x < o) s[threadIdx.x] = fmaxf(s[threadIdx.x], s[threadIdx.x + o]);
        __syncthreads();
    }
    if (threadIdx.x == 0) {
        g_rowmax[row] = s[0];
        g_u[row] = 1.0f; g_v[row] = 1.0f;
        if (row < 2) g_delta[row] = 0u;
    }
}

__global__ void exp_kernel(const float* __restrict__ A) {
    __shared__ __half tile[32][33];
    int x = blockIdx.x * 32 + threadIdx.x;
    int y = blockIdx.y * 32 + threadIdx.y;
    float rm = g_rowmax[y];
    __half e = __float2half_rn(expf(TEMP * (A[(size_t)y * N + x] - rm)));
    g_Eh[(size_t)y * N + x] = e;
    tile[threadIdx.y][threadIdx.x] = e;
    __syncthreads();
    int tx = blockIdx.y * 32 + threadIdx.x;
    int ty = blockIdx.x * 32 + threadIdx.y;
    g_ETh[(size_t)ty * N + tx] = tile[threadIdx.x][threadIdx.y];
}

// ---------------- persistent Sinkhorn + fused G' epilogue -----------------------
__device__ __forceinline__ float dot8(uint4 e, const float4* sv2i) {
    __half2 h0 = *(__half2*)&e.x, h1 = *(__half2*)&e.y,
            h2 = *(__half2*)&e.z, h3 = *(__half2*)&e.w;
    float2 f0 = __half22float2(h0), f1 = __half22float2(h1),
           f2 = __half22float2(h2), f3 = __half22float2(h3);
    float4 v0 = sv2i[0], v1 = sv2i[1];
    return f0.x*v0.x + f0.y*v0.y + f1.x*v0.z + f1.y*v0.w
         + f2.x*v1.x + f2.y*v1.y + f3.x*v1.z + f3.y*v1.w;
}

__device__ __forceinline__ uint32_t pack_h2(__half a, __half b) {
    __half2 t = __halves2half2(a, b);
    return *(uint32_t*)&t;
}

__global__ void __launch_bounds__(SBLOCK, 1) sinkhorn_kernel() {
    const int tid  = threadIdx.x;
    const int wid  = tid >> 5;
    const int lane = tid & 31;
    const int row  = blockIdx.x * WPC + wid;   // 128 * 16 = 2048 rows

    __shared__ float svec[N];
    __shared__ float sdel[WPC];
    __shared__ float sflag;
    float4* svec4 = (float4*)svec;

    const uint4* erow  = (const uint4*)g_Eh  + (size_t)row * (N / 8);
    const uint4* etrow = (const uint4*)g_ETh + (size_t)row * (N / 8);
    uint4 eR[8], etR[8];
#pragma unroll
    for (int i = 0; i < 8; ++i) {
        eR[i]  = erow [i * 32 + lane];
        etR[i] = etrow[i * 32 + lane];
    }

    float u_old = 1.0f;

    for (int t = 0; t < ITERS; ++t) {
        // ---------- phase A: u = 1 / (E v) ----------
        {
            const float4* v4 = (const float4*)g_v;
            svec4[tid] = v4[tid];
            __syncthreads();

            float s = 0.0f;
#pragma unroll
            for (int i = 0; i < 8; ++i)
                s += dot8(eR[i], svec4 + 2 * (i * 32 + lane));
#pragma unroll
            for (int o = 16; o > 0; o >>= 1) s += __shfl_xor_sync(0xffffffffu, s, o);
            if (lane == 0) {
                float un = 1.0f / s;
                g_u[row] = un;
                sdel[wid] = fabsf(un - u_old) / u_old;
                u_old = un;
            }
            __syncthreads();
            if (tid == 0) {
                float dm = 0.0f;
#pragma unroll
                for (int i = 0; i < WPC; ++i) dm = fmaxf(dm, sdel[i]);
                atomicMax(&g_delta[t & 1], __float_as_uint(dm));
            }
        }
        grid_sync();

        if (tid == 0) {
            unsigned db;
            asm volatile("ld.acquire.gpu.global.u32 %0, [%1];" : "=r"(db) : "l"(&g_delta[t & 1]));
            sflag = (t > 0 && __uint_as_float(db) < EPS_CONV) ? 1.0f : 0.0f;
            g_delta[(t + 1) & 1] = 0u;
        }

        // ---------- phase B: v = 1 / (ET u) ----------
        bool conv;
        {
            const float4* u4 = (const float4*)g_u;
            svec4[tid] = u4[tid];
            __syncthreads();
            conv = (sflag > 0.5f);

            float s = 0.0f;
#pragma unroll
            for (int i = 0; i < 8; ++i)
                s += dot8(etR[i], svec4 + 2 * (i * 32 + lane));
#pragma unroll
            for (int o = 16; o > 0; o >>= 1) s += __shfl_xor_sync(0xffffffffu, s, o);
            if (lane == 0) g_v[row] = 1.0f / s;
        }
        grid_sync();

        if (conv) break;
    }

    // ---------- fused epilogue: G'[row,k] = v_k * suffixSum_k(u_row * E[row,:] ⊙ v) ----------
    {
        const float4* v4 = (const float4*)g_v;
        svec4[tid] = v4[tid];
        __syncthreads();

        float uu = __shfl_sync(0xffffffffu, u_old, 0);

        float cs[8], ics[8], T[8];
#pragma unroll
        for (int i = 0; i < 8; ++i)
            cs[i] = uu * dot8(eR[i], svec4 + 2 * (i * 32 + lane));

#pragma unroll
        for (int i = 0; i < 8; ++i) {
            float x = cs[i];
#pragma unroll
            for (int o = 1; o < 32; o <<= 1) {
                float y = __shfl_up_sync(0xffffffffu, x, o);
                if (lane >= o) x += y;
            }
            ics[i] = x;
            T[i] = __shfl_sync(0xffffffffu, x, 31);
        }

        float offi[8], tot = 0.0f;
#pragma unroll
        for (int i = 0; i < 8; ++i) { offi[i] = tot; tot += T[i]; }

        uint4* gp = (uint4*)g_Gp + (size_t)row * (N / 8);
#pragma unroll
        for (int i = 0; i < 8; ++i) {
            float pf = offi[i] + ics[i] - cs[i];

            const float4* sv2 = svec4 + 2 * (i * 32 + lane);
            float4 v0 = sv2[0], v1 = sv2[1];
            float vv[8] = {v0.x, v0.y, v0.z, v0.w, v1.x, v1.y, v1.z, v1.w};

            uint4 e = eR[i];
            __half2 h0 = *(__half2*)&e.x, h1 = *(__half2*)&e.y,
                    h2 = *(__half2*)&e.z, h3 = *(__half2*)&e.w;
            float2 f0 = __half22float2(h0), f1 = __half22float2(h1),
                   f2 = __half22float2(h2), f3 = __half22float2(h3);
            float m[8];
            m[0] = uu * f0.x * vv[0];  m[1] = uu * f0.y * vv[1];
            m[2] = uu * f1.x * vv[2];  m[3] = uu * f1.y * vv[3];
            m[4] = uu * f2.x * vv[4];  m[5] = uu * f2.y * vv[5];
            m[6] = uu * f3.x * vv[6];  m[7] = uu * f3.y * vv[7];

            __half gh[8];
#pragma unroll
            for (int q = 0; q < 8; ++q) {
                float g = tot - pf;
                pf += m[q];
                gh[q] = __float2half_rn(g * vv[q]);
            }
            gp[i * 32 + lane] =
                make_uint4(pack_h2(gh[0],gh[1]), pack_h2(gh[2],gh[3]),
                           pack_h2(gh[4],gh[5]), pack_h2(gh[6],gh[7]));
        }
    }
}

// ================= mma.sync fp16 GEMM: C[a,b] = u_a * dot(E[a,:], G'[b,:]) =======
// 512 threads (16 warps, 4x4), warp tile 32x32, BK=64, 3-stage pipeline, occ 2.
// Small warp tiles => ~62 regs/thread => 32 warps/SM for latency hiding.
#define BK       64
#define KCHUNKS  (N / BK)              // 32
#define PITCH    72                    // halves per smem row (64 + 8 pad) -> 144B
#define TILE_B   (128 * PITCH * 2)     // 18432 bytes per tile
#define STAGE_B  (2 * TILE_B)          // A(E), B(G') = 36864 bytes
#define NSTAGE   3
#define GT       512

__device__ __forceinline__ uint32_t smem_u32(const void* p) {
    uint32_t a;
    asm("{ .reg .u64 t; cvta.to.shared.u64 t, %1; cvt.u32.u64 %0, t; }" : "=r"(a) : "l"(p));
    return a;
}
__device__ __forceinline__ void cp16(uint32_t dst, const void* src) {
    asm volatile("cp.async.cg.shared.global [%0], [%1], 16;" :: "r"(dst), "l"(src));
}
__device__ __forceinline__ void cp_commit() { asm volatile("cp.async.commit_group;" ::: "memory"); }
__device__ __forceinline__ void cp_wait1()  { asm volatile("cp.async.wait_group 1;" ::: "memory"); }

__device__ __forceinline__ void ldsm4(uint32_t addr, uint32_t* r) {
    asm volatile("ldmatrix.sync.aligned.m8n8.x4.shared.b16 {%0,%1,%2,%3}, [%4];"
                 : "=r"(r[0]), "=r"(r[1]), "=r"(r[2]), "=r"(r[3]) : "r"(addr));
}
__device__ __forceinline__ void mma16816(float* c, const uint32_t* a, uint32_t b0, uint32_t b1) {
    asm volatile("mma.sync.aligned.m16n8k16.row.col.f32.f16.f16.f32 "
                 "{%0,%1,%2,%3}, {%4,%5,%6,%7}, {%8,%9}, {%0,%1,%2,%3};"
                 : "+f"(c[0]), "+f"(c[1]), "+f"(c[2]), "+f"(c[3])
                 : "r"(a[0]), "r"(a[1]), "r"(a[2]), "r"(a[3]), "r"(b0), "r"(b1));
}

// load one stage: A rows [bi,bi+128), B rows [bj,bj+128), k window [k0,k0+64)
__device__ __forceinline__ void load_stage(uint32_t S, int bi, int bj, int k0, int tid) {
    const __half* gs0 = g_Eh + (size_t)bi * N + k0;
    const __half* gs1 = g_Gp + (size_t)bj * N + k0;
#pragma unroll
    for (int i = 0; i < 4; ++i) {
        int p = tid + i * GT;              // 0..2047
        int tile = p >> 10;                // 0..1
        int r = (p >> 3) & 127;
        int s = p & 7;
        const __half* src = (tile == 0 ? gs0 : gs1) + (size_t)r * N + s * 8;
        uint32_t dst = S + tile * TILE_B + r * (PITCH * 2) + s * 16;
        cp16(dst, src);
    }
}

__global__ void __launch_bounds__(GT, 2) gemm_kernel(float* __restrict__ C) {
    extern __shared__ char smem[];
    const uint32_t SB = smem_u32(smem);

    const int tid  = threadIdx.x;
    const int lane = tid & 31;
    const int wid  = tid >> 5;
    const int wm   = wid & 3;          // warp M index (0..3)
    const int wn   = wid >> 2;         // warp N index (0..3)
    const int bi   = blockIdx.y * 128;
    const int bj   = blockIdx.x * 128;

    const int arow = lane & 15;
    const int asel = lane >> 4;
    const int brow = (lane & 7) + ((lane >> 4) << 3);
    const int bsel = (lane >> 3) & 1;

    // base in-stage byte offsets at kk=0; per k-slice add ks*32 bytes (16 halves)
    uint32_t aBase[2], bBase[2];
#pragma unroll
    for (int mi = 0; mi < 2; ++mi)
        aBase[mi] = (uint32_t)((wm * 32 + mi * 16 + arow) * (PITCH * 2) + (asel * 8) * 2);
#pragma unroll
    for (int np = 0; np < 2; ++np)
        bBase[np] = (uint32_t)((wn * 32 + np * 16 + brow) * (PITCH * 2) + (bsel * 8) * 2) + TILE_B;

    float acc[2][4][4];
#pragma unroll
    for (int mi = 0; mi < 2; ++mi)
#pragma unroll
        for (int ni = 0; ni < 4; ++ni)
#pragma unroll
            for (int q = 0; q < 4; ++q) acc[mi][ni][q] = 0.0f;

    // prologue: stages 0,1
#pragma unroll
    for (int s = 0; s < NSTAGE - 1; ++s) {
        load_stage(SB + s * STAGE_B, bi, bj, s * BK, tid);
        cp_commit();
    }

    for (int c = 0; c < KCHUNKS; ++c) {
        cp_wait1();
        __syncthreads();

        if (c + NSTAGE - 1 < KCHUNKS)
            load_stage(SB + ((c + NSTAGE - 1) % NSTAGE) * STAGE_B, bi, bj, (c + NSTAGE - 1) * BK, tid);
        cp_commit();

        const uint32_t S = SB + (c % NSTAGE) * STAGE_B;

#pragma unroll
        for (int ks = 0; ks < 4; ++ks) {
            const uint32_t kOff = ks * 32;   // 16 halves per k-slice
            uint32_t aF[2][4];
#pragma unroll
            for (int mi = 0; mi < 2; ++mi)
                ldsm4(S + aBase[mi] + kOff, aF[mi]);

            uint32_t bF[2][4];
#pragma unroll
            for (int np = 0; np < 2; ++np)
                ldsm4(S + bBase[np] + kOff, bF[np]);

            // 8 MMAs, all-independent accumulators
#pragma unroll
            for (int np = 0; np < 2; ++np)
#pragma unroll
                for (int mi = 0; mi < 2; ++mi) {
                    mma16816(acc[mi][2 * np],     aF[mi], bF[np][0], bF[np][1]);
                    mma16816(acc[mi][2 * np + 1], aF[mi], bF[np][2], bF[np][3]);
                }
        }
    }

    // epilogue: scale by u_a and store (warp tile 32x32)
    const int gid = lane >> 2;
    const int tig = lane & 3;
#pragma unroll
    for (int mi = 0; mi < 2; ++mi) {
        int a0 = bi + wm * 32 + mi * 16 + gid;
        float u0 = g_u[a0];
        float u8 = g_u[a0 + 8];
#pragma unroll
        for (int ni = 0; ni < 4; ++ni) {
            int b0 = bj + wn * 32 + ni * 8 + tig * 2;
            *(float2*)(C + (size_t)a0 * N + b0) =
                make_float2(acc[mi][ni][0] * u0, acc[mi][ni][1] * u0);
            *(float2*)(C + (size_t)(a0 + 8) * N + b0) =
                make_float2(acc[mi][ni][2] * u8, acc[mi][ni][3] * u8);
        }
    }
}

// ---------------- launch --------------------------------------------------------
extern "C" void kernel_launch(void* const* d_in, const int* in_sizes, int n_in,
                              void* d_out, int out_size) {
    const float* A = (const float*)d_in[0];
    float* out = (float*)d_out;

    static const int GEMM_SMEM = NSTAGE * STAGE_B;   // 110592 bytes
    cudaFuncSetAttribute(gemm_kernel, cudaFuncAttributeMaxDynamicSharedMemorySize, GEMM_SMEM);

    rowmax_kernel<<<N, 256>>>(A);
    exp_kernel<<<dim3(N / 32, N / 32), dim3(32, 32)>>>(A);
    sinkhorn_kernel<<<SGRID, SBLOCK>>>();
    gemm_kernel<<<dim3(N / 128, N / 128), GT, GEMM_SMEM>>>(out);
}